// round 2
// baseline (speedup 1.0000x reference)
#include <cuda_runtime.h>
#include <math.h>

#define EPSC 1e-6f
#define INV_SQRT_2PI 0.3989422804014327f

__constant__ float GT[10] = {0.715951561820333f, 1.039358092507381f, 0.948607106485449f,
                             0.715951555650637f, 0.715951343627955f, 1.039354251532628f,
                             0.484068718800797f, 0.715951452277779f, 1.039355768740833f,
                             1.446433070133343f};
__constant__ float GS[10] = {0.519483084417772f, 0.357944855434941f, 0.723301195883257f,
                             0.474918009444542f, 0.519483382721337f, 0.357945091498072f,
                             0.519481351904163f, 0.357945544542554f, 0.242049896394596f,
                             0.357944917042638f};

// ------------------- scratch (__device__ globals, no allocs) -------------------
__device__ float g_h1[64 * 512];
__device__ float g_zvar[64 * 64];
__device__ float g_m3[64 * 512];
__device__ float g_a0[64 * 512];
__device__ float g_a1[64 * 512];
__device__ float g_a2[64 * 512];
__device__ float g_a3[64 * 512];
__device__ float g_v[64 * 512];
__device__ float g_H[(size_t)64 * 512 * 512];   // cov_h3, 67 MB
__device__ float g_m41[64 * 784];
__device__ float g_diag41[64 * 784];

// packed f32x2 helpers ---------------------------------------------------------
__device__ __forceinline__ void ffma2(unsigned long long& d,
                                      unsigned long long a,
                                      unsigned long long b) {
    asm("fma.rn.f32x2 %0, %1, %2, %0;" : "+l"(d) : "l"(a), "l"(b));
}
__device__ __forceinline__ unsigned long long dup2(float x) {
    unsigned u = __float_as_uint(x);
    return (unsigned long long)u | ((unsigned long long)u << 32);
}
__device__ __forceinline__ float2 unpack2(unsigned long long v) {
    float2 r;
    r.x = __uint_as_float((unsigned)v);
    r.y = __uint_as_float((unsigned)(v >> 32));
    return r;
}

// ------------------- generic small GEMM: out[64,N] = act(A[64,K] @ Bw[N,K]^T + bias) ----
// MODE 0: tanh    MODE 1: identity    MODE 2: identity -> out, exp(val) -> out2
template <int MODE>
__global__ __launch_bounds__(256) void gemm_bias_act(
    const float* __restrict__ A, const float* __restrict__ Bw,
    const float* __restrict__ bias, float* __restrict__ out,
    int N, int K, float* __restrict__ out2)
{
    __shared__ float As[16 * 68];
    __shared__ float Bs[16 * 68];
    const int t = threadIdx.x;
    const int tx = t & 15, ty = t >> 4;
    const int n_base = blockIdx.x * 64;

    float acc[4][4];
#pragma unroll
    for (int r = 0; r < 4; r++)
#pragma unroll
        for (int c = 0; c < 4; c++) acc[r][c] = 0.f;

    for (int k0 = 0; k0 < K; k0 += 16) {
        {   // A tile (64 rows x 16 k), transposed into As[k][m]
            int row = t >> 2, c4 = t & 3;
            float4 v = *reinterpret_cast<const float4*>(A + (size_t)row * K + k0 + c4 * 4);
            As[(c4 * 4 + 0) * 68 + row] = v.x;
            As[(c4 * 4 + 1) * 68 + row] = v.y;
            As[(c4 * 4 + 2) * 68 + row] = v.z;
            As[(c4 * 4 + 3) * 68 + row] = v.w;
        }
        {   // B tile (64 n-rows x 16 k), transposed into Bs[k][n]
            int row = t >> 2, c4 = t & 3;
            int ng = n_base + row;
            float4 v = make_float4(0.f, 0.f, 0.f, 0.f);
            if (ng < N) v = *reinterpret_cast<const float4*>(Bw + (size_t)ng * K + k0 + c4 * 4);
            Bs[(c4 * 4 + 0) * 68 + row] = v.x;
            Bs[(c4 * 4 + 1) * 68 + row] = v.y;
            Bs[(c4 * 4 + 2) * 68 + row] = v.z;
            Bs[(c4 * 4 + 3) * 68 + row] = v.w;
        }
        __syncthreads();
#pragma unroll
        for (int kk = 0; kk < 16; kk++) {
            float4 am = *reinterpret_cast<const float4*>(&As[kk * 68 + ty * 4]);
            float4 bn = *reinterpret_cast<const float4*>(&Bs[kk * 68 + tx * 4]);
            float a[4] = {am.x, am.y, am.z, am.w};
            float bb[4] = {bn.x, bn.y, bn.z, bn.w};
#pragma unroll
            for (int r = 0; r < 4; r++)
#pragma unroll
                for (int c = 0; c < 4; c++) acc[r][c] += a[r] * bb[c];
        }
        __syncthreads();
    }

#pragma unroll
    for (int r = 0; r < 4; r++) {
        int m = ty * 4 + r;
#pragma unroll
        for (int c = 0; c < 4; c++) {
            int ng = n_base + tx * 4 + c;
            if (ng < N) {
                float val = acc[r][c] + bias[ng];
                if (MODE == 0) val = tanhf(val);
                out[(size_t)m * N + ng] = val;
                if (MODE == 2) out2[(size_t)m * N + ng] = expf(val);
            }
        }
    }
}

// ------------------- moments (tanh): A0..A3 coefficients + clipped diag --------
__global__ void moments_tanh(const float* __restrict__ w3)
{
    int idx = blockIdx.x * blockDim.x + threadIdx.x;
    if (idx >= 64 * 512) return;
    int b = idx >> 9, i = idx & 511;

    const float* wr = w3 + i * 64;
    const float* zr = g_zvar + b * 64;
    float v = 0.f;
#pragma unroll 8
    for (int l = 0; l < 64; l++) v += wr[l] * wr[l] * zr[l];
    v = fmaxf(v, EPSC);

    float m = g_m3[idx];
    float s0 = 0.f, s1 = 0.f, s2 = 0.f, s3 = 0.f;
#pragma unroll
    for (int g = 0; g < 10; g++) {
        float gam = GT[g];
        float cg = 1.0f / (2.0f * gam * gam);
        float ivh = v + cg;
        float sq = sqrtf(ivh);
        float mu = m / sq;
        float Bv = expf(-0.5f * mu * mu) * INV_SQRT_2PI / sq;
        float Cv = 0.5f * (1.0f + erff(mu * 0.70710678118654752f));
        s0 += 2.f * Cv - 1.f;
        s1 += 2.f * Bv;
        s2 += -Bv * m / ivh;
        s3 += (1.f / 3.f) * Bv * (m * m - ivh) / (ivh * ivh);
    }
    g_a0[idx] = s0 * 0.1f;
    g_a1[idx] = s1 * 0.1f;
    g_a2[idx] = s2 * 0.1f;
    g_a3[idx] = s3 * 0.1f;
    g_v[idx]  = v;
}

// ------------------- build H = cov_h3 (fused cov3 + moment transform) ----------
__global__ __launch_bounds__(256, 2) void build_H(const float* __restrict__ w3)
{
    __shared__ float Wi[32 * 132];
    __shared__ float Wj[32 * 132];
    const int t = threadIdx.x;
    const int tx = t & 15, ty = t >> 4;
    const int ib = blockIdx.x * 128, jb = blockIdx.y * 128, b = blockIdx.z;
    const float* zr = g_zvar + b * 64;

    float acc[8][8];
#pragma unroll
    for (int r = 0; r < 8; r++)
#pragma unroll
        for (int c = 0; c < 8; c++) acc[r][c] = 0.f;

    for (int lc = 0; lc < 64; lc += 32) {
#pragma unroll
        for (int q = 0; q < 4; q++) {
            int f = t + q * 256;         // [0,1024)
            int row = f >> 3, c4 = f & 7;
            int l = lc + c4 * 4;
            float4 vi = *reinterpret_cast<const float4*>(w3 + (size_t)(ib + row) * 64 + l);
            Wi[(c4 * 4 + 0) * 132 + row] = vi.x;
            Wi[(c4 * 4 + 1) * 132 + row] = vi.y;
            Wi[(c4 * 4 + 2) * 132 + row] = vi.z;
            Wi[(c4 * 4 + 3) * 132 + row] = vi.w;
            float4 vj = *reinterpret_cast<const float4*>(w3 + (size_t)(jb + row) * 64 + l);
            Wj[(c4 * 4 + 0) * 132 + row] = vj.x * zr[l + 0];
            Wj[(c4 * 4 + 1) * 132 + row] = vj.y * zr[l + 1];
            Wj[(c4 * 4 + 2) * 132 + row] = vj.z * zr[l + 2];
            Wj[(c4 * 4 + 3) * 132 + row] = vj.w * zr[l + 3];
        }
        __syncthreads();
#pragma unroll
        for (int l = 0; l < 32; l++) {
            float a[8], bb[8];
            *reinterpret_cast<float4*>(a)      = *reinterpret_cast<const float4*>(&Wi[l * 132 + ty * 8]);
            *reinterpret_cast<float4*>(a + 4)  = *reinterpret_cast<const float4*>(&Wi[l * 132 + ty * 8 + 4]);
            *reinterpret_cast<float4*>(bb)     = *reinterpret_cast<const float4*>(&Wj[l * 132 + tx * 8]);
            *reinterpret_cast<float4*>(bb + 4) = *reinterpret_cast<const float4*>(&Wj[l * 132 + tx * 8 + 4]);
#pragma unroll
            for (int r = 0; r < 8; r++)
#pragma unroll
                for (int c = 0; c < 8; c++) acc[r][c] += a[r] * bb[c];
        }
        __syncthreads();
    }

    float a1i[8], a2i[8], a3i[8], vi[8];
    float a1j[8], a2j[8], a3j[8], vj[8];
#pragma unroll
    for (int r = 0; r < 8; r++) {
        int ig = b * 512 + ib + ty * 8 + r;
        a1i[r] = g_a1[ig]; a2i[r] = g_a2[ig]; a3i[r] = g_a3[ig]; vi[r] = g_v[ig];
    }
#pragma unroll
    for (int c = 0; c < 8; c++) {
        int jg = b * 512 + jb + tx * 8 + c;
        a1j[c] = g_a1[jg]; a2j[c] = g_a2[jg]; a3j[c] = g_a3[jg]; vj[c] = g_v[jg];
    }
#pragma unroll
    for (int r = 0; r < 8; r++) {
        int ig = ib + ty * 8 + r;
#pragma unroll
        for (int c = 0; c < 8; c++) {
            int jg = jb + tx * 8 + c;
            float c0 = acc[r][c];
            if (ig == jg) c0 = fmaxf(c0, EPSC);
            float c2 = c0 * c0;
            float h = a1i[r] * a1j[c] * c0
                    + 2.f * a2i[r] * a2j[c] * c2
                    + a3i[r] * a3j[c] * (6.f * c2 * c0 + 9.f * vi[r] * vj[c] * c0);
            g_H[((size_t)b * 512 + ig) * 512 + jg] = h;
        }
    }
}

// ------------------- diag41[b,o] = w41[o,:] H[b] w41[o,:]^T --------------------
// Packed-f32x2 version: A operand duplicated in SMEM, B pairs loaded natively,
// inner loop is pure fma.rn.f32x2 (2 fp32 FMA per issue slot).
__global__ __launch_bounds__(256) void bilinear_diag(const float* __restrict__ w41)
{
    __shared__ unsigned long long As2[16 * 132];  // [k][o] -> {a,a} packed, 16.9 KB
    __shared__ float Bs[16 * 128];                // [k][j],  8 KB
    const int t = threadIdx.x;
    const int tx = t & 15, ty = t >> 4;
    const int ob = blockIdx.x * 128;
    const int b  = blockIdx.y;
    const float* Hb = g_H + ((size_t)b << 18);

    float partD[8];
#pragma unroll
    for (int r = 0; r < 8; r++) partD[r] = 0.f;

    for (int jt = 0; jt < 4; jt++) {
        const int jb = jt * 128;
        unsigned long long acc2[8][4];
#pragma unroll
        for (int r = 0; r < 8; r++)
#pragma unroll
            for (int c = 0; c < 4; c++) acc2[r][c] = 0ULL;

        for (int kc = 0; kc < 512; kc += 16) {
#pragma unroll
            for (int q = 0; q < 2; q++) {           // A tile (w41): dup-pack to As2[k][o]
                int f = t + q * 256;                 // [0,512)
                int row = f >> 2, c4 = f & 3;
                int og = ob + row;
                float4 v = make_float4(0.f, 0.f, 0.f, 0.f);
                if (og < 784) v = *reinterpret_cast<const float4*>(w41 + (size_t)og * 512 + kc + c4 * 4);
                As2[(c4 * 4 + 0) * 132 + row] = dup2(v.x);
                As2[(c4 * 4 + 1) * 132 + row] = dup2(v.y);
                As2[(c4 * 4 + 2) * 132 + row] = dup2(v.z);
                As2[(c4 * 4 + 3) * 132 + row] = dup2(v.w);
            }
#pragma unroll
            for (int q = 0; q < 2; q++) {           // B tile (H): direct
                int f = t + q * 256;
                int row = f >> 5, c4 = f & 31;
                float4 v = *reinterpret_cast<const float4*>(Hb + (size_t)(kc + row) * 512 + jb + c4 * 4);
                *reinterpret_cast<float4*>(&Bs[row * 128 + c4 * 4]) = v;
            }
            __syncthreads();
#pragma unroll
            for (int kk = 0; kk < 16; kk++) {
                unsigned long long a[8];
                *reinterpret_cast<ulonglong2*>(&a[0]) = *reinterpret_cast<const ulonglong2*>(&As2[kk * 132 + ty * 8 + 0]);
                *reinterpret_cast<ulonglong2*>(&a[2]) = *reinterpret_cast<const ulonglong2*>(&As2[kk * 132 + ty * 8 + 2]);
                *reinterpret_cast<ulonglong2*>(&a[4]) = *reinterpret_cast<const ulonglong2*>(&As2[kk * 132 + ty * 8 + 4]);
                *reinterpret_cast<ulonglong2*>(&a[6]) = *reinterpret_cast<const ulonglong2*>(&As2[kk * 132 + ty * 8 + 6]);
                unsigned long long bp[4];
                *reinterpret_cast<ulonglong2*>(&bp[0]) = *reinterpret_cast<const ulonglong2*>(&Bs[kk * 128 + tx * 8]);
                *reinterpret_cast<ulonglong2*>(&bp[2]) = *reinterpret_cast<const ulonglong2*>(&Bs[kk * 128 + tx * 8 + 4]);
#pragma unroll
                for (int r = 0; r < 8; r++)
#pragma unroll
                    for (int c = 0; c < 4; c++) ffma2(acc2[r][c], a[r], bp[c]);
            }
            __syncthreads();
        }

        // epilogue: multiply by w41[o, j] and accumulate row partials
#pragma unroll
        for (int r = 0; r < 8; r++) {
            int og = ob + ty * 8 + r;
            if (og < 784) {
                float4 u0 = *reinterpret_cast<const float4*>(w41 + (size_t)og * 512 + jb + tx * 8);
                float4 u1 = *reinterpret_cast<const float4*>(w41 + (size_t)og * 512 + jb + tx * 8 + 4);
                float2 p0 = unpack2(acc2[r][0]);
                float2 p1 = unpack2(acc2[r][1]);
                float2 p2 = unpack2(acc2[r][2]);
                float2 p3 = unpack2(acc2[r][3]);
                partD[r] += p0.x * u0.x + p0.y * u0.y + p1.x * u0.z + p1.y * u0.w
                          + p2.x * u1.x + p2.y * u1.y + p3.x * u1.z + p3.y * u1.w;
            }
        }
    }

    // cross-thread reduction over tx (16 partials per o), reuse As2 as float buffer
    float* red = reinterpret_cast<float*>(As2);   // needs 2048 floats; As2 has 4224 slots
#pragma unroll
    for (int r = 0; r < 8; r++) red[(ty * 8 + r) * 16 + tx] = partD[r];
    __syncthreads();
    if (t < 128) {
        float s = 0.f;
#pragma unroll
        for (int q = 0; q < 16; q++) s += red[t * 16 + q];
        int og = ob + t;
        if (og < 784) g_diag41[b * 784 + og] = s;
    }
}

// ------------------- probs: sigmoid A0 only ------------------------------------
__global__ void probs_kernel(float* __restrict__ out)
{
    int idx = blockIdx.x * blockDim.x + threadIdx.x;
    if (idx >= 64 * 784) return;
    float v = fmaxf(g_diag41[idx], EPSC);
    float m = g_m41[idx];
    float s = 0.f;
#pragma unroll
    for (int g = 0; g < 10; g++) {
        float gam = GS[g];
        float cg = 1.0f / (2.0f * gam * gam);
        float ivh = v + cg;
        s += 0.5f * (1.0f + erff(m / sqrtf(2.0f * ivh)));
    }
    out[idx] = s * 0.1f;
}

// ------------------- launcher --------------------------------------------------
extern "C" void kernel_launch(void* const* d_in, const int* in_sizes, int n_in,
                              void* d_out, int out_size)
{
    const float* x   = (const float*)d_in[0];
    const float* w1  = (const float*)d_in[1];
    const float* b1  = (const float*)d_in[2];
    const float* w21 = (const float*)d_in[3];
    const float* b21 = (const float*)d_in[4];
    const float* w22 = (const float*)d_in[5];
    const float* b22 = (const float*)d_in[6];
    const float* w3  = (const float*)d_in[7];
    const float* b3  = (const float*)d_in[8];
    const float* w41 = (const float*)d_in[9];
    const float* b41 = (const float*)d_in[10];
    float* out = (float*)d_out;

    float *h1, *zvar, *m3, *a0, *m41;
    cudaGetSymbolAddress((void**)&h1,   g_h1);
    cudaGetSymbolAddress((void**)&zvar, g_zvar);
    cudaGetSymbolAddress((void**)&m3,   g_m3);
    cudaGetSymbolAddress((void**)&a0,   g_a0);
    cudaGetSymbolAddress((void**)&m41,  g_m41);

    // h1 = tanh(x @ w1.T + b1)                       [64,512]
    gemm_bias_act<0><<<8, 256>>>(x, w1, b1, h1, 512, 784, nullptr);
    // z_mean -> out[0:4096]                          [64,64]
    gemm_bias_act<1><<<1, 256>>>(h1, w21, b21, out, 64, 512, nullptr);
    // z_logvar -> out[4096:8192], z_var -> scratch   [64,64]
    gemm_bias_act<2><<<1, 256>>>(h1, w22, b22, out + 64 * 64, 64, 512, zvar);
    // m3 = z_mean @ w3.T + b3                        [64,512]
    gemm_bias_act<1><<<8, 256>>>(out, w3, b3, m3, 512, 64, nullptr);
    // tanh moment coefficients + clipped diag
    moments_tanh<<<128, 256>>>(w3);
    // H = cov_h3 (fused cov3 construction + transform)
    build_H<<<dim3(4, 4, 64), 256>>>(w3);
    // m41 = a0 @ w41.T + b41                         [64,784]
    gemm_bias_act<1><<<13, 256>>>(a0, w41, b41, m41, 784, 512, nullptr);
    // diag of cov41 only (the key algebraic saving)
    bilinear_diag<<<dim3(7, 64), 256>>>(w41);
    // probs -> out[8192:]
    probs_kernel<<<(64 * 784 + 255) / 256, 256>>>(out + 2 * 64 * 64);
}

// round 3
// speedup vs baseline: 2.0290x; 2.0290x over previous
#include <cuda_runtime.h>
#include <math.h>

#define EPSC 1e-6f
#define INV_SQRT_2PI 0.3989422804014327f

__constant__ float GT[10] = {0.715951561820333f, 1.039358092507381f, 0.948607106485449f,
                             0.715951555650637f, 0.715951343627955f, 1.039354251532628f,
                             0.484068718800797f, 0.715951452277779f, 1.039355768740833f,
                             1.446433070133343f};
__constant__ float GS[10] = {0.519483084417772f, 0.357944855434941f, 0.723301195883257f,
                             0.474918009444542f, 0.519483382721337f, 0.357945091498072f,
                             0.519481351904163f, 0.357945544542554f, 0.242049896394596f,
                             0.357944917042638f};

// ------------------- scratch (__device__ globals, no allocs) -------------------
__device__ float g_h1[64 * 512];
__device__ float g_zvar[64 * 64];
__device__ float g_m3[64 * 512];
__device__ float g_a0[64 * 512];
__device__ float g_a1[64 * 512];
__device__ float g_a2[64 * 512];
__device__ float g_a3[64 * 512];
__device__ float g_v[64 * 512];
__device__ float g_H[(size_t)64 * 512 * 512];   // cov_h3, 67 MB
__device__ float g_m41[64 * 784];
__device__ float g_diag41[64 * 784];

__device__ __forceinline__ unsigned f2tf32(float x) {
    unsigned r;
    asm("cvt.rna.tf32.f32 %0, %1;" : "=r"(r) : "f"(x));
    return r;
}

// ------------------- generic small GEMM: out[64,N] = act(A[64,K] @ Bw[N,K]^T + bias) ----
// MODE 0: tanh    MODE 1: identity    MODE 2: identity -> out, exp(val) -> out2
template <int MODE>
__global__ __launch_bounds__(256) void gemm_bias_act(
    const float* __restrict__ A, const float* __restrict__ Bw,
    const float* __restrict__ bias, float* __restrict__ out,
    int N, int K, float* __restrict__ out2)
{
    __shared__ float As[16 * 68];
    __shared__ float Bs[16 * 68];
    const int t = threadIdx.x;
    const int tx = t & 15, ty = t >> 4;
    const int n_base = blockIdx.x * 64;

    float acc[4][4];
#pragma unroll
    for (int r = 0; r < 4; r++)
#pragma unroll
        for (int c = 0; c < 4; c++) acc[r][c] = 0.f;

    for (int k0 = 0; k0 < K; k0 += 16) {
        {   // A tile (64 rows x 16 k), transposed into As[k][m]
            int row = t >> 2, c4 = t & 3;
            float4 v = *reinterpret_cast<const float4*>(A + (size_t)row * K + k0 + c4 * 4);
            As[(c4 * 4 + 0) * 68 + row] = v.x;
            As[(c4 * 4 + 1) * 68 + row] = v.y;
            As[(c4 * 4 + 2) * 68 + row] = v.z;
            As[(c4 * 4 + 3) * 68 + row] = v.w;
        }
        {   // B tile (64 n-rows x 16 k), transposed into Bs[k][n]
            int row = t >> 2, c4 = t & 3;
            int ng = n_base + row;
            float4 v = make_float4(0.f, 0.f, 0.f, 0.f);
            if (ng < N) v = *reinterpret_cast<const float4*>(Bw + (size_t)ng * K + k0 + c4 * 4);
            Bs[(c4 * 4 + 0) * 68 + row] = v.x;
            Bs[(c4 * 4 + 1) * 68 + row] = v.y;
            Bs[(c4 * 4 + 2) * 68 + row] = v.z;
            Bs[(c4 * 4 + 3) * 68 + row] = v.w;
        }
        __syncthreads();
#pragma unroll
        for (int kk = 0; kk < 16; kk++) {
            float4 am = *reinterpret_cast<const float4*>(&As[kk * 68 + ty * 4]);
            float4 bn = *reinterpret_cast<const float4*>(&Bs[kk * 68 + tx * 4]);
            float a[4] = {am.x, am.y, am.z, am.w};
            float bb[4] = {bn.x, bn.y, bn.z, bn.w};
#pragma unroll
            for (int r = 0; r < 4; r++)
#pragma unroll
                for (int c = 0; c < 4; c++) acc[r][c] += a[r] * bb[c];
        }
        __syncthreads();
    }

#pragma unroll
    for (int r = 0; r < 4; r++) {
        int m = ty * 4 + r;
#pragma unroll
        for (int c = 0; c < 4; c++) {
            int ng = n_base + tx * 4 + c;
            if (ng < N) {
                float val = acc[r][c] + bias[ng];
                if (MODE == 0) val = tanhf(val);
                out[(size_t)m * N + ng] = val;
                if (MODE == 2) out2[(size_t)m * N + ng] = expf(val);
            }
        }
    }
}

// ------------------- moments (tanh): A0..A3 coefficients + clipped diag --------
__global__ void moments_tanh(const float* __restrict__ w3)
{
    int idx = blockIdx.x * blockDim.x + threadIdx.x;
    if (idx >= 64 * 512) return;
    int b = idx >> 9, i = idx & 511;

    const float* wr = w3 + i * 64;
    const float* zr = g_zvar + b * 64;
    float v = 0.f;
#pragma unroll 8
    for (int l = 0; l < 64; l++) v += wr[l] * wr[l] * zr[l];
    v = fmaxf(v, EPSC);

    float m = g_m3[idx];
    float s0 = 0.f, s1 = 0.f, s2 = 0.f, s3 = 0.f;
#pragma unroll
    for (int g = 0; g < 10; g++) {
        float gam = GT[g];
        float cg = 1.0f / (2.0f * gam * gam);
        float ivh = v + cg;
        float sq = sqrtf(ivh);
        float mu = m / sq;
        float Bv = expf(-0.5f * mu * mu) * INV_SQRT_2PI / sq;
        float Cv = 0.5f * (1.0f + erff(mu * 0.70710678118654752f));
        s0 += 2.f * Cv - 1.f;
        s1 += 2.f * Bv;
        s2 += -Bv * m / ivh;
        s3 += (1.f / 3.f) * Bv * (m * m - ivh) / (ivh * ivh);
    }
    g_a0[idx] = s0 * 0.1f;
    g_a1[idx] = s1 * 0.1f;
    g_a2[idx] = s2 * 0.1f;
    g_a3[idx] = s3 * 0.1f;
    g_v[idx]  = v;
}

// ------------------- build H = cov_h3 (fused cov3 + moment transform) ----------
__global__ __launch_bounds__(256, 2) void build_H(const float* __restrict__ w3)
{
    __shared__ float Wi[32 * 132];
    __shared__ float Wj[32 * 132];
    const int t = threadIdx.x;
    const int tx = t & 15, ty = t >> 4;
    const int ib = blockIdx.x * 128, jb = blockIdx.y * 128, b = blockIdx.z;
    const float* zr = g_zvar + b * 64;

    float acc[8][8];
#pragma unroll
    for (int r = 0; r < 8; r++)
#pragma unroll
        for (int c = 0; c < 8; c++) acc[r][c] = 0.f;

    for (int lc = 0; lc < 64; lc += 32) {
#pragma unroll
        for (int q = 0; q < 4; q++) {
            int f = t + q * 256;         // [0,1024)
            int row = f >> 3, c4 = f & 7;
            int l = lc + c4 * 4;
            float4 vi = *reinterpret_cast<const float4*>(w3 + (size_t)(ib + row) * 64 + l);
            Wi[(c4 * 4 + 0) * 132 + row] = vi.x;
            Wi[(c4 * 4 + 1) * 132 + row] = vi.y;
            Wi[(c4 * 4 + 2) * 132 + row] = vi.z;
            Wi[(c4 * 4 + 3) * 132 + row] = vi.w;
            float4 vj = *reinterpret_cast<const float4*>(w3 + (size_t)(jb + row) * 64 + l);
            Wj[(c4 * 4 + 0) * 132 + row] = vj.x * zr[l + 0];
            Wj[(c4 * 4 + 1) * 132 + row] = vj.y * zr[l + 1];
            Wj[(c4 * 4 + 2) * 132 + row] = vj.z * zr[l + 2];
            Wj[(c4 * 4 + 3) * 132 + row] = vj.w * zr[l + 3];
        }
        __syncthreads();
#pragma unroll
        for (int l = 0; l < 32; l++) {
            float a[8], bb[8];
            *reinterpret_cast<float4*>(a)      = *reinterpret_cast<const float4*>(&Wi[l * 132 + ty * 8]);
            *reinterpret_cast<float4*>(a + 4)  = *reinterpret_cast<const float4*>(&Wi[l * 132 + ty * 8 + 4]);
            *reinterpret_cast<float4*>(bb)     = *reinterpret_cast<const float4*>(&Wj[l * 132 + tx * 8]);
            *reinterpret_cast<float4*>(bb + 4) = *reinterpret_cast<const float4*>(&Wj[l * 132 + tx * 8 + 4]);
#pragma unroll
            for (int r = 0; r < 8; r++)
#pragma unroll
                for (int c = 0; c < 8; c++) acc[r][c] += a[r] * bb[c];
        }
        __syncthreads();
    }

    float a1i[8], a2i[8], a3i[8], vi[8];
    float a1j[8], a2j[8], a3j[8], vj[8];
#pragma unroll
    for (int r = 0; r < 8; r++) {
        int ig = b * 512 + ib + ty * 8 + r;
        a1i[r] = g_a1[ig]; a2i[r] = g_a2[ig]; a3i[r] = g_a3[ig]; vi[r] = g_v[ig];
    }
#pragma unroll
    for (int c = 0; c < 8; c++) {
        int jg = b * 512 + jb + tx * 8 + c;
        a1j[c] = g_a1[jg]; a2j[c] = g_a2[jg]; a3j[c] = g_a3[jg]; vj[c] = g_v[jg];
    }
#pragma unroll
    for (int r = 0; r < 8; r++) {
        int ig = ib + ty * 8 + r;
#pragma unroll
        for (int c = 0; c < 8; c++) {
            int jg = jb + tx * 8 + c;
            float c0 = acc[r][c];
            if (ig == jg) c0 = fmaxf(c0, EPSC);
            float c2 = c0 * c0;
            float h = a1i[r] * a1j[c] * c0
                    + 2.f * a2i[r] * a2j[c] * c2
                    + a3i[r] * a3j[c] * (6.f * c2 * c0 + 9.f * vi[r] * vj[c] * c0);
            g_H[((size_t)b * 512 + ig) * 512 + jg] = h;
        }
    }
}

// ------------------- diag41 via tf32 tensor cores ------------------------------
// diag41[b,o] = w41[o,:] H[b] w41[o,:]^T
// Block = 128 o-rows of one batch, 8 warps x 16 rows. mma.sync.m16n8k8 tf32.
// A = w41 (o x k), B = H_b (k x j). Epilogue folds in w41[o,j] and reduces.
#define KC 32
__global__ __launch_bounds__(256, 2) void bilinear_diag_mma(const float* __restrict__ w41)
{
    __shared__ unsigned As[KC][136];   // [k][o]  tf32 bits, 17.4 KB
    __shared__ unsigned Bs[KC][136];   // [k][n]  tf32 bits, 17.4 KB

    const int t = threadIdx.x;
    const int lane = t & 31;
    const int w = t >> 5;              // warp id, owns o rows [w*16, w*16+16)
    const int ob = blockIdx.x * 128;
    const int b  = blockIdx.y;
    const float* Hb = g_H + ((size_t)b << 18);

    const int grp = lane >> 2;         // 0..7
    const int qid = lane & 3;          // 0..3

    float s0 = 0.f, s1 = 0.f;          // partials for rows o_r0, o_r0+8

    const int o_r0 = ob + w * 16 + grp;
    const int o_r1 = o_r0 + 8;

    for (int jt = 0; jt < 4; jt++) {
        const int jb = jt * 128;
        float d[16][4];
#pragma unroll
        for (int nt = 0; nt < 16; nt++)
#pragma unroll
            for (int c = 0; c < 4; c++) d[nt][c] = 0.f;

        for (int kc = 0; kc < 512; kc += KC) {
            // load A chunk: w41[ob..+128, kc..+KC] -> As[k][o] (transposed, tf32)
#pragma unroll
            for (int q = 0; q < 4; q++) {
                int f = t + q * 256;             // [0,1024)
                int row = f >> 3, c4 = f & 7;    // 128 rows x 8 float4
                int og = ob + row;
                float4 v = make_float4(0.f, 0.f, 0.f, 0.f);
                if (og < 784) v = *reinterpret_cast<const float4*>(w41 + (size_t)og * 512 + kc + c4 * 4);
                As[c4 * 4 + 0][row] = f2tf32(v.x);
                As[c4 * 4 + 1][row] = f2tf32(v.y);
                As[c4 * 4 + 2][row] = f2tf32(v.z);
                As[c4 * 4 + 3][row] = f2tf32(v.w);
            }
            // load B chunk: H[kc..+KC, jb..+128] -> Bs[k][n] (tf32)
#pragma unroll
            for (int q = 0; q < 4; q++) {
                int f = t + q * 256;             // [0,1024)
                int row = f >> 5, c4 = f & 31;   // 32 rows x 32 float4
                float4 v = *reinterpret_cast<const float4*>(Hb + (size_t)(kc + row) * 512 + jb + c4 * 4);
                Bs[row][c4 * 4 + 0] = f2tf32(v.x);
                Bs[row][c4 * 4 + 1] = f2tf32(v.y);
                Bs[row][c4 * 4 + 2] = f2tf32(v.z);
                Bs[row][c4 * 4 + 3] = f2tf32(v.w);
            }
            __syncthreads();

#pragma unroll
            for (int kk = 0; kk < KC / 8; kk++) {
                // A fragment for this warp's 16 rows, k-slab kk*8..+8
                unsigned a0 = As[kk * 8 + qid    ][w * 16 + grp];
                unsigned a1 = As[kk * 8 + qid    ][w * 16 + grp + 8];
                unsigned a2 = As[kk * 8 + qid + 4][w * 16 + grp];
                unsigned a3 = As[kk * 8 + qid + 4][w * 16 + grp + 8];
#pragma unroll
                for (int nt = 0; nt < 16; nt++) {
                    unsigned b0 = Bs[kk * 8 + qid    ][nt * 8 + grp];
                    unsigned b1 = Bs[kk * 8 + qid + 4][nt * 8 + grp];
                    asm volatile(
                        "mma.sync.aligned.m16n8k8.row.col.f32.tf32.tf32.f32 "
                        "{%0,%1,%2,%3}, {%4,%5,%6,%7}, {%8,%9}, {%0,%1,%2,%3};"
                        : "+f"(d[nt][0]), "+f"(d[nt][1]), "+f"(d[nt][2]), "+f"(d[nt][3])
                        : "r"(a0), "r"(a1), "r"(a2), "r"(a3), "r"(b0), "r"(b1));
                }
            }
            __syncthreads();
        }

        // epilogue: fold in w41[o, j] for this j-tile
        if (o_r0 < 784) {
#pragma unroll
            for (int nt = 0; nt < 16; nt++) {
                int j0 = jb + nt * 8 + qid * 2;
                float2 u0 = *reinterpret_cast<const float2*>(w41 + (size_t)o_r0 * 512 + j0);
                float2 u1 = *reinterpret_cast<const float2*>(w41 + (size_t)o_r1 * 512 + j0);
                s0 += d[nt][0] * u0.x + d[nt][1] * u0.y;
                s1 += d[nt][2] * u1.x + d[nt][3] * u1.y;
            }
        }
    }

    // reduce across the 4 lanes sharing each row
    s0 += __shfl_xor_sync(0xffffffff, s0, 1);
    s0 += __shfl_xor_sync(0xffffffff, s0, 2);
    s1 += __shfl_xor_sync(0xffffffff, s1, 1);
    s1 += __shfl_xor_sync(0xffffffff, s1, 2);
    if (qid == 0 && o_r0 < 784) {
        g_diag41[b * 784 + o_r0] = s0;
        g_diag41[b * 784 + o_r1] = s1;
    }
}

// ------------------- probs: sigmoid A0 only ------------------------------------
__global__ void probs_kernel(float* __restrict__ out)
{
    int idx = blockIdx.x * blockDim.x + threadIdx.x;
    if (idx >= 64 * 784) return;
    float v = fmaxf(g_diag41[idx], EPSC);
    float m = g_m41[idx];
    float s = 0.f;
#pragma unroll
    for (int g = 0; g < 10; g++) {
        float gam = GS[g];
        float cg = 1.0f / (2.0f * gam * gam);
        float ivh = v + cg;
        s += 0.5f * (1.0f + erff(m / sqrtf(2.0f * ivh)));
    }
    out[idx] = s * 0.1f;
}

// ------------------- launcher --------------------------------------------------
extern "C" void kernel_launch(void* const* d_in, const int* in_sizes, int n_in,
                              void* d_out, int out_size)
{
    const float* x   = (const float*)d_in[0];
    const float* w1  = (const float*)d_in[1];
    const float* b1  = (const float*)d_in[2];
    const float* w21 = (const float*)d_in[3];
    const float* b21 = (const float*)d_in[4];
    const float* w22 = (const float*)d_in[5];
    const float* b22 = (const float*)d_in[6];
    const float* w3  = (const float*)d_in[7];
    const float* b3  = (const float*)d_in[8];
    const float* w41 = (const float*)d_in[9];
    const float* b41 = (const float*)d_in[10];
    float* out = (float*)d_out;

    float *h1, *zvar, *m3, *a0, *m41;
    cudaGetSymbolAddress((void**)&h1,   g_h1);
    cudaGetSymbolAddress((void**)&zvar, g_zvar);
    cudaGetSymbolAddress((void**)&m3,   g_m3);
    cudaGetSymbolAddress((void**)&a0,   g_a0);
    cudaGetSymbolAddress((void**)&m41,  g_m41);

    // h1 = tanh(x @ w1.T + b1)                       [64,512]
    gemm_bias_act<0><<<8, 256>>>(x, w1, b1, h1, 512, 784, nullptr);
    // z_mean -> out[0:4096]                          [64,64]
    gemm_bias_act<1><<<1, 256>>>(h1, w21, b21, out, 64, 512, nullptr);
    // z_logvar -> out[4096:8192], z_var -> scratch   [64,64]
    gemm_bias_act<2><<<1, 256>>>(h1, w22, b22, out + 64 * 64, 64, 512, zvar);
    // m3 = z_mean @ w3.T + b3                        [64,512]
    gemm_bias_act<1><<<8, 256>>>(out, w3, b3, m3, 512, 64, nullptr);
    // tanh moment coefficients + clipped diag
    moments_tanh<<<128, 256>>>(w3);
    // H = cov_h3 (fused cov3 construction + transform)
    build_H<<<dim3(4, 4, 64), 256>>>(w3);
    // m41 = a0 @ w41.T + b41                         [64,784]
    gemm_bias_act<1><<<13, 256>>>(a0, w41, b41, m41, 784, 512, nullptr);
    // diag of cov41 only -- now on tensor cores (tf32)
    bilinear_diag_mma<<<dim3(7, 64), 256>>>(w41);
    // probs -> out[8192:]
    probs_kernel<<<(64 * 784 + 255) / 256, 256>>>(out + 2 * 64 * 64);
}

// round 4
// speedup vs baseline: 3.8120x; 1.8788x over previous
#include <cuda_runtime.h>
#include <cuda_bf16.h>
#include <math.h>

#define EPSC 1e-6f
#define INV_SQRT_2PI 0.3989422804014327f

__constant__ float GT[10] = {0.715951561820333f, 1.039358092507381f, 0.948607106485449f,
                             0.715951555650637f, 0.715951343627955f, 1.039354251532628f,
                             0.484068718800797f, 0.715951452277779f, 1.039355768740833f,
                             1.446433070133343f};
__constant__ float GS[10] = {0.519483084417772f, 0.357944855434941f, 0.723301195883257f,
                             0.474918009444542f, 0.519483382721337f, 0.357945091498072f,
                             0.519481351904163f, 0.357945544542554f, 0.242049896394596f,
                             0.357944917042638f};

// ------------------- scratch (__device__ globals, no allocs) -------------------
__device__ float g_h1[64 * 512];
__device__ float g_zvar[64 * 64];
__device__ float g_m3[64 * 512];
__device__ float g_a0[64 * 512];
__device__ float g_a1[64 * 512];
__device__ float g_a2[64 * 512];
__device__ float g_a3[64 * 512];
__device__ float g_v[64 * 512];
__device__ __nv_bfloat16 g_Hbf[(size_t)64 * 512 * 512];   // cov_h3 in bf16, 33.5 MB
__device__ __nv_bfloat16 g_w41bf[784 * 512];
__device__ float g_m41[64 * 784];
__device__ float g_diag41[64 * 784];

// ------------------- generic small GEMM: out[64,N] = act(A[64,K] @ Bw[N,K]^T + bias) ----
// MODE 0: tanh    MODE 1: identity    MODE 2: identity -> out, exp(val) -> out2
template <int MODE>
__global__ __launch_bounds__(256) void gemm_bias_act(
    const float* __restrict__ A, const float* __restrict__ Bw,
    const float* __restrict__ bias, float* __restrict__ out,
    int N, int K, float* __restrict__ out2)
{
    __shared__ float As[16 * 68];
    __shared__ float Bs[16 * 68];
    const int t = threadIdx.x;
    const int tx = t & 15, ty = t >> 4;
    const int n_base = blockIdx.x * 64;

    float acc[4][4];
#pragma unroll
    for (int r = 0; r < 4; r++)
#pragma unroll
        for (int c = 0; c < 4; c++) acc[r][c] = 0.f;

    for (int k0 = 0; k0 < K; k0 += 16) {
        {
            int row = t >> 2, c4 = t & 3;
            float4 v = *reinterpret_cast<const float4*>(A + (size_t)row * K + k0 + c4 * 4);
            As[(c4 * 4 + 0) * 68 + row] = v.x;
            As[(c4 * 4 + 1) * 68 + row] = v.y;
            As[(c4 * 4 + 2) * 68 + row] = v.z;
            As[(c4 * 4 + 3) * 68 + row] = v.w;
        }
        {
            int row = t >> 2, c4 = t & 3;
            int ng = n_base + row;
            float4 v = make_float4(0.f, 0.f, 0.f, 0.f);
            if (ng < N) v = *reinterpret_cast<const float4*>(Bw + (size_t)ng * K + k0 + c4 * 4);
            Bs[(c4 * 4 + 0) * 68 + row] = v.x;
            Bs[(c4 * 4 + 1) * 68 + row] = v.y;
            Bs[(c4 * 4 + 2) * 68 + row] = v.z;
            Bs[(c4 * 4 + 3) * 68 + row] = v.w;
        }
        __syncthreads();
#pragma unroll
        for (int kk = 0; kk < 16; kk++) {
            float4 am = *reinterpret_cast<const float4*>(&As[kk * 68 + ty * 4]);
            float4 bn = *reinterpret_cast<const float4*>(&Bs[kk * 68 + tx * 4]);
            float a[4] = {am.x, am.y, am.z, am.w};
            float bb[4] = {bn.x, bn.y, bn.z, bn.w};
#pragma unroll
            for (int r = 0; r < 4; r++)
#pragma unroll
                for (int c = 0; c < 4; c++) acc[r][c] += a[r] * bb[c];
        }
        __syncthreads();
    }

#pragma unroll
    for (int r = 0; r < 4; r++) {
        int m = ty * 4 + r;
#pragma unroll
        for (int c = 0; c < 4; c++) {
            int ng = n_base + tx * 4 + c;
            if (ng < N) {
                float val = acc[r][c] + bias[ng];
                if (MODE == 0) val = tanhf(val);
                out[(size_t)m * N + ng] = val;
                if (MODE == 2) out2[(size_t)m * N + ng] = expf(val);
            }
        }
    }
}

// ------------------- moments (tanh): A0..A3 coefficients + clipped diag --------
__global__ void moments_tanh(const float* __restrict__ w3)
{
    int idx = blockIdx.x * blockDim.x + threadIdx.x;
    if (idx >= 64 * 512) return;
    int b = idx >> 9, i = idx & 511;

    const float* wr = w3 + i * 64;
    const float* zr = g_zvar + b * 64;
    float v = 0.f;
#pragma unroll 8
    for (int l = 0; l < 64; l++) v += wr[l] * wr[l] * zr[l];
    v = fmaxf(v, EPSC);

    float m = g_m3[idx];
    float s0 = 0.f, s1 = 0.f, s2 = 0.f, s3 = 0.f;
#pragma unroll
    for (int g = 0; g < 10; g++) {
        float gam = GT[g];
        float cg = 1.0f / (2.0f * gam * gam);
        float ivh = v + cg;
        float sq = sqrtf(ivh);
        float mu = m / sq;
        float Bv = expf(-0.5f * mu * mu) * INV_SQRT_2PI / sq;
        float Cv = 0.5f * (1.0f + erff(mu * 0.70710678118654752f));
        s0 += 2.f * Cv - 1.f;
        s1 += 2.f * Bv;
        s2 += -Bv * m / ivh;
        s3 += (1.f / 3.f) * Bv * (m * m - ivh) / (ivh * ivh);
    }
    g_a0[idx] = s0 * 0.1f;
    g_a1[idx] = s1 * 0.1f;
    g_a2[idx] = s2 * 0.1f;
    g_a3[idx] = s3 * 0.1f;
    g_v[idx]  = v;
}

// ------------------- w41 -> bf16 one-shot conversion ---------------------------
__global__ void conv_w41(const float* __restrict__ w41)
{
    int i = blockIdx.x * 256 + threadIdx.x;   // over pairs
    if (i < 784 * 512 / 2) {
        float2 v = reinterpret_cast<const float2*>(w41)[i];
        reinterpret_cast<__nv_bfloat162*>(g_w41bf)[i] =
            __floats2bfloat162_rn(v.x, v.y);
    }
}

// ------------------- build H = cov_h3 (fused cov3 + moment transform) ----------
// Emits bf16 H with packed 16-byte stores.
__global__ __launch_bounds__(256, 2) void build_H(const float* __restrict__ w3)
{
    __shared__ float Wi[32 * 132];
    __shared__ float Wj[32 * 132];
    const int t = threadIdx.x;
    const int tx = t & 15, ty = t >> 4;
    const int ib = blockIdx.x * 128, jb = blockIdx.y * 128, b = blockIdx.z;
    const float* zr = g_zvar + b * 64;

    float acc[8][8];
#pragma unroll
    for (int r = 0; r < 8; r++)
#pragma unroll
        for (int c = 0; c < 8; c++) acc[r][c] = 0.f;

    for (int lc = 0; lc < 64; lc += 32) {
#pragma unroll
        for (int q = 0; q < 4; q++) {
            int f = t + q * 256;
            int row = f >> 3, c4 = f & 7;
            int l = lc + c4 * 4;
            float4 vi = *reinterpret_cast<const float4*>(w3 + (size_t)(ib + row) * 64 + l);
            Wi[(c4 * 4 + 0) * 132 + row] = vi.x;
            Wi[(c4 * 4 + 1) * 132 + row] = vi.y;
            Wi[(c4 * 4 + 2) * 132 + row] = vi.z;
            Wi[(c4 * 4 + 3) * 132 + row] = vi.w;
            float4 vj = *reinterpret_cast<const float4*>(w3 + (size_t)(jb + row) * 64 + l);
            Wj[(c4 * 4 + 0) * 132 + row] = vj.x * zr[l + 0];
            Wj[(c4 * 4 + 1) * 132 + row] = vj.y * zr[l + 1];
            Wj[(c4 * 4 + 2) * 132 + row] = vj.z * zr[l + 2];
            Wj[(c4 * 4 + 3) * 132 + row] = vj.w * zr[l + 3];
        }
        __syncthreads();
#pragma unroll
        for (int l = 0; l < 32; l++) {
            float a[8], bb[8];
            *reinterpret_cast<float4*>(a)      = *reinterpret_cast<const float4*>(&Wi[l * 132 + ty * 8]);
            *reinterpret_cast<float4*>(a + 4)  = *reinterpret_cast<const float4*>(&Wi[l * 132 + ty * 8 + 4]);
            *reinterpret_cast<float4*>(bb)     = *reinterpret_cast<const float4*>(&Wj[l * 132 + tx * 8]);
            *reinterpret_cast<float4*>(bb + 4) = *reinterpret_cast<const float4*>(&Wj[l * 132 + tx * 8 + 4]);
#pragma unroll
            for (int r = 0; r < 8; r++)
#pragma unroll
                for (int c = 0; c < 8; c++) acc[r][c] += a[r] * bb[c];
        }
        __syncthreads();
    }

    float a1i[8], a2i[8], a3i[8], vi[8];
    float a1j[8], a2j[8], a3j[8], vj[8];
#pragma unroll
    for (int r = 0; r < 8; r++) {
        int ig = b * 512 + ib + ty * 8 + r;
        a1i[r] = g_a1[ig]; a2i[r] = g_a2[ig]; a3i[r] = g_a3[ig]; vi[r] = g_v[ig];
    }
#pragma unroll
    for (int c = 0; c < 8; c++) {
        int jg = b * 512 + jb + tx * 8 + c;
        a1j[c] = g_a1[jg]; a2j[c] = g_a2[jg]; a3j[c] = g_a3[jg]; vj[c] = g_v[jg];
    }
#pragma unroll
    for (int r = 0; r < 8; r++) {
        int ig = ib + ty * 8 + r;
        __nv_bfloat162 pk[4];
#pragma unroll
        for (int c2 = 0; c2 < 4; c2++) {
            float hv[2];
#pragma unroll
            for (int u = 0; u < 2; u++) {
                int c = c2 * 2 + u;
                int jg = jb + tx * 8 + c;
                float c0 = acc[r][c];
                if (ig == jg) c0 = fmaxf(c0, EPSC);
                float cc2 = c0 * c0;
                hv[u] = a1i[r] * a1j[c] * c0
                      + 2.f * a2i[r] * a2j[c] * cc2
                      + a3i[r] * a3j[c] * (6.f * cc2 * c0 + 9.f * vi[r] * vj[c] * c0);
            }
            pk[c2] = __floats2bfloat162_rn(hv[0], hv[1]);
        }
        *reinterpret_cast<uint4*>(&g_Hbf[((size_t)b * 512 + ig) * 512 + jb + tx * 8]) =
            *reinterpret_cast<const uint4*>(pk);
    }
}

// ------------------- diag41 via bf16 tensor cores ------------------------------
// diag41[b,o] = w41[o,:] H[b] w41[o,:]^T   (H symmetric -> B tile read row-major
// along the contraction dim; all SMEM stores are direct float4, all fragment
// loads are single conflict-free 32-bit LDS).
__global__ __launch_bounds__(256, 2) void bilinear_diag_bf16(const float* __restrict__ w41)
{
    __shared__ __align__(16) __nv_bfloat16 As[128][72];   // [o][k], stride 36 words
    __shared__ __align__(16) __nv_bfloat16 Bs[128][72];   // [j][i] = H[j][i] (sym)

    const int t = threadIdx.x;
    const int lane = t & 31;
    const int w = t >> 5;                 // warp -> o rows [w*16, w*16+16)
    const int ob = blockIdx.x * 128;
    const int b  = blockIdx.y;
    const __nv_bfloat16* Hb = g_Hbf + ((size_t)b << 18);

    const int grp = lane >> 2;            // 0..7
    const int qid = lane & 3;             // 0..3
    const unsigned* Asw = reinterpret_cast<const unsigned*>(As);
    const unsigned* Bsw = reinterpret_cast<const unsigned*>(Bs);
    const int ar0 = (w * 16 + grp) * 36;
    const int ar1 = ar0 + 8 * 36;

    float s0 = 0.f, s1 = 0.f;
    const int o_r0 = ob + w * 16 + grp;
    const int o_r1 = o_r0 + 8;

    for (int jt = 0; jt < 4; jt++) {
        const int jb = jt * 128;
        float d[16][4];
#pragma unroll
        for (int nt = 0; nt < 16; nt++)
#pragma unroll
            for (int c = 0; c < 4; c++) d[nt][c] = 0.f;

        for (int kc = 0; kc < 512; kc += 64) {
#pragma unroll
            for (int q = 0; q < 4; q++) {
                int f = t + q * 256;             // [0,1024)
                int row = f >> 3, g = f & 7;     // 128 rows x 8 x (8 bf16)
                int og = ob + row;
                uint4 av = make_uint4(0, 0, 0, 0);
                if (og < 784)
                    av = *reinterpret_cast<const uint4*>(g_w41bf + (size_t)og * 512 + kc + g * 8);
                *reinterpret_cast<uint4*>(&As[row][g * 8]) = av;
                uint4 bv = *reinterpret_cast<const uint4*>(Hb + (size_t)(jb + row) * 512 + kc + g * 8);
                *reinterpret_cast<uint4*>(&Bs[row][g * 8]) = bv;
            }
            __syncthreads();

#pragma unroll
            for (int kk = 0; kk < 4; kk++) {
                unsigned a0 = Asw[ar0 + kk * 8 + qid];
                unsigned a1 = Asw[ar1 + kk * 8 + qid];
                unsigned a2 = Asw[ar0 + kk * 8 + qid + 4];
                unsigned a3 = Asw[ar1 + kk * 8 + qid + 4];
#pragma unroll
                for (int nt = 0; nt < 16; nt++) {
                    int br = (nt * 8 + grp) * 36 + kk * 8 + qid;
                    unsigned b0 = Bsw[br];
                    unsigned b1 = Bsw[br + 4];
                    asm volatile(
                        "mma.sync.aligned.m16n8k16.row.col.f32.bf16.bf16.f32 "
                        "{%0,%1,%2,%3}, {%4,%5,%6,%7}, {%8,%9}, {%0,%1,%2,%3};"
                        : "+f"(d[nt][0]), "+f"(d[nt][1]), "+f"(d[nt][2]), "+f"(d[nt][3])
                        : "r"(a0), "r"(a1), "r"(a2), "r"(a3), "r"(b0), "r"(b1));
                }
            }
            __syncthreads();
        }

        // epilogue: fold in w41[o, j] (fp32) for this j-tile
        if (o_r0 < 784) {
#pragma unroll
            for (int nt = 0; nt < 16; nt++) {
                int j0 = jb + nt * 8 + qid * 2;
                float2 u0 = *reinterpret_cast<const float2*>(w41 + (size_t)o_r0 * 512 + j0);
                float2 u1 = *reinterpret_cast<const float2*>(w41 + (size_t)o_r1 * 512 + j0);
                s0 += d[nt][0] * u0.x + d[nt][1] * u0.y;
                s1 += d[nt][2] * u1.x + d[nt][3] * u1.y;
            }
        }
    }

    s0 += __shfl_xor_sync(0xffffffff, s0, 1);
    s0 += __shfl_xor_sync(0xffffffff, s0, 2);
    s1 += __shfl_xor_sync(0xffffffff, s1, 1);
    s1 += __shfl_xor_sync(0xffffffff, s1, 2);
    if (qid == 0 && o_r0 < 784) {
        g_diag41[b * 784 + o_r0] = s0;
        g_diag41[b * 784 + o_r1] = s1;
    }
}

// ------------------- probs: sigmoid A0 only ------------------------------------
__global__ void probs_kernel(float* __restrict__ out)
{
    int idx = blockIdx.x * blockDim.x + threadIdx.x;
    if (idx >= 64 * 784) return;
    float v = fmaxf(g_diag41[idx], EPSC);
    float m = g_m41[idx];
    float s = 0.f;
#pragma unroll
    for (int g = 0; g < 10; g++) {
        float gam = GS[g];
        float cg = 1.0f / (2.0f * gam * gam);
        float ivh = v + cg;
        s += 0.5f * (1.0f + erff(m / sqrtf(2.0f * ivh)));
    }
    out[idx] = s * 0.1f;
}

// ------------------- launcher --------------------------------------------------
extern "C" void kernel_launch(void* const* d_in, const int* in_sizes, int n_in,
                              void* d_out, int out_size)
{
    const float* x   = (const float*)d_in[0];
    const float* w1  = (const float*)d_in[1];
    const float* b1  = (const float*)d_in[2];
    const float* w21 = (const float*)d_in[3];
    const float* b21 = (const float*)d_in[4];
    const float* w22 = (const float*)d_in[5];
    const float* b22 = (const float*)d_in[6];
    const float* w3  = (const float*)d_in[7];
    const float* b3  = (const float*)d_in[8];
    const float* w41 = (const float*)d_in[9];
    const float* b41 = (const float*)d_in[10];
    float* out = (float*)d_out;

    float *h1, *zvar, *m3, *a0, *m41;
    cudaGetSymbolAddress((void**)&h1,   g_h1);
    cudaGetSymbolAddress((void**)&zvar, g_zvar);
    cudaGetSymbolAddress((void**)&m3,   g_m3);
    cudaGetSymbolAddress((void**)&a0,   g_a0);
    cudaGetSymbolAddress((void**)&m41,  g_m41);

    // one-shot weight conversion (independent of everything else)
    conv_w41<<<784, 256>>>(w41);
    // h1 = tanh(x @ w1.T + b1)                       [64,512]
    gemm_bias_act<0><<<8, 256>>>(x, w1, b1, h1, 512, 784, nullptr);
    // z_mean -> out[0:4096]                          [64,64]
    gemm_bias_act<1><<<1, 256>>>(h1, w21, b21, out, 64, 512, nullptr);
    // z_logvar -> out[4096:8192], z_var -> scratch   [64,64]
    gemm_bias_act<2><<<1, 256>>>(h1, w22, b22, out + 64 * 64, 64, 512, zvar);
    // m3 = z_mean @ w3.T + b3                        [64,512]
    gemm_bias_act<1><<<8, 256>>>(out, w3, b3, m3, 512, 64, nullptr);
    // tanh moment coefficients + clipped diag
    moments_tanh<<<128, 256>>>(w3);
    // H = cov_h3 (fused cov3 construction + transform), bf16 output
    build_H<<<dim3(4, 4, 64), 256>>>(w3);
    // m41 = a0 @ w41.T + b41                         [64,784]
    gemm_bias_act<1><<<13, 256>>>(a0, w41, b41, m41, 784, 512, nullptr);
    // diag of cov41 only -- bf16 tensor cores, symmetric-H layout
    bilinear_diag_bf16<<<dim3(7, 64), 256>>>(w41);
    // probs -> out[8192:]
    probs_kernel<<<(64 * 784 + 255) / 256, 256>>>(out + 2 * 64 * 64);
}

// round 5
// speedup vs baseline: 7.1633x; 1.8791x over previous
#include <cuda_runtime.h>
#include <cuda_bf16.h>
#include <math.h>

#define EPSC 1e-6f
#define INV_SQRT_2PI 0.3989422804014327f

__constant__ float GT[10] = {0.715951561820333f, 1.039358092507381f, 0.948607106485449f,
                             0.715951555650637f, 0.715951343627955f, 1.039354251532628f,
                             0.484068718800797f, 0.715951452277779f, 1.039355768740833f,
                             1.446433070133343f};
__constant__ float GS[10] = {0.519483084417772f, 0.357944855434941f, 0.723301195883257f,
                             0.474918009444542f, 0.519483382721337f, 0.519481351904163f ? 0.357945091498072f : 0.357945091498072f,
                             0.519481351904163f, 0.357945544542554f, 0.242049896394596f,
                             0.357944917042638f};
// NOTE: the ternary above is a constant-folded identity (kept values identical to reference).

// lower-triangle tile-pair tables for build_H (row tile >= col tile)
__constant__ int RT[10] = {0, 1, 1, 2, 2, 2, 3, 3, 3, 3};
__constant__ int CT[10] = {0, 0, 1, 0, 1, 2, 0, 1, 2, 3};

// ------------------- scratch (__device__ globals, no allocs) -------------------
__device__ float g_h1[64 * 512];
__device__ float g_zvar[64 * 64];
__device__ float g_m3[64 * 512];
__device__ float g_a0[64 * 512];
__device__ float g_a1[64 * 512];
__device__ float g_a2[64 * 512];
__device__ float g_a3[64 * 512];
__device__ float g_v[64 * 512];
__device__ __nv_bfloat16 g_Hbf[(size_t)64 * 512 * 512];   // G = lower(H)+half-diag, bf16
__device__ __nv_bfloat16 g_w41bf[784 * 512];
__device__ float g_m41[64 * 784];

// ------------------- warp-tile small GEMM --------------------------------------
// Each warp computes a 2x2 output tile of out[M,N] = act(A[M,K] @ Bw[N,K]^T + b).
// MODE 0: tanh   MODE 1: identity   MODE 2: identity -> out, exp -> out2
template <int MODE>
__global__ __launch_bounds__(256) void gemm_warp(
    const float* __restrict__ A, const float* __restrict__ Bw,
    const float* __restrict__ bias, float* __restrict__ out,
    int M, int N, int K, float* __restrict__ out2)
{
    const int wid  = (blockIdx.x * blockDim.x + threadIdx.x) >> 5;
    const int lane = threadIdx.x & 31;
    const int ntiles = N >> 1;
    const int tm = wid / ntiles;
    const int tn = wid - tm * ntiles;
    const int m0 = tm * 2, n0 = tn * 2;
    if (m0 >= M) return;

    const float4* a0p = reinterpret_cast<const float4*>(A + (size_t)m0 * K);
    const float4* a1p = reinterpret_cast<const float4*>(A + (size_t)(m0 + 1) * K);
    const float4* w0p = reinterpret_cast<const float4*>(Bw + (size_t)n0 * K);
    const float4* w1p = reinterpret_cast<const float4*>(Bw + (size_t)(n0 + 1) * K);
    const int K4 = K >> 2;

    float s00 = 0.f, s01 = 0.f, s10 = 0.f, s11 = 0.f;
    for (int i = lane; i < K4; i += 32) {
        float4 a0 = a0p[i], a1 = a1p[i], w0 = w0p[i], w1 = w1p[i];
        s00 += a0.x * w0.x + a0.y * w0.y + a0.z * w0.z + a0.w * w0.w;
        s01 += a0.x * w1.x + a0.y * w1.y + a0.z * w1.z + a0.w * w1.w;
        s10 += a1.x * w0.x + a1.y * w0.y + a1.z * w0.z + a1.w * w0.w;
        s11 += a1.x * w1.x + a1.y * w1.y + a1.z * w1.z + a1.w * w1.w;
    }
#pragma unroll
    for (int off = 16; off; off >>= 1) {
        s00 += __shfl_xor_sync(0xffffffff, s00, off);
        s01 += __shfl_xor_sync(0xffffffff, s01, off);
        s10 += __shfl_xor_sync(0xffffffff, s10, off);
        s11 += __shfl_xor_sync(0xffffffff, s11, off);
    }
    if (lane == 0) {
        float b0 = bias[n0], b1 = bias[n0 + 1];
        float v00 = s00 + b0, v01 = s01 + b1, v10 = s10 + b0, v11 = s11 + b1;
        if (MODE == 0) {
            v00 = tanhf(v00); v01 = tanhf(v01); v10 = tanhf(v10); v11 = tanhf(v11);
        }
        out[(size_t)m0 * N + n0]           = v00;
        out[(size_t)m0 * N + n0 + 1]       = v01;
        out[(size_t)(m0 + 1) * N + n0]     = v10;
        out[(size_t)(m0 + 1) * N + n0 + 1] = v11;
        if (MODE == 2) {
            out2[(size_t)m0 * N + n0]           = expf(v00);
            out2[(size_t)m0 * N + n0 + 1]       = expf(v01);
            out2[(size_t)(m0 + 1) * N + n0]     = expf(v10);
            out2[(size_t)(m0 + 1) * N + n0 + 1] = expf(v11);
        }
    }
}

// ------------------- moments (tanh): A0..A3 coefficients + clipped diag --------
__global__ void moments_tanh(const float* __restrict__ w3)
{
    int idx = blockIdx.x * blockDim.x + threadIdx.x;
    if (idx >= 64 * 512) return;
    int b = idx >> 9, i = idx & 511;

    const float* wr = w3 + i * 64;
    const float* zr = g_zvar + b * 64;
    float v = 0.f;
#pragma unroll 8
    for (int l = 0; l < 64; l++) v += wr[l] * wr[l] * zr[l];
    v = fmaxf(v, EPSC);

    float m = g_m3[idx];
    float s0 = 0.f, s1 = 0.f, s2 = 0.f, s3 = 0.f;
#pragma unroll
    for (int g = 0; g < 10; g++) {
        float gam = GT[g];
        float cg = 1.0f / (2.0f * gam * gam);
        float ivh = v + cg;
        float sq = sqrtf(ivh);
        float mu = m / sq;
        float Bv = expf(-0.5f * mu * mu) * INV_SQRT_2PI / sq;
        float Cv = 0.5f * (1.0f + erff(mu * 0.70710678118654752f));
        s0 += 2.f * Cv - 1.f;
        s1 += 2.f * Bv;
        s2 += -Bv * m / ivh;
        s3 += (1.f / 3.f) * Bv * (m * m - ivh) / (ivh * ivh);
    }
    g_a0[idx] = s0 * 0.1f;
    g_a1[idx] = s1 * 0.1f;
    g_a2[idx] = s2 * 0.1f;
    g_a3[idx] = s3 * 0.1f;
    g_v[idx]  = v;
}

// ------------------- w41 -> bf16 one-shot conversion ---------------------------
__global__ void conv_w41(const float* __restrict__ w41)
{
    int i = blockIdx.x * 256 + threadIdx.x;   // over pairs
    if (i < 784 * 512 / 2) {
        float2 v = reinterpret_cast<const float2*>(w41)[i];
        reinterpret_cast<__nv_bfloat162*>(g_w41bf)[i] =
            __floats2bfloat162_rn(v.x, v.y);
    }
}

// ------------------- build G = lower(H) + half-diag, bf16 ----------------------
// Only 10 lower tile-pairs per batch. Diagonal tiles masked triangularly.
__global__ __launch_bounds__(256, 2) void build_H(const float* __restrict__ w3)
{
    __shared__ float Wi[32 * 132];
    __shared__ float Wj[32 * 132];
    const int t = threadIdx.x;
    const int tx = t & 15, ty = t >> 4;
    const int ib = RT[blockIdx.x] * 128, jb = CT[blockIdx.x] * 128;
    const int b = blockIdx.y;
    const float* zr = g_zvar + b * 64;

    float acc[8][8];
#pragma unroll
    for (int r = 0; r < 8; r++)
#pragma unroll
        for (int c = 0; c < 8; c++) acc[r][c] = 0.f;

    for (int lc = 0; lc < 64; lc += 32) {
#pragma unroll
        for (int q = 0; q < 4; q++) {
            int f = t + q * 256;
            int row = f >> 3, c4 = f & 7;
            int l = lc + c4 * 4;
            float4 vi = *reinterpret_cast<const float4*>(w3 + (size_t)(ib + row) * 64 + l);
            Wi[(c4 * 4 + 0) * 132 + row] = vi.x;
            Wi[(c4 * 4 + 1) * 132 + row] = vi.y;
            Wi[(c4 * 4 + 2) * 132 + row] = vi.z;
            Wi[(c4 * 4 + 3) * 132 + row] = vi.w;
            float4 vj = *reinterpret_cast<const float4*>(w3 + (size_t)(jb + row) * 64 + l);
            Wj[(c4 * 4 + 0) * 132 + row] = vj.x * zr[l + 0];
            Wj[(c4 * 4 + 1) * 132 + row] = vj.y * zr[l + 1];
            Wj[(c4 * 4 + 2) * 132 + row] = vj.z * zr[l + 2];
            Wj[(c4 * 4 + 3) * 132 + row] = vj.w * zr[l + 3];
        }
        __syncthreads();
#pragma unroll
        for (int l = 0; l < 32; l++) {
            float a[8], bb[8];
            *reinterpret_cast<float4*>(a)      = *reinterpret_cast<const float4*>(&Wi[l * 132 + ty * 8]);
            *reinterpret_cast<float4*>(a + 4)  = *reinterpret_cast<const float4*>(&Wi[l * 132 + ty * 8 + 4]);
            *reinterpret_cast<float4*>(bb)     = *reinterpret_cast<const float4*>(&Wj[l * 132 + tx * 8]);
            *reinterpret_cast<float4*>(bb + 4) = *reinterpret_cast<const float4*>(&Wj[l * 132 + tx * 8 + 4]);
#pragma unroll
            for (int r = 0; r < 8; r++)
#pragma unroll
                for (int c = 0; c < 8; c++) acc[r][c] += a[r] * bb[c];
        }
        __syncthreads();
    }

    float a1i[8], a2i[8], a3i[8], vi[8];
    float a1j[8], a2j[8], a3j[8], vj[8];
#pragma unroll
    for (int r = 0; r < 8; r++) {
        int ig = b * 512 + ib + ty * 8 + r;
        a1i[r] = g_a1[ig]; a2i[r] = g_a2[ig]; a3i[r] = g_a3[ig]; vi[r] = g_v[ig];
    }
#pragma unroll
    for (int c = 0; c < 8; c++) {
        int jg = b * 512 + jb + tx * 8 + c;
        a1j[c] = g_a1[jg]; a2j[c] = g_a2[jg]; a3j[c] = g_a3[jg]; vj[c] = g_v[jg];
    }
#pragma unroll
    for (int r = 0; r < 8; r++) {
        int ig = ib + ty * 8 + r;
        __nv_bfloat162 pk[4];
#pragma unroll
        for (int c2 = 0; c2 < 4; c2++) {
            float hv[2];
#pragma unroll
            for (int u = 0; u < 2; u++) {
                int c = c2 * 2 + u;
                int jg = jb + tx * 8 + c;
                float c0 = acc[r][c];
                if (ig == jg) c0 = fmaxf(c0, EPSC);
                float cc2 = c0 * c0;
                float h = a1i[r] * a1j[c] * c0
                        + 2.f * a2i[r] * a2j[c] * cc2
                        + a3i[r] * a3j[c] * (6.f * cc2 * c0 + 9.f * vi[r] * vj[c] * c0);
                // triangular mask: G = strict-lower(H) + 0.5*diag(H)
                if (ig < jg) h = 0.f;
                else if (ig == jg) h *= 0.5f;
                hv[u] = h;
            }
            pk[c2] = __floats2bfloat162_rn(hv[0], hv[1]);
        }
        *reinterpret_cast<uint4*>(&g_Hbf[((size_t)b * 512 + ig) * 512 + jb + tx * 8]) =
            *reinterpret_cast<const uint4*>(pk);
    }
}

// ------------------- diag + probs via bf16 tensor cores ------------------------
// diag[b,o] = 2 * w41[o,:] G[b] w41[o,:]^T  (G lower-triangular: k-loop truncated)
// Fused sigmoid-A0 epilogue writes probs directly.
__global__ __launch_bounds__(256, 2) void bilinear_probs_bf16(
    const float* __restrict__ w41, float* __restrict__ probs_out)
{
    __shared__ __align__(16) __nv_bfloat16 As[128][72];   // [o][k]
    __shared__ __align__(16) __nv_bfloat16 Bs[128][72];   // [j][k] = G[j][k]

    const int t = threadIdx.x;
    const int lane = t & 31;
    const int w = t >> 5;
    const int ob = blockIdx.x * 128;
    const int b  = blockIdx.y;
    const __nv_bfloat16* Hb = g_Hbf + ((size_t)b << 18);

    const int grp = lane >> 2;
    const int qid = lane & 3;
    const unsigned* Asw = reinterpret_cast<const unsigned*>(As);
    const unsigned* Bsw = reinterpret_cast<const unsigned*>(Bs);
    const int ar0 = (w * 16 + grp) * 36;
    const int ar1 = ar0 + 8 * 36;

    float s0 = 0.f, s1 = 0.f;
    const int o_r0 = ob + w * 16 + grp;
    const int o_r1 = o_r0 + 8;

    for (int jt = 0; jt < 4; jt++) {
        const int jb = jt * 128;
        const int kend = (jt + 1) * 128;       // triangular truncation
        float d[16][4];
#pragma unroll
        for (int nt = 0; nt < 16; nt++)
#pragma unroll
            for (int c = 0; c < 4; c++) d[nt][c] = 0.f;

        for (int kc = 0; kc < kend; kc += 64) {
#pragma unroll
            for (int q = 0; q < 4; q++) {
                int f = t + q * 256;
                int row = f >> 3, g = f & 7;
                int og = ob + row;
                uint4 av = make_uint4(0, 0, 0, 0);
                if (og < 784)
                    av = *reinterpret_cast<const uint4*>(g_w41bf + (size_t)og * 512 + kc + g * 8);
                *reinterpret_cast<uint4*>(&As[row][g * 8]) = av;
                uint4 bv = *reinterpret_cast<const uint4*>(Hb + (size_t)(jb + row) * 512 + kc + g * 8);
                *reinterpret_cast<uint4*>(&Bs[row][g * 8]) = bv;
            }
            __syncthreads();

#pragma unroll
            for (int kk = 0; kk < 4; kk++) {
                unsigned a0 = Asw[ar0 + kk * 8 + qid];
                unsigned a1 = Asw[ar1 + kk * 8 + qid];
                unsigned a2 = Asw[ar0 + kk * 8 + qid + 4];
                unsigned a3 = Asw[ar1 + kk * 8 + qid + 4];
#pragma unroll
                for (int nt = 0; nt < 16; nt++) {
                    int br = (nt * 8 + grp) * 36 + kk * 8 + qid;
                    unsigned b0 = Bsw[br];
                    unsigned b1 = Bsw[br + 4];
                    asm volatile(
                        "mma.sync.aligned.m16n8k16.row.col.f32.bf16.bf16.f32 "
                        "{%0,%1,%2,%3}, {%4,%5,%6,%7}, {%8,%9}, {%0,%1,%2,%3};"
                        : "+f"(d[nt][0]), "+f"(d[nt][1]), "+f"(d[nt][2]), "+f"(d[nt][3])
                        : "r"(a0), "r"(a1), "r"(a2), "r"(a3), "r"(b0), "r"(b1));
                }
            }
            __syncthreads();
        }

        if (o_r0 < 784) {
#pragma unroll
            for (int nt = 0; nt < 16; nt++) {
                int j0 = jb + nt * 8 + qid * 2;
                float2 u0 = *reinterpret_cast<const float2*>(w41 + (size_t)o_r0 * 512 + j0);
                float2 u1 = *reinterpret_cast<const float2*>(w41 + (size_t)o_r1 * 512 + j0);
                s0 += d[nt][0] * u0.x + d[nt][1] * u0.y;
                s1 += d[nt][2] * u1.x + d[nt][3] * u1.y;
            }
        }
    }

    s0 += __shfl_xor_sync(0xffffffff, s0, 1);
    s0 += __shfl_xor_sync(0xffffffff, s0, 2);
    s1 += __shfl_xor_sync(0xffffffff, s1, 1);
    s1 += __shfl_xor_sync(0xffffffff, s1, 2);

    if (qid == 0 && o_r0 < 784) {
        float vv[2] = {fmaxf(2.f * s0, EPSC), fmaxf(2.f * s1, EPSC)};
        int oo[2] = {o_r0, o_r1};
#pragma unroll
        for (int u = 0; u < 2; u++) {
            float m = g_m41[b * 784 + oo[u]];
            float s = 0.f;
#pragma unroll
            for (int g = 0; g < 10; g++) {
                float gam = GS[g];
                float cg = 1.0f / (2.0f * gam * gam);
                float ivh = vv[u] + cg;
                s += 0.5f * (1.0f + erff(m / sqrtf(2.0f * ivh)));
            }
            probs_out[b * 784 + oo[u]] = s * 0.1f;
        }
    }
}

// ------------------- launcher --------------------------------------------------
extern "C" void kernel_launch(void* const* d_in, const int* in_sizes, int n_in,
                              void* d_out, int out_size)
{
    const float* x   = (const float*)d_in[0];
    const float* w1  = (const float*)d_in[1];
    const float* b1  = (const float*)d_in[2];
    const float* w21 = (const float*)d_in[3];
    const float* b21 = (const float*)d_in[4];
    const float* w22 = (const float*)d_in[5];
    const float* b22 = (const float*)d_in[6];
    const float* w3  = (const float*)d_in[7];
    const float* b3  = (const float*)d_in[8];
    const float* w41 = (const float*)d_in[9];
    const float* b41 = (const float*)d_in[10];
    float* out = (float*)d_out;

    float *h1, *zvar, *m3, *a0, *m41;
    cudaGetSymbolAddress((void**)&h1,   g_h1);
    cudaGetSymbolAddress((void**)&zvar, g_zvar);
    cudaGetSymbolAddress((void**)&m3,   g_m3);
    cudaGetSymbolAddress((void**)&a0,   g_a0);
    cudaGetSymbolAddress((void**)&m41,  g_m41);

    auto grid_for = [](int M, int N) { return ((M / 2) * (N / 2) + 7) / 8; };

    // one-shot weight conversion (independent of everything else)
    conv_w41<<<784, 256>>>(w41);
    // h1 = tanh(x @ w1.T + b1)                       [64,512] K=784
    gemm_warp<0><<<grid_for(64, 512), 256>>>(x, w1, b1, h1, 64, 512, 784, nullptr);
    // z_mean -> out[0:4096]                          [64,64]  K=512
    gemm_warp<1><<<grid_for(64, 64), 256>>>(h1, w21, b21, out, 64, 64, 512, nullptr);
    // z_logvar -> out[4096:8192], z_var -> scratch   [64,64]  K=512
    gemm_warp<2><<<grid_for(64, 64), 256>>>(h1, w22, b22, out + 64 * 64, 64, 64, 512, zvar);
    // m3 = z_mean @ w3.T + b3                        [64,512] K=64
    gemm_warp<1><<<grid_for(64, 512), 256>>>(out, w3, b3, m3, 64, 512, 64, nullptr);
    // tanh moment coefficients + clipped diag
    moments_tanh<<<128, 256>>>(w3);
    // G = lower(cov_h3)+half-diag, bf16, 10 tile-pairs per batch
    build_H<<<dim3(10, 64), 256>>>(w3);
    // m41 = a0 @ w41.T + b41                         [64,784] K=512
    gemm_warp<1><<<grid_for(64, 784), 256>>>(a0, w41, b41, m41, 64, 784, 512, nullptr);
    // diag of cov41 (x2 triangular) + fused sigmoid probs -> out[8192:]
    bilinear_probs_bf16<<<dim3(7, 64), 256>>>(w41, out + 2 * 64 * 64);
}

// round 6
// speedup vs baseline: 7.4668x; 1.0424x over previous
#include <cuda_runtime.h>
#include <cuda_bf16.h>
#include <math.h>

#define EPSC 1e-6f
#define INV_SQRT_2PI 0.3989422804014327f

__constant__ float GT[10] = {0.715951561820333f, 1.039358092507381f, 0.948607106485449f,
                             0.715951555650637f, 0.715951343627955f, 1.039354251532628f,
                             0.484068718800797f, 0.715951452277779f, 1.039355768740833f,
                             1.446433070133343f};
__constant__ float GS[10] = {0.519483084417772f, 0.357944855434941f, 0.723301195883257f,
                             0.474918009444542f, 0.519483382721337f, 0.357945091498072f,
                             0.519481351904163f, 0.357945544542554f, 0.242049896394596f,
                             0.357944917042638f};

// lower-triangle tile-pair tables for build_H (row tile >= col tile)
__constant__ int RT[10] = {0, 1, 1, 2, 2, 2, 3, 3, 3, 3};
__constant__ int CT[10] = {0, 0, 1, 0, 1, 2, 0, 1, 2, 3};

// ------------------- scratch (__device__ globals, no allocs) -------------------
__device__ float g_h1[64 * 512];
__device__ float g_zvar[64 * 64];
__device__ float g_a0[64 * 512];
__device__ float g_a1[64 * 512];
__device__ float g_a2[64 * 512];
__device__ float g_a3[64 * 512];
__device__ float g_v[64 * 512];
__device__ __nv_bfloat16 g_Hbf[(size_t)64 * 512 * 512];   // G = lower(H)+half-diag, bf16
__device__ __nv_bfloat16 g_w41bf[784 * 512];
__device__ float g_m41[64 * 784];

// ------------------- warp-tile small GEMM --------------------------------------
// Each warp computes a 2x2 output tile of out[M,N] = act(A[M,K] @ Bw[N,K]^T + b).
// MODE 0: tanh   MODE 1: identity
template <int MODE>
__global__ __launch_bounds__(256) void gemm_warp(
    const float* __restrict__ A, const float* __restrict__ Bw,
    const float* __restrict__ bias, float* __restrict__ out,
    int M, int N, int K)
{
    const int wid  = (blockIdx.x * blockDim.x + threadIdx.x) >> 5;
    const int lane = threadIdx.x & 31;
    const int ntiles = N >> 1;
    const int tm = wid / ntiles;
    const int tn = wid - tm * ntiles;
    const int m0 = tm * 2, n0 = tn * 2;
    if (m0 >= M) return;

    const float4* a0p = reinterpret_cast<const float4*>(A + (size_t)m0 * K);
    const float4* a1p = reinterpret_cast<const float4*>(A + (size_t)(m0 + 1) * K);
    const float4* w0p = reinterpret_cast<const float4*>(Bw + (size_t)n0 * K);
    const float4* w1p = reinterpret_cast<const float4*>(Bw + (size_t)(n0 + 1) * K);
    const int K4 = K >> 2;

    float s00 = 0.f, s01 = 0.f, s10 = 0.f, s11 = 0.f;
    for (int i = lane; i < K4; i += 32) {
        float4 a0 = a0p[i], a1 = a1p[i], w0 = w0p[i], w1 = w1p[i];
        s00 += a0.x * w0.x + a0.y * w0.y + a0.z * w0.z + a0.w * w0.w;
        s01 += a0.x * w1.x + a0.y * w1.y + a0.z * w1.z + a0.w * w1.w;
        s10 += a1.x * w0.x + a1.y * w0.y + a1.z * w0.z + a1.w * w0.w;
        s11 += a1.x * w1.x + a1.y * w1.y + a1.z * w1.z + a1.w * w1.w;
    }
#pragma unroll
    for (int off = 16; off; off >>= 1) {
        s00 += __shfl_xor_sync(0xffffffff, s00, off);
        s01 += __shfl_xor_sync(0xffffffff, s01, off);
        s10 += __shfl_xor_sync(0xffffffff, s10, off);
        s11 += __shfl_xor_sync(0xffffffff, s11, off);
    }
    if (lane == 0) {
        float b0 = bias[n0], b1 = bias[n0 + 1];
        float v00 = s00 + b0, v01 = s01 + b1, v10 = s10 + b0, v11 = s11 + b1;
        if (MODE == 0) {
            v00 = tanhf(v00); v01 = tanhf(v01); v10 = tanhf(v10); v11 = tanhf(v11);
        }
        out[(size_t)m0 * N + n0]           = v00;
        out[(size_t)m0 * N + n0 + 1]       = v01;
        out[(size_t)(m0 + 1) * N + n0]     = v10;
        out[(size_t)(m0 + 1) * N + n0 + 1] = v11;
    }
}

// ------------------- dual z GEMM: z_mean and z_logvar(+exp) in one launch ------
__global__ __launch_bounds__(256) void gemm_warp_zdual(
    const float* __restrict__ h1,
    const float* __restrict__ w21, const float* __restrict__ b21,
    const float* __restrict__ w22, const float* __restrict__ b22,
    float* __restrict__ out)       // z_mean -> out, z_logvar -> out+4096, exp->g_zvar
{
    const int half = gridDim.x >> 1;
    const bool second = blockIdx.x >= half;
    const int bx = second ? blockIdx.x - half : blockIdx.x;
    const float* Bw = second ? w22 : w21;
    const float* bias = second ? b22 : b21;
    float* o = second ? out + 64 * 64 : out;

    const int wid  = (bx * blockDim.x + threadIdx.x) >> 5;
    const int lane = threadIdx.x & 31;
    const int M = 64, N = 64, K = 512;
    const int ntiles = N >> 1;
    const int tm = wid / ntiles;
    const int tn = wid - tm * ntiles;
    const int m0 = tm * 2, n0 = tn * 2;
    if (m0 >= M) return;

    const float4* a0p = reinterpret_cast<const float4*>(h1 + (size_t)m0 * K);
    const float4* a1p = reinterpret_cast<const float4*>(h1 + (size_t)(m0 + 1) * K);
    const float4* w0p = reinterpret_cast<const float4*>(Bw + (size_t)n0 * K);
    const float4* w1p = reinterpret_cast<const float4*>(Bw + (size_t)(n0 + 1) * K);
    const int K4 = K >> 2;

    float s00 = 0.f, s01 = 0.f, s10 = 0.f, s11 = 0.f;
    for (int i = lane; i < K4; i += 32) {
        float4 a0 = a0p[i], a1 = a1p[i], w0 = w0p[i], w1 = w1p[i];
        s00 += a0.x * w0.x + a0.y * w0.y + a0.z * w0.z + a0.w * w0.w;
        s01 += a0.x * w1.x + a0.y * w1.y + a0.z * w1.z + a0.w * w1.w;
        s10 += a1.x * w0.x + a1.y * w0.y + a1.z * w0.z + a1.w * w0.w;
        s11 += a1.x * w1.x + a1.y * w1.y + a1.z * w1.z + a1.w * w1.w;
    }
#pragma unroll
    for (int off = 16; off; off >>= 1) {
        s00 += __shfl_xor_sync(0xffffffff, s00, off);
        s01 += __shfl_xor_sync(0xffffffff, s01, off);
        s10 += __shfl_xor_sync(0xffffffff, s10, off);
        s11 += __shfl_xor_sync(0xffffffff, s11, off);
    }
    if (lane == 0) {
        float b0 = bias[n0], b1 = bias[n0 + 1];
        float v00 = s00 + b0, v01 = s01 + b1, v10 = s10 + b0, v11 = s11 + b1;
        o[(size_t)m0 * N + n0]           = v00;
        o[(size_t)m0 * N + n0 + 1]       = v01;
        o[(size_t)(m0 + 1) * N + n0]     = v10;
        o[(size_t)(m0 + 1) * N + n0 + 1] = v11;
        if (second) {
            g_zvar[(size_t)m0 * N + n0]           = expf(v00);
            g_zvar[(size_t)m0 * N + n0 + 1]       = expf(v01);
            g_zvar[(size_t)(m0 + 1) * N + n0]     = expf(v10);
            g_zvar[(size_t)(m0 + 1) * N + n0 + 1] = expf(v11);
        }
    }
}

// ------------------- moments (tanh): fused m3 GEMM + A0..A3 + clipped diag -----
__global__ void moments_tanh(const float* __restrict__ w3,
                             const float* __restrict__ b3,
                             const float* __restrict__ zmean)
{
    int idx = blockIdx.x * blockDim.x + threadIdx.x;
    if (idx >= 64 * 512) return;
    int b = idx >> 9, i = idx & 511;

    const float* wr = w3 + i * 64;
    const float* zr = g_zvar + b * 64;
    const float* zm = zmean + b * 64;
    float v = 0.f, m = b3[i];
#pragma unroll 8
    for (int l = 0; l < 64; l++) {
        float w = wr[l];
        v += w * w * zr[l];
        m += w * zm[l];
    }
    v = fmaxf(v, EPSC);

    float s0 = 0.f, s1 = 0.f, s2 = 0.f, s3 = 0.f;
#pragma unroll
    for (int g = 0; g < 10; g++) {
        float gam = GT[g];
        float cg = 1.0f / (2.0f * gam * gam);
        float ivh = v + cg;
        float sq = sqrtf(ivh);
        float mu = m / sq;
        float Bv = expf(-0.5f * mu * mu) * INV_SQRT_2PI / sq;
        float Cv = 0.5f * (1.0f + erff(mu * 0.70710678118654752f));
        s0 += 2.f * Cv - 1.f;
        s1 += 2.f * Bv;
        s2 += -Bv * m / ivh;
        s3 += (1.f / 3.f) * Bv * (m * m - ivh) / (ivh * ivh);
    }
    g_a0[idx] = s0 * 0.1f;
    g_a1[idx] = s1 * 0.1f;
    g_a2[idx] = s2 * 0.1f;
    g_a3[idx] = s3 * 0.1f;
    g_v[idx]  = v;
}

// ------------------- w41 -> bf16 one-shot conversion ---------------------------
__global__ void conv_w41(const float* __restrict__ w41)
{
    int i = blockIdx.x * 256 + threadIdx.x;
    if (i < 784 * 512 / 2) {
        float2 v = reinterpret_cast<const float2*>(w41)[i];
        reinterpret_cast<__nv_bfloat162*>(g_w41bf)[i] =
            __floats2bfloat162_rn(v.x, v.y);
    }
}

// ------------------- build G = lower(H) + half-diag, bf16 ----------------------
__global__ __launch_bounds__(256, 2) void build_H(const float* __restrict__ w3)
{
    __shared__ float Wi[32 * 132];
    __shared__ float Wj[32 * 132];
    const int t = threadIdx.x;
    const int tx = t & 15, ty = t >> 4;
    const int ib = RT[blockIdx.x] * 128, jb = CT[blockIdx.x] * 128;
    const int b = blockIdx.y;
    const float* zr = g_zvar + b * 64;

    float acc[8][8];
#pragma unroll
    for (int r = 0; r < 8; r++)
#pragma unroll
        for (int c = 0; c < 8; c++) acc[r][c] = 0.f;

    for (int lc = 0; lc < 64; lc += 32) {
#pragma unroll
        for (int q = 0; q < 4; q++) {
            int f = t + q * 256;
            int row = f >> 3, c4 = f & 7;
            int l = lc + c4 * 4;
            float4 vi = *reinterpret_cast<const float4*>(w3 + (size_t)(ib + row) * 64 + l);
            Wi[(c4 * 4 + 0) * 132 + row] = vi.x;
            Wi[(c4 * 4 + 1) * 132 + row] = vi.y;
            Wi[(c4 * 4 + 2) * 132 + row] = vi.z;
            Wi[(c4 * 4 + 3) * 132 + row] = vi.w;
            float4 vj = *reinterpret_cast<const float4*>(w3 + (size_t)(jb + row) * 64 + l);
            Wj[(c4 * 4 + 0) * 132 + row] = vj.x * zr[l + 0];
            Wj[(c4 * 4 + 1) * 132 + row] = vj.y * zr[l + 1];
            Wj[(c4 * 4 + 2) * 132 + row] = vj.z * zr[l + 2];
            Wj[(c4 * 4 + 3) * 132 + row] = vj.w * zr[l + 3];
        }
        __syncthreads();
#pragma unroll
        for (int l = 0; l < 32; l++) {
            float a[8], bb[8];
            *reinterpret_cast<float4*>(a)      = *reinterpret_cast<const float4*>(&Wi[l * 132 + ty * 8]);
            *reinterpret_cast<float4*>(a + 4)  = *reinterpret_cast<const float4*>(&Wi[l * 132 + ty * 8 + 4]);
            *reinterpret_cast<float4*>(bb)     = *reinterpret_cast<const float4*>(&Wj[l * 132 + tx * 8]);
            *reinterpret_cast<float4*>(bb + 4) = *reinterpret_cast<const float4*>(&Wj[l * 132 + tx * 8 + 4]);
#pragma unroll
            for (int r = 0; r < 8; r++)
#pragma unroll
                for (int c = 0; c < 8; c++) acc[r][c] += a[r] * bb[c];
        }
        __syncthreads();
    }

    float a1i[8], a2i[8], a3i[8], vi[8];
    float a1j[8], a2j[8], a3j[8], vj[8];
#pragma unroll
    for (int r = 0; r < 8; r++) {
        int ig = b * 512 + ib + ty * 8 + r;
        a1i[r] = g_a1[ig]; a2i[r] = g_a2[ig]; a3i[r] = g_a3[ig]; vi[r] = g_v[ig];
    }
#pragma unroll
    for (int c = 0; c < 8; c++) {
        int jg = b * 512 + jb + tx * 8 + c;
        a1j[c] = g_a1[jg]; a2j[c] = g_a2[jg]; a3j[c] = g_a3[jg]; vj[c] = g_v[jg];
    }
#pragma unroll
    for (int r = 0; r < 8; r++) {
        int ig = ib + ty * 8 + r;
        __nv_bfloat162 pk[4];
#pragma unroll
        for (int c2 = 0; c2 < 4; c2++) {
            float hv[2];
#pragma unroll
            for (int u = 0; u < 2; u++) {
                int c = c2 * 2 + u;
                int jg = jb + tx * 8 + c;
                float c0 = acc[r][c];
                if (ig == jg) c0 = fmaxf(c0, EPSC);
                float cc2 = c0 * c0;
                float h = a1i[r] * a1j[c] * c0
                        + 2.f * a2i[r] * a2j[c] * cc2
                        + a3i[r] * a3j[c] * (6.f * cc2 * c0 + 9.f * vi[r] * vj[c] * c0);
                if (ig < jg) h = 0.f;
                else if (ig == jg) h *= 0.5f;
                hv[u] = h;
            }
            pk[c2] = __floats2bfloat162_rn(hv[0], hv[1]);
        }
        *reinterpret_cast<uint4*>(&g_Hbf[((size_t)b * 512 + ig) * 512 + jb + tx * 8]) =
            *reinterpret_cast<const uint4*>(pk);
    }
}

// ------------------- diag + probs via bf16 tensor cores + ldmatrix -------------
// diag[b,o] = 2 * w41[o,:] G[b] w41[o,:]^T  (G lower-triangular: k-loop truncated)
__global__ __launch_bounds__(256, 2) void bilinear_probs_bf16(
    const float* __restrict__ w41, float* __restrict__ probs_out)
{
    __shared__ __align__(16) __nv_bfloat16 As[128][72];   // [o][k]
    __shared__ __align__(16) __nv_bfloat16 Bs[128][72];   // [j][k] = G[j][k]

    const int t = threadIdx.x;
    const int lane = t & 31;
    const int w = t >> 5;
    const int ob = blockIdx.x * 128;
    const int b  = blockIdx.y;
    const __nv_bfloat16* Hb = g_Hbf + ((size_t)b << 18);

    const int grp = lane >> 2;
    const int qid = lane & 3;

    // per-lane ldmatrix base addresses (bytes, shared space)
    unsigned as_base = (unsigned)__cvta_generic_to_shared(&As[0][0]);
    unsigned bs_base = (unsigned)__cvta_generic_to_shared(&Bs[0][0]);
    // A: lanes 0-15 -> rows m0-15 k+0 ; lanes 16-31 -> rows m0-15 k+8
    unsigned a_addr = as_base + (((w * 16 + (lane & 15)) * 72 + ((lane >> 4) << 3)) << 1);
    // B: rows n0-7 (lanes 0-15) / n8-15 (lanes 16-31); k+0 (lane&8==0) / k+8
    unsigned b_addr = bs_base + ((((lane & 7) + ((lane & 16) >> 1)) * 72 + (lane & 8)) << 1);

    float s0 = 0.f, s1 = 0.f;
    const int o_r0 = ob + w * 16 + grp;
    const int o_r1 = o_r0 + 8;

    for (int jt = 0; jt < 4; jt++) {
        const int jb = jt * 128;
        const int kend = (jt + 1) * 128;       // triangular truncation
        float d[16][4];
#pragma unroll
        for (int nt = 0; nt < 16; nt++)
#pragma unroll
            for (int c = 0; c < 4; c++) d[nt][c] = 0.f;

        for (int kc = 0; kc < kend; kc += 64) {
#pragma unroll
            for (int q = 0; q < 4; q++) {
                int f = t + q * 256;
                int row = f >> 3, g = f & 7;
                int og = ob + row;
                uint4 av = make_uint4(0, 0, 0, 0);
                if (og < 784)
                    av = *reinterpret_cast<const uint4*>(g_w41bf + (size_t)og * 512 + kc + g * 8);
                *reinterpret_cast<uint4*>(&As[row][g * 8]) = av;
                uint4 bv = *reinterpret_cast<const uint4*>(Hb + (size_t)(jb + row) * 512 + kc + g * 8);
                *reinterpret_cast<uint4*>(&Bs[row][g * 8]) = bv;
            }
            __syncthreads();

#pragma unroll
            for (int kk = 0; kk < 4; kk++) {
                unsigned a0, a1, a2, a3;
                asm volatile(
                    "ldmatrix.sync.aligned.m8n8.x4.shared.b16 {%0,%1,%2,%3}, [%4];"
                    : "=r"(a0), "=r"(a1), "=r"(a2), "=r"(a3)
                    : "r"(a_addr + kk * 32));
#pragma unroll
                for (int nt2 = 0; nt2 < 8; nt2++) {
                    unsigned b0, b1, b2, b3;
                    asm volatile(
                        "ldmatrix.sync.aligned.m8n8.x4.shared.b16 {%0,%1,%2,%3}, [%4];"
                        : "=r"(b0), "=r"(b1), "=r"(b2), "=r"(b3)
                        : "r"(b_addr + nt2 * 2304 + kk * 32));
                    asm volatile(
                        "mma.sync.aligned.m16n8k16.row.col.f32.bf16.bf16.f32 "
                        "{%0,%1,%2,%3}, {%4,%5,%6,%7}, {%8,%9}, {%0,%1,%2,%3};"
                        : "+f"(d[2 * nt2][0]), "+f"(d[2 * nt2][1]),
                          "+f"(d[2 * nt2][2]), "+f"(d[2 * nt2][3])
                        : "r"(a0), "r"(a1), "r"(a2), "r"(a3), "r"(b0), "r"(b1));
                    asm volatile(
                        "mma.sync.aligned.m16n8k16.row.col.f32.bf16.bf16.f32 "
                        "{%0,%1,%2,%3}, {%4,%5,%6,%7}, {%8,%9}, {%0,%1,%2,%3};"
                        : "+f"(d[2 * nt2 + 1][0]), "+f"(d[2 * nt2 + 1][1]),
                          "+f"(d[2 * nt2 + 1][2]), "+f"(d[2 * nt2 + 1][3])
                        : "r"(a0), "r"(a1), "r"(a2), "r"(a3), "r"(b2), "r"(b3));
                }
            }
            __syncthreads();
        }

        if (o_r0 < 784) {
#pragma unroll
            for (int nt = 0; nt < 16; nt++) {
                int j0 = jb + nt * 8 + qid * 2;
                float2 u0 = *reinterpret_cast<const float2*>(w41 + (size_t)o_r0 * 512 + j0);
                float2 u1 = *reinterpret_cast<const float2*>(w41 + (size_t)o_r1 * 512 + j0);
                s0 += d[nt][0] * u0.x + d[nt][1] * u0.y;
                s1 += d[nt][2] * u1.x + d[nt][3] * u1.y;
            }
        }
    }

    s0 += __shfl_xor_sync(0xffffffff, s0, 1);
    s0 += __shfl_xor_sync(0xffffffff, s0, 2);
    s1 += __shfl_xor_sync(0xffffffff, s1, 1);
    s1 += __shfl_xor_sync(0xffffffff, s1, 2);

    if (qid == 0 && o_r0 < 784) {
        float vv[2] = {fmaxf(2.f * s0, EPSC), fmaxf(2.f * s1, EPSC)};
        int oo[2] = {o_r0, o_r1};
#pragma unroll
        for (int u = 0; u < 2; u++) {
            float m = g_m41[b * 784 + oo[u]];
            float s = 0.f;
#pragma unroll
            for (int g = 0; g < 10; g++) {
                float gam = GS[g];
                float cg = 1.0f / (2.0f * gam * gam);
                float ivh = vv[u] + cg;
                s += 0.5f * (1.0f + erff(m / sqrtf(2.0f * ivh)));
            }
            probs_out[b * 784 + oo[u]] = s * 0.1f;
        }
    }
}

// ------------------- launcher --------------------------------------------------
extern "C" void kernel_launch(void* const* d_in, const int* in_sizes, int n_in,
                              void* d_out, int out_size)
{
    const float* x   = (const float*)d_in[0];
    const float* w1  = (const float*)d_in[1];
    const float* b1  = (const float*)d_in[2];
    const float* w21 = (const float*)d_in[3];
    const float* b21 = (const float*)d_in[4];
    const float* w22 = (const float*)d_in[5];
    const float* b22 = (const float*)d_in[6];
    const float* w3  = (const float*)d_in[7];
    const float* b3  = (const float*)d_in[8];
    const float* w41 = (const float*)d_in[9];
    const float* b41 = (const float*)d_in[10];
    float* out = (float*)d_out;

    float *h1, *a0, *m41;
    cudaGetSymbolAddress((void**)&h1,  g_h1);
    cudaGetSymbolAddress((void**)&a0,  g_a0);
    cudaGetSymbolAddress((void**)&m41, g_m41);

    auto grid_for = [](int M, int N) { return ((M / 2) * (N / 2) + 7) / 8; };

    // one-shot weight conversion (independent of everything else)
    conv_w41<<<784, 256>>>(w41);
    // h1 = tanh(x @ w1.T + b1)                       [64,512] K=784
    gemm_warp<0><<<grid_for(64, 512), 256>>>(x, w1, b1, h1, 64, 512, 784);
    // z_mean -> out[0:4096], z_logvar -> out[4096:8192] (+exp -> g_zvar)
    gemm_warp_zdual<<<2 * grid_for(64, 64), 256>>>(h1, w21, b21, w22, b22, out);
    // fused m3 GEMM + tanh moment coefficients
    moments_tanh<<<128, 256>>>(w3, b3, out);
    // G = lower(cov_h3)+half-diag, bf16, 10 tile-pairs per batch
    build_H<<<dim3(10, 64), 256>>>(w3);
    // m41 = a0 @ w41.T + b41                         [64,784] K=512
    gemm_warp<1><<<grid_for(64, 784), 256>>>(a0, w41, b41, m41, 64, 784, 512);
    // diag of cov41 (x2 triangular) + fused sigmoid probs -> out[8192:]
    bilinear_probs_bf16<<<dim3(7, 64), 256>>>(w41, out + 2 * 64 * 64);
}

// round 7
// speedup vs baseline: 8.9677x; 1.2010x over previous
#include <cuda_runtime.h>
#include <cuda_bf16.h>
#include <math.h>

#define EPSC 1e-6f
#define INV_SQRT_2PI 0.3989422804014327f

// deduped gamma tables (values within 4e-6 merged; weights preserve the mean)
__constant__ float GTU[5] = {0.715951561820333f, 1.039358092507381f, 0.948607106485449f,
                             0.484068718800797f, 1.446433070133343f};
__constant__ float WTU[5] = {4.f, 3.f, 1.f, 1.f, 1.f};
__constant__ float GSU[5] = {0.519483084417772f, 0.357944855434941f, 0.723301195883257f,
                             0.474918009444542f, 0.242049896394596f};
__constant__ float WSU[5] = {3.f, 4.f, 1.f, 1.f, 1.f};

// lower-triangle tile-pair tables for build_H (row tile >= col tile)
__constant__ int RT[10] = {0, 1, 1, 2, 2, 2, 3, 3, 3, 3};
__constant__ int CT[10] = {0, 0, 1, 0, 1, 2, 0, 1, 2, 3};

// ------------------- scratch (__device__ globals, no allocs) -------------------
__device__ float g_h1[64 * 512];
__device__ float g_zvar[64 * 64];
__device__ float g_a0[64 * 512];
__device__ float g_a1[64 * 512];
__device__ float g_a2[64 * 512];
__device__ float g_a3[64 * 512];
__device__ float g_v[64 * 512];
__device__ __nv_bfloat16 g_Hbf[(size_t)64 * 512 * 512];   // G = lower(H)+half-diag, bf16
__device__ __nv_bfloat16 g_w41bf[784 * 512];
__device__ float g_m41[64 * 784];

// ------------------- mma/ldmatrix helpers --------------------------------------
__device__ __forceinline__ void mma_bf16(float* d, unsigned a0, unsigned a1,
                                         unsigned a2, unsigned a3,
                                         unsigned b0, unsigned b1) {
    asm volatile(
        "mma.sync.aligned.m16n8k16.row.col.f32.bf16.bf16.f32 "
        "{%0,%1,%2,%3}, {%4,%5,%6,%7}, {%8,%9}, {%0,%1,%2,%3};"
        : "+f"(d[0]), "+f"(d[1]), "+f"(d[2]), "+f"(d[3])
        : "r"(a0), "r"(a1), "r"(a2), "r"(a3), "r"(b0), "r"(b1));
}
__device__ __forceinline__ void ldmx4(unsigned& r0, unsigned& r1, unsigned& r2,
                                      unsigned& r3, unsigned addr) {
    asm volatile(
        "ldmatrix.sync.aligned.m8n8.x4.shared.b16 {%0,%1,%2,%3}, [%4];"
        : "=r"(r0), "=r"(r1), "=r"(r2), "=r"(r3) : "r"(addr));
}

// ------------------- h1 GEMM + w41 bf16 conversion (merged launch) -------------
__global__ __launch_bounds__(256) void h1_conv(
    const float* __restrict__ x, const float* __restrict__ w1,
    const float* __restrict__ b1, const float* __restrict__ w41)
{
    if (blockIdx.x >= 1024) {           // w41 -> bf16, 784 blocks
        int i = (blockIdx.x - 1024) * 256 + threadIdx.x;   // over pairs, exact
        float2 v = reinterpret_cast<const float2*>(w41)[i];
        reinterpret_cast<__nv_bfloat162*>(g_w41bf)[i] = __floats2bfloat162_rn(v.x, v.y);
        return;
    }
    // h1 = tanh(x @ w1^T + b1), M=64 N=512 K=784
    const int wid  = (blockIdx.x * 256 + threadIdx.x) >> 5;
    const int lane = threadIdx.x & 31;
    const int tm = wid >> 8, tn = wid & 255;
    const int m0 = tm * 2, n0 = tn * 2;
    const int K = 784, N = 512;

    const float4* a0p = reinterpret_cast<const float4*>(x + (size_t)m0 * K);
    const float4* a1p = reinterpret_cast<const float4*>(x + (size_t)(m0 + 1) * K);
    const float4* w0p = reinterpret_cast<const float4*>(w1 + (size_t)n0 * K);
    const float4* w1p = reinterpret_cast<const float4*>(w1 + (size_t)(n0 + 1) * K);
    const int K4 = K >> 2;

    float s00 = 0.f, s01 = 0.f, s10 = 0.f, s11 = 0.f;
    for (int i = lane; i < K4; i += 32) {
        float4 a0 = a0p[i], a1 = a1p[i], w0 = w0p[i], w1v = w1p[i];
        s00 += a0.x * w0.x + a0.y * w0.y + a0.z * w0.z + a0.w * w0.w;
        s01 += a0.x * w1v.x + a0.y * w1v.y + a0.z * w1v.z + a0.w * w1v.w;
        s10 += a1.x * w0.x + a1.y * w0.y + a1.z * w0.z + a1.w * w0.w;
        s11 += a1.x * w1v.x + a1.y * w1v.y + a1.z * w1v.z + a1.w * w1v.w;
    }
#pragma unroll
    for (int off = 16; off; off >>= 1) {
        s00 += __shfl_xor_sync(0xffffffff, s00, off);
        s01 += __shfl_xor_sync(0xffffffff, s01, off);
        s10 += __shfl_xor_sync(0xffffffff, s10, off);
        s11 += __shfl_xor_sync(0xffffffff, s11, off);
    }
    if (lane == 0) {
        float b0 = b1[n0], b1v = b1[n0 + 1];
        g_h1[(size_t)m0 * N + n0]           = tanhf(s00 + b0);
        g_h1[(size_t)m0 * N + n0 + 1]       = tanhf(s01 + b1v);
        g_h1[(size_t)(m0 + 1) * N + n0]     = tanhf(s10 + b0);
        g_h1[(size_t)(m0 + 1) * N + n0 + 1] = tanhf(s11 + b1v);
    }
}

// ------------------- dual z GEMM: z_mean and z_logvar(+exp) in one launch ------
__global__ __launch_bounds__(256) void gemm_warp_zdual(
    const float* __restrict__ h1,
    const float* __restrict__ w21, const float* __restrict__ b21,
    const float* __restrict__ w22, const float* __restrict__ b22,
    float* __restrict__ out)
{
    const int half = gridDim.x >> 1;
    const bool second = blockIdx.x >= half;
    const int bx = second ? blockIdx.x - half : blockIdx.x;
    const float* Bw = second ? w22 : w21;
    const float* bias = second ? b22 : b21;
    float* o = second ? out + 64 * 64 : out;

    const int wid  = (bx * 256 + threadIdx.x) >> 5;
    const int lane = threadIdx.x & 31;
    const int N = 64, K = 512;
    const int tm = wid >> 5, tn = wid & 31;
    const int m0 = tm * 2, n0 = tn * 2;

    const float4* a0p = reinterpret_cast<const float4*>(h1 + (size_t)m0 * K);
    const float4* a1p = reinterpret_cast<const float4*>(h1 + (size_t)(m0 + 1) * K);
    const float4* w0p = reinterpret_cast<const float4*>(Bw + (size_t)n0 * K);
    const float4* w1p = reinterpret_cast<const float4*>(Bw + (size_t)(n0 + 1) * K);
    const int K4 = K >> 2;

    float s00 = 0.f, s01 = 0.f, s10 = 0.f, s11 = 0.f;
    for (int i = lane; i < K4; i += 32) {
        float4 a0 = a0p[i], a1 = a1p[i], w0 = w0p[i], w1 = w1p[i];
        s00 += a0.x * w0.x + a0.y * w0.y + a0.z * w0.z + a0.w * w0.w;
        s01 += a0.x * w1.x + a0.y * w1.y + a0.z * w1.z + a0.w * w1.w;
        s10 += a1.x * w0.x + a1.y * w0.y + a1.z * w0.z + a1.w * w0.w;
        s11 += a1.x * w1.x + a1.y * w1.y + a1.z * w1.z + a1.w * w1.w;
    }
#pragma unroll
    for (int off = 16; off; off >>= 1) {
        s00 += __shfl_xor_sync(0xffffffff, s00, off);
        s01 += __shfl_xor_sync(0xffffffff, s01, off);
        s10 += __shfl_xor_sync(0xffffffff, s10, off);
        s11 += __shfl_xor_sync(0xffffffff, s11, off);
    }
    if (lane == 0) {
        float b0 = bias[n0], b1 = bias[n0 + 1];
        float v00 = s00 + b0, v01 = s01 + b1, v10 = s10 + b0, v11 = s11 + b1;
        o[(size_t)m0 * N + n0]           = v00;
        o[(size_t)m0 * N + n0 + 1]       = v01;
        o[(size_t)(m0 + 1) * N + n0]     = v10;
        o[(size_t)(m0 + 1) * N + n0 + 1] = v11;
        if (second) {
            g_zvar[(size_t)m0 * N + n0]           = expf(v00);
            g_zvar[(size_t)m0 * N + n0 + 1]       = expf(v01);
            g_zvar[(size_t)(m0 + 1) * N + n0]     = expf(v10);
            g_zvar[(size_t)(m0 + 1) * N + n0 + 1] = expf(v11);
        }
    }
}

// ------------------- moments (tanh): fused m3 GEMM + coefficients --------------
// smem-staged broadcasts + float4 w3 + 5 weighted gammas.
__global__ __launch_bounds__(256) void moments_tanh(
    const float* __restrict__ w3, const float* __restrict__ b3,
    const float* __restrict__ zmean)
{
    __shared__ float zr[64], zm[64];
    const int t = threadIdx.x;
    const int b = blockIdx.x >> 1;
    const int i = ((blockIdx.x & 1) << 8) + t;
    if (t < 64) zr[t] = g_zvar[b * 64 + t];
    else if (t < 128) zm[t - 64] = zmean[b * 64 + t - 64];
    __syncthreads();

    const float4* wr = reinterpret_cast<const float4*>(w3 + (size_t)i * 64);
    float v = 0.f, m = b3[i];
#pragma unroll
    for (int q = 0; q < 16; q++) {
        float4 w = wr[q];
        v += w.x * w.x * zr[q * 4 + 0] + w.y * w.y * zr[q * 4 + 1]
           + w.z * w.z * zr[q * 4 + 2] + w.w * w.w * zr[q * 4 + 3];
        m += w.x * zm[q * 4 + 0] + w.y * zm[q * 4 + 1]
           + w.z * zm[q * 4 + 2] + w.w * zm[q * 4 + 3];
    }
    v = fmaxf(v, EPSC);

    float s0 = 0.f, s1 = 0.f, s2 = 0.f, s3 = 0.f;
#pragma unroll
    for (int g = 0; g < 5; g++) {
        float gam = GTU[g], wgt = WTU[g];
        float cg = 1.0f / (2.0f * gam * gam);
        float ivh = v + cg;
        float sq = sqrtf(ivh);
        float mu = m / sq;
        float Bv = expf(-0.5f * mu * mu) * INV_SQRT_2PI / sq;
        float Cv = 0.5f * (1.0f + erff(mu * 0.70710678118654752f));
        s0 += wgt * (2.f * Cv - 1.f);
        s1 += wgt * (2.f * Bv);
        s2 += wgt * (-Bv * m / ivh);
        s3 += wgt * ((1.f / 3.f) * Bv * (m * m - ivh) / (ivh * ivh));
    }
    int idx = b * 512 + i;
    g_a0[idx] = s0 * 0.1f;
    g_a1[idx] = s1 * 0.1f;
    g_a2[idx] = s2 * 0.1f;
    g_a3[idx] = s3 * 0.1f;
    g_v[idx]  = v;
}

// ------------------- build G (bf16 MMA) + m41 GEMM (merged launch) -------------
// blocks [0,640): G = lower(H)+half-diag via tensor cores
// blocks [640,2208): m41 = a0 @ w41^T + b41
__global__ __launch_bounds__(256, 2) void build_H_m41(
    const float* __restrict__ w3, const float* __restrict__ w41,
    const float* __restrict__ b41)
{
    __shared__ __align__(16) __nv_bfloat16 Abf[128][72];   // [i][k]
    __shared__ __align__(16) __nv_bfloat16 Bbf[128][72];   // [j][k] (z-scaled)
    __shared__ float zrs[64];

    const int t = threadIdx.x;
    if (blockIdx.x >= 640) {            // ---- m41 warp GEMM ----
        const int wid  = ((blockIdx.x - 640) * 256 + t) >> 5;
        const int lane = t & 31;
        const int N = 784, K = 512;
        const int tm = wid / 392, tn = wid - tm * 392;
        const int m0 = tm * 2, n0 = tn * 2;

        const float4* a0p = reinterpret_cast<const float4*>(g_a0 + (size_t)m0 * K);
        const float4* a1p = reinterpret_cast<const float4*>(g_a0 + (size_t)(m0 + 1) * K);
        const float4* w0p = reinterpret_cast<const float4*>(w41 + (size_t)n0 * K);
        const float4* w1p = reinterpret_cast<const float4*>(w41 + (size_t)(n0 + 1) * K);

        float s00 = 0.f, s01 = 0.f, s10 = 0.f, s11 = 0.f;
        for (int i = lane; i < (K >> 2); i += 32) {
            float4 a0 = a0p[i], a1 = a1p[i], w0 = w0p[i], w1 = w1p[i];
            s00 += a0.x * w0.x + a0.y * w0.y + a0.z * w0.z + a0.w * w0.w;
            s01 += a0.x * w1.x + a0.y * w1.y + a0.z * w1.z + a0.w * w1.w;
            s10 += a1.x * w0.x + a1.y * w0.y + a1.z * w0.z + a1.w * w0.w;
            s11 += a1.x * w1.x + a1.y * w1.y + a1.z * w1.z + a1.w * w1.w;
        }
#pragma unroll
        for (int off = 16; off; off >>= 1) {
            s00 += __shfl_xor_sync(0xffffffff, s00, off);
            s01 += __shfl_xor_sync(0xffffffff, s01, off);
            s10 += __shfl_xor_sync(0xffffffff, s10, off);
            s11 += __shfl_xor_sync(0xffffffff, s11, off);
        }
        if (lane == 0) {
            float b0 = b41[n0], b1 = b41[n0 + 1];
            g_m41[(size_t)m0 * N + n0]           = s00 + b0;
            g_m41[(size_t)m0 * N + n0 + 1]       = s01 + b1;
            g_m41[(size_t)(m0 + 1) * N + n0]     = s10 + b0;
            g_m41[(size_t)(m0 + 1) * N + n0 + 1] = s11 + b1;
        }
        return;
    }

    // ---- build G ----
    const int pair = blockIdx.x % 10;
    const int b = blockIdx.x / 10;
    const int ib = RT[pair] * 128, jb = CT[pair] * 128;
    const bool diag_tile = (ib == jb);

    if (t < 64) zrs[t] = g_zvar[b * 64 + t];
    __syncthreads();

    {   // stage W3 tiles (bf16), B side z-scaled
        int row = t >> 1, base = (t & 1) * 8;
        const float4* wa = reinterpret_cast<const float4*>(w3 + (size_t)(ib + row) * 64);
        const float4* wb = reinterpret_cast<const float4*>(w3 + (size_t)(jb + row) * 64);
#pragma unroll
        for (int q = 0; q < 8; q++) {
            int c4 = base + q;
            float4 va = wa[c4];
            __nv_bfloat162 pa0 = __floats2bfloat162_rn(va.x, va.y);
            __nv_bfloat162 pa1 = __floats2bfloat162_rn(va.z, va.w);
            *reinterpret_cast<__nv_bfloat162*>(&Abf[row][c4 * 4])     = pa0;
            *reinterpret_cast<__nv_bfloat162*>(&Abf[row][c4 * 4 + 2]) = pa1;
            float4 vb = wb[c4];
            __nv_bfloat162 pb0 = __floats2bfloat162_rn(vb.x * zrs[c4 * 4 + 0],
                                                       vb.y * zrs[c4 * 4 + 1]);
            __nv_bfloat162 pb1 = __floats2bfloat162_rn(vb.z * zrs[c4 * 4 + 2],
                                                       vb.w * zrs[c4 * 4 + 3]);
            *reinterpret_cast<__nv_bfloat162*>(&Bbf[row][c4 * 4])     = pb0;
            *reinterpret_cast<__nv_bfloat162*>(&Bbf[row][c4 * 4 + 2]) = pb1;
        }
    }
    __syncthreads();

    const int lane = t & 31;
    const int w = t >> 5;
    const int wm = w & 3, wn = w >> 2;         // warp -> 32 m-rows x 64 n-cols
    const int grp = lane >> 2, qid = lane & 3;

    unsigned as_base = (unsigned)__cvta_generic_to_shared(&Abf[0][0]);
    unsigned bs_base = (unsigned)__cvta_generic_to_shared(&Bbf[0][0]);
    unsigned a_addr = as_base + (((wm * 32 + (lane & 15)) * 72 + ((lane >> 4) << 3)) << 1);
    unsigned b_addr = bs_base + (((wn * 64 + (lane & 7) + ((lane & 16) >> 1)) * 72 + (lane & 8)) << 1);

    float d[2][8][4];
#pragma unroll
    for (int mt = 0; mt < 2; mt++)
#pragma unroll
        for (int nt = 0; nt < 8; nt++)
#pragma unroll
            for (int e = 0; e < 4; e++) d[mt][nt][e] = 0.f;

#pragma unroll
    for (int kk = 0; kk < 4; kk++) {
        unsigned a[2][4];
        ldmx4(a[0][0], a[0][1], a[0][2], a[0][3], a_addr + kk * 32);
        ldmx4(a[1][0], a[1][1], a[1][2], a[1][3], a_addr + 2304 + kk * 32);
#pragma unroll
        for (int np = 0; np < 4; np++) {
            unsigned b0, b1, b2, b3;
            ldmx4(b0, b1, b2, b3, b_addr + np * 2304 + kk * 32);
            mma_bf16(d[0][2 * np],     a[0][0], a[0][1], a[0][2], a[0][3], b0, b1);
            mma_bf16(d[0][2 * np + 1], a[0][0], a[0][1], a[0][2], a[0][3], b2, b3);
            mma_bf16(d[1][2 * np],     a[1][0], a[1][1], a[1][2], a[1][3], b0, b1);
            mma_bf16(d[1][2 * np + 1], a[1][0], a[1][1], a[1][2], a[1][3], b2, b3);
        }
    }

    // epilogue: moment transform -> bf16 G
    float A1i[4], A2i[4], A3i[4], Vi[4];
#pragma unroll
    for (int mh = 0; mh < 4; mh++) {
        int gi = b * 512 + ib + wm * 32 + (mh >> 1) * 16 + grp + (mh & 1) * 8;
        A1i[mh] = g_a1[gi]; A2i[mh] = g_a2[gi]; A3i[mh] = g_a3[gi]; Vi[mh] = g_v[gi];
    }
#pragma unroll
    for (int nt = 0; nt < 8; nt++) {
        int gj0 = jb + wn * 64 + nt * 8 + qid * 2;
        float A1j[2], A2j[2], A3j[2], Vj[2];
#pragma unroll
        for (int c = 0; c < 2; c++) {
            int gj = b * 512 + gj0 + c;
            A1j[c] = g_a1[gj]; A2j[c] = g_a2[gj]; A3j[c] = g_a3[gj]; Vj[c] = g_v[gj];
        }
#pragma unroll
        for (int mh = 0; mh < 4; mh++) {
            int mt = mh >> 1, hh = mh & 1;
            int gi = ib + wm * 32 + mt * 16 + grp + hh * 8;
            float hv[2];
#pragma unroll
            for (int c = 0; c < 2; c++) {
                int gj = gj0 + c;
                float c0 = d[mt][nt][hh * 2 + c];
                float h;
                if (diag_tile && gi < gj) {
                    h = 0.f;
                } else if (gi == gj) {
                    c0 = Vi[mh];                       // exact fp32 diagonal
                    float cc2 = c0 * c0;
                    h = 0.5f * (A1i[mh] * A1j[c] * c0
                              + 2.f * A2i[mh] * A2j[c] * cc2
                              + A3i[mh] * A3j[c] * (6.f * cc2 * c0 + 9.f * Vi[mh] * Vj[c] * c0));
                } else {
                    float cc2 = c0 * c0;
                    h = A1i[mh] * A1j[c] * c0
                      + 2.f * A2i[mh] * A2j[c] * cc2
                      + A3i[mh] * A3j[c] * (6.f * cc2 * c0 + 9.f * Vi[mh] * Vj[c] * c0);
                }
                hv[c] = h;
            }
            *reinterpret_cast<__nv_bfloat162*>(
                &g_Hbf[((size_t)b * 512 + gi) * 512 + gj0]) =
                __floats2bfloat162_rn(hv[0], hv[1]);
        }
    }
}

// ------------------- diag + probs via bf16 tensor cores + ldmatrix -------------
__global__ __launch_bounds__(256, 2) void bilinear_probs_bf16(
    const float* __restrict__ w41, float* __restrict__ probs_out)
{
    __shared__ __align__(16) __nv_bfloat16 As[128][72];   // [o][k]
    __shared__ __align__(16) __nv_bfloat16 Bs[128][72];   // [j][k] = G[j][k]

    const int t = threadIdx.x;
    const int lane = t & 31;
    const int w = t >> 5;
    const int ob = blockIdx.x * 128;
    const int b  = blockIdx.y;
    const __nv_bfloat16* Hb = g_Hbf + ((size_t)b << 18);

    const int grp = lane >> 2;
    const int qid = lane & 3;

    unsigned as_base = (unsigned)__cvta_generic_to_shared(&As[0][0]);
    unsigned bs_base = (unsigned)__cvta_generic_to_shared(&Bs[0][0]);
    unsigned a_addr = as_base + (((w * 16 + (lane & 15)) * 72 + ((lane >> 4) << 3)) << 1);
    unsigned b_addr = bs_base + ((((lane & 7) + ((lane & 16) >> 1)) * 72 + (lane & 8)) << 1);

    float s0 = 0.f, s1 = 0.f;
    const int o_r0 = ob + w * 16 + grp;
    const int o_r1 = o_r0 + 8;

    for (int jt = 0; jt < 4; jt++) {
        const int jb = jt * 128;
        const int kend = (jt + 1) * 128;       // triangular truncation
        float d[16][4];
#pragma unroll
        for (int nt = 0; nt < 16; nt++)
#pragma unroll
            for (int c = 0; c < 4; c++) d[nt][c] = 0.f;

        for (int kc = 0; kc < kend; kc += 64) {
#pragma unroll
            for (int q = 0; q < 4; q++) {
                int f = t + q * 256;
                int row = f >> 3, g = f & 7;
                int og = ob + row;
                uint4 av = make_uint4(0, 0, 0, 0);
                if (og < 784)
                    av = *reinterpret_cast<const uint4*>(g_w41bf + (size_t)og * 512 + kc + g * 8);
                *reinterpret_cast<uint4*>(&As[row][g * 8]) = av;
                uint4 bv = *reinterpret_cast<const uint4*>(Hb + (size_t)(jb + row) * 512 + kc + g * 8);
                *reinterpret_cast<uint4*>(&Bs[row][g * 8]) = bv;
            }
            __syncthreads();

#pragma unroll
            for (int kk = 0; kk < 4; kk++) {
                unsigned a0, a1, a2, a3;
                ldmx4(a0, a1, a2, a3, a_addr + kk * 32);
#pragma unroll
                for (int nt2 = 0; nt2 < 8; nt2++) {
                    unsigned b0, b1, b2, b3;
                    ldmx4(b0, b1, b2, b3, b_addr + nt2 * 2304 + kk * 32);
                    mma_bf16(d[2 * nt2],     a0, a1, a2, a3, b0, b1);
                    mma_bf16(d[2 * nt2 + 1], a0, a1, a2, a3, b2, b3);
                }
            }
            __syncthreads();
        }

        if (o_r0 < 784) {
#pragma unroll
            for (int nt = 0; nt < 16; nt++) {
                int j0 = jb + nt * 8 + qid * 2;
                float2 u0 = *reinterpret_cast<const float2*>(w41 + (size_t)o_r0 * 512 + j0);
                float2 u1 = *reinterpret_cast<const float2*>(w41 + (size_t)o_r1 * 512 + j0);
                s0 += d[nt][0] * u0.x + d[nt][1] * u0.y;
                s1 += d[nt][2] * u1.x + d[nt][3] * u1.y;
            }
        }
    }

    s0 += __shfl_xor_sync(0xffffffff, s0, 1);
    s0 += __shfl_xor_sync(0xffffffff, s0, 2);
    s1 += __shfl_xor_sync(0xffffffff, s1, 1);
    s1 += __shfl_xor_sync(0xffffffff, s1, 2);

    if (qid == 0 && o_r0 < 784) {
        float vv[2] = {fmaxf(2.f * s0, EPSC), fmaxf(2.f * s1, EPSC)};
        int oo[2] = {o_r0, o_r1};
#pragma unroll
        for (int u = 0; u < 2; u++) {
            float m = g_m41[b * 784 + oo[u]];
            float s = 0.f;
#pragma unroll
            for (int g = 0; g < 5; g++) {
                float gam = GSU[g];
                float cg = 1.0f / (2.0f * gam * gam);
                float ivh = vv[u] + cg;
                s += WSU[g] * 0.5f * (1.0f + erff(m / sqrtf(2.0f * ivh)));
            }
            probs_out[b * 784 + oo[u]] = s * 0.1f;
        }
    }
}

// ------------------- launcher --------------------------------------------------
extern "C" void kernel_launch(void* const* d_in, const int* in_sizes, int n_in,
                              void* d_out, int out_size)
{
    const float* x   = (const float*)d_in[0];
    const float* w1  = (const float*)d_in[1];
    const float* b1  = (const float*)d_in[2];
    const float* w21 = (const float*)d_in[3];
    const float* b21 = (const float*)d_in[4];
    const float* w22 = (const float*)d_in[5];
    const float* b22 = (const float*)d_in[6];
    const float* w3  = (const float*)d_in[7];
    const float* b3  = (const float*)d_in[8];
    const float* w41 = (const float*)d_in[9];
    const float* b41 = (const float*)d_in[10];
    float* out = (float*)d_out;

    float* h1;
    cudaGetSymbolAddress((void**)&h1, g_h1);

    // h1 GEMM (1024 blocks) + w41 bf16 conversion (784 blocks)
    h1_conv<<<1808, 256>>>(x, w1, b1, w41);
    // z_mean -> out[0:4096], z_logvar -> out[4096:8192] (+exp -> g_zvar)
    gemm_warp_zdual<<<256, 256>>>(h1, w21, b21, w22, b22, out);
    // fused m3 GEMM + tanh moment coefficients (5 weighted gammas)
    moments_tanh<<<128, 256>>>(w3, b3, out);
    // G build via bf16 MMA (640 blocks) + m41 GEMM (1568 blocks), one launch
    build_H_m41<<<2208, 256>>>(w3, w41, b41);
    // diag of cov41 (x2 triangular) + fused sigmoid probs -> out[8192:]
    bilinear_probs_bf16<<<dim3(7, 64), 256>>>(w41, out + 2 * 64 * 64);
}

// round 8
// speedup vs baseline: 9.0874x; 1.0133x over previous
#include <cuda_runtime.h>
#include <cuda_bf16.h>
#include <math.h>

#define EPSC 1e-6f
#define INV_SQRT_2PI 0.3989422804014327f

// deduped gamma tables (values within 4e-6 merged; weights preserve the mean)
__constant__ float GTU[5] = {0.715951561820333f, 1.039358092507381f, 0.948607106485449f,
                             0.484068718800797f, 1.446433070133343f};
__constant__ float WTU[5] = {4.f, 3.f, 1.f, 1.f, 1.f};
__constant__ float GSU[5] = {0.519483084417772f, 0.357944855434941f, 0.723301195883257f,
                             0.474918009444542f, 0.242049896394596f};
__constant__ float WSU[5] = {3.f, 4.f, 1.f, 1.f, 1.f};

// lower-triangle tile-pair tables for build_H (row tile >= col tile)
__constant__ int RT[10] = {0, 1, 1, 2, 2, 2, 3, 3, 3, 3};
__constant__ int CT[10] = {0, 0, 1, 0, 1, 2, 0, 1, 2, 3};

// ------------------- scratch (__device__ globals, no allocs) -------------------
__device__ float g_h1[64 * 512];
__device__ float g_zvar[64 * 64];
__device__ float g_a0[64 * 512];
__device__ float g_a1[64 * 512];
__device__ float g_a2[64 * 512];
__device__ float g_a3[64 * 512];
__device__ float g_v[64 * 512];
__device__ __nv_bfloat16 g_Hbf[(size_t)64 * 512 * 512];   // G = lower(H)+half-diag, bf16
__device__ __nv_bfloat16 g_w41bf[784 * 512];
__device__ float g_m41[64 * 784];

// ------------------- mma/ldmatrix helpers --------------------------------------
__device__ __forceinline__ void mma_bf16(float* d, unsigned a0, unsigned a1,
                                         unsigned a2, unsigned a3,
                                         unsigned b0, unsigned b1) {
    asm volatile(
        "mma.sync.aligned.m16n8k16.row.col.f32.bf16.bf16.f32 "
        "{%0,%1,%2,%3}, {%4,%5,%6,%7}, {%8,%9}, {%0,%1,%2,%3};"
        : "+f"(d[0]), "+f"(d[1]), "+f"(d[2]), "+f"(d[3])
        : "r"(a0), "r"(a1), "r"(a2), "r"(a3), "r"(b0), "r"(b1));
}
__device__ __forceinline__ void ldmx4(unsigned& r0, unsigned& r1, unsigned& r2,
                                      unsigned& r3, unsigned addr) {
    asm volatile(
        "ldmatrix.sync.aligned.m8n8.x4.shared.b16 {%0,%1,%2,%3}, [%4];"
        : "=r"(r0), "=r"(r1), "=r"(r2), "=r"(r3) : "r"(addr));
}

// ------------------- 8x4 warp-tile fp32 GEMM body ------------------------------
// s[8][4] accumulators, K4 float4 chunks, butterfly reduce -> all lanes hold sums.
template <bool TANH>
__device__ __forceinline__ void warp_gemm_8x4(
    const float* __restrict__ A, int lda,       // 8 rows starting at m0
    const float* __restrict__ B, int ldb,       // 4 rows starting at n0
    const float* __restrict__ bias,
    float* __restrict__ out, int ldo,
    int m0, int n0, int K4, int lane)
{
    float s[8][4];
#pragma unroll
    for (int r = 0; r < 8; r++)
#pragma unroll
        for (int c = 0; c < 4; c++) s[r][c] = 0.f;

    const float4* ap[8];
#pragma unroll
    for (int r = 0; r < 8; r++)
        ap[r] = reinterpret_cast<const float4*>(A + (size_t)(m0 + r) * lda);
    const float4* bp[4];
#pragma unroll
    for (int c = 0; c < 4; c++)
        bp[c] = reinterpret_cast<const float4*>(B + (size_t)(n0 + c) * ldb);

    for (int i = lane; i < K4; i += 32) {
        float4 w[4];
#pragma unroll
        for (int c = 0; c < 4; c++) w[c] = bp[c][i];
#pragma unroll
        for (int r = 0; r < 8; r++) {
            float4 a = ap[r][i];
#pragma unroll
            for (int c = 0; c < 4; c++)
                s[r][c] += a.x * w[c].x + a.y * w[c].y + a.z * w[c].z + a.w * w[c].w;
        }
    }
#pragma unroll
    for (int off = 16; off; off >>= 1)
#pragma unroll
        for (int r = 0; r < 8; r++)
#pragma unroll
            for (int c = 0; c < 4; c++)
                s[r][c] += __shfl_xor_sync(0xffffffff, s[r][c], off);

    if (lane < 8) {
        float4 bb = *reinterpret_cast<const float4*>(bias + n0);
        float v0 = 0.f, v1 = 0.f, v2 = 0.f, v3 = 0.f;
#pragma unroll
        for (int r = 0; r < 8; r++)
            if (lane == r) { v0 = s[r][0]; v1 = s[r][1]; v2 = s[r][2]; v3 = s[r][3]; }
        float4 o;
        if (TANH) {
            o.x = tanhf(v0 + bb.x); o.y = tanhf(v1 + bb.y);
            o.z = tanhf(v2 + bb.z); o.w = tanhf(v3 + bb.w);
        } else {
            o.x = v0 + bb.x; o.y = v1 + bb.y; o.z = v2 + bb.z; o.w = v3 + bb.w;
        }
        *reinterpret_cast<float4*>(out + (size_t)(m0 + lane) * ldo + n0) = o;
    }
}

// ------------------- h1 GEMM (8x4 tiles) + w41 bf16 conversion -----------------
__global__ __launch_bounds__(256) void h1_conv(
    const float* __restrict__ x, const float* __restrict__ w1,
    const float* __restrict__ b1, const float* __restrict__ w41)
{
    if (blockIdx.x >= 128) {           // w41 -> bf16, 784 blocks
        int i = (blockIdx.x - 128) * 256 + threadIdx.x;   // over pairs, exact
        float2 v = reinterpret_cast<const float2*>(w41)[i];
        reinterpret_cast<__nv_bfloat162*>(g_w41bf)[i] = __floats2bfloat162_rn(v.x, v.y);
        return;
    }
    // h1 = tanh(x @ w1^T + b1), M=64 N=512 K=784 : 8 m-groups x 128 n-groups
    const int wid  = (blockIdx.x * 256 + threadIdx.x) >> 5;
    const int lane = threadIdx.x & 31;
    const int tm = wid >> 7, tn = wid & 127;
    warp_gemm_8x4<true>(x, 784, w1, 784, b1, g_h1, 512,
                        tm * 8, tn * 4, 196, lane);
}

// ------------------- dual z GEMM: z_mean and z_logvar(+exp) in one launch ------
__global__ __launch_bounds__(256) void gemm_warp_zdual(
    const float* __restrict__ h1,
    const float* __restrict__ w21, const float* __restrict__ b21,
    const float* __restrict__ w22, const float* __restrict__ b22,
    float* __restrict__ out)
{
    const int half = gridDim.x >> 1;
    const bool second = blockIdx.x >= half;
    const int bx = second ? blockIdx.x - half : blockIdx.x;
    const float* Bw = second ? w22 : w21;
    const float* bias = second ? b22 : b21;
    float* o = second ? out + 64 * 64 : out;

    const int wid  = (bx * 256 + threadIdx.x) >> 5;
    const int lane = threadIdx.x & 31;
    const int N = 64, K = 512;
    const int tm = wid >> 5, tn = wid & 31;
    const int m0 = tm * 2, n0 = tn * 2;

    const float4* a0p = reinterpret_cast<const float4*>(h1 + (size_t)m0 * K);
    const float4* a1p = reinterpret_cast<const float4*>(h1 + (size_t)(m0 + 1) * K);
    const float4* w0p = reinterpret_cast<const float4*>(Bw + (size_t)n0 * K);
    const float4* w1p = reinterpret_cast<const float4*>(Bw + (size_t)(n0 + 1) * K);
    const int K4 = K >> 2;

    float s00 = 0.f, s01 = 0.f, s10 = 0.f, s11 = 0.f;
    for (int i = lane; i < K4; i += 32) {
        float4 a0 = a0p[i], a1 = a1p[i], w0 = w0p[i], w1 = w1p[i];
        s00 += a0.x * w0.x + a0.y * w0.y + a0.z * w0.z + a0.w * w0.w;
        s01 += a0.x * w1.x + a0.y * w1.y + a0.z * w1.z + a0.w * w1.w;
        s10 += a1.x * w0.x + a1.y * w0.y + a1.z * w0.z + a1.w * w0.w;
        s11 += a1.x * w1.x + a1.y * w1.y + a1.z * w1.z + a1.w * w1.w;
    }
#pragma unroll
    for (int off = 16; off; off >>= 1) {
        s00 += __shfl_xor_sync(0xffffffff, s00, off);
        s01 += __shfl_xor_sync(0xffffffff, s01, off);
        s10 += __shfl_xor_sync(0xffffffff, s10, off);
        s11 += __shfl_xor_sync(0xffffffff, s11, off);
    }
    if (lane == 0) {
        float b0 = bias[n0], b1 = bias[n0 + 1];
        float v00 = s00 + b0, v01 = s01 + b1, v10 = s10 + b0, v11 = s11 + b1;
        o[(size_t)m0 * N + n0]           = v00;
        o[(size_t)m0 * N + n0 + 1]       = v01;
        o[(size_t)(m0 + 1) * N + n0]     = v10;
        o[(size_t)(m0 + 1) * N + n0 + 1] = v11;
        if (second) {
            g_zvar[(size_t)m0 * N + n0]           = expf(v00);
            g_zvar[(size_t)m0 * N + n0 + 1]       = expf(v01);
            g_zvar[(size_t)(m0 + 1) * N + n0]     = expf(v10);
            g_zvar[(size_t)(m0 + 1) * N + n0 + 1] = expf(v11);
        }
    }
}

// ------------------- moments (tanh): fused m3 GEMM + coefficients --------------
__global__ __launch_bounds__(256) void moments_tanh(
    const float* __restrict__ w3, const float* __restrict__ b3,
    const float* __restrict__ zmean)
{
    __shared__ float zr[64], zm[64];
    const int t = threadIdx.x;
    const int b = blockIdx.x >> 1;
    const int i = ((blockIdx.x & 1) << 8) + t;
    if (t < 64) zr[t] = g_zvar[b * 64 + t];
    else if (t < 128) zm[t - 64] = zmean[b * 64 + t - 64];
    __syncthreads();

    const float4* wr = reinterpret_cast<const float4*>(w3 + (size_t)i * 64);
    float v = 0.f, m = b3[i];
#pragma unroll
    for (int q = 0; q < 16; q++) {
        float4 w = wr[q];
        v += w.x * w.x * zr[q * 4 + 0] + w.y * w.y * zr[q * 4 + 1]
           + w.z * w.z * zr[q * 4 + 2] + w.w * w.w * zr[q * 4 + 3];
        m += w.x * zm[q * 4 + 0] + w.y * zm[q * 4 + 1]
           + w.z * zm[q * 4 + 2] + w.w * zm[q * 4 + 3];
    }
    v = fmaxf(v, EPSC);

    float s0 = 0.f, s1 = 0.f, s2 = 0.f, s3 = 0.f;
#pragma unroll
    for (int g = 0; g < 5; g++) {
        float gam = GTU[g], wgt = WTU[g];
        float cg = 1.0f / (2.0f * gam * gam);
        float ivh = v + cg;
        float sq = sqrtf(ivh);
        float mu = m / sq;
        float Bv = expf(-0.5f * mu * mu) * INV_SQRT_2PI / sq;
        float Cv = 0.5f * (1.0f + erff(mu * 0.70710678118654752f));
        s0 += wgt * (2.f * Cv - 1.f);
        s1 += wgt * (2.f * Bv);
        s2 += wgt * (-Bv * m / ivh);
        s3 += wgt * ((1.f / 3.f) * Bv * (m * m - ivh) / (ivh * ivh));
    }
    int idx = b * 512 + i;
    g_a0[idx] = s0 * 0.1f;
    g_a1[idx] = s1 * 0.1f;
    g_a2[idx] = s2 * 0.1f;
    g_a3[idx] = s3 * 0.1f;
    g_v[idx]  = v;
}

// ------------------- build G (bf16 MMA) + m41 GEMM (merged launch) -------------
// blocks [0,640): G = lower(H)+half-diag via tensor cores
// blocks [640,836): m41 = a0 @ w41^T + b41  (8x4 warp tiles)
__global__ __launch_bounds__(256, 2) void build_H_m41(
    const float* __restrict__ w3, const float* __restrict__ w41,
    const float* __restrict__ b41)
{
    __shared__ __align__(16) __nv_bfloat16 Abf[128][72];   // [i][k]
    __shared__ __align__(16) __nv_bfloat16 Bbf[128][72];   // [j][k] (z-scaled)
    __shared__ float zrs[64];

    const int t = threadIdx.x;
    if (blockIdx.x >= 640) {            // ---- m41 8x4 warp GEMM ----
        const int wid  = ((blockIdx.x - 640) * 256 + t) >> 5;   // [0,1568)
        const int lane = t & 31;
        const int tm = wid / 196, tn = wid - tm * 196;
        warp_gemm_8x4<false>(g_a0, 512, w41, 512, b41, g_m41, 784,
                             tm * 8, tn * 4, 128, lane);
        return;
    }

    // ---- build G ----
    const int pair = blockIdx.x % 10;
    const int b = blockIdx.x / 10;
    const int ib = RT[pair] * 128, jb = CT[pair] * 128;
    const bool diag_tile = (ib == jb);

    if (t < 64) zrs[t] = g_zvar[b * 64 + t];
    __syncthreads();

    {   // stage W3 tiles (bf16), B side z-scaled
        int row = t >> 1, base = (t & 1) * 8;
        const float4* wa = reinterpret_cast<const float4*>(w3 + (size_t)(ib + row) * 64);
        const float4* wb = reinterpret_cast<const float4*>(w3 + (size_t)(jb + row) * 64);
#pragma unroll
        for (int q = 0; q < 8; q++) {
            int c4 = base + q;
            float4 va = wa[c4];
            *reinterpret_cast<__nv_bfloat162*>(&Abf[row][c4 * 4])     = __floats2bfloat162_rn(va.x, va.y);
            *reinterpret_cast<__nv_bfloat162*>(&Abf[row][c4 * 4 + 2]) = __floats2bfloat162_rn(va.z, va.w);
            float4 vb = wb[c4];
            *reinterpret_cast<__nv_bfloat162*>(&Bbf[row][c4 * 4])     =
                __floats2bfloat162_rn(vb.x * zrs[c4 * 4 + 0], vb.y * zrs[c4 * 4 + 1]);
            *reinterpret_cast<__nv_bfloat162*>(&Bbf[row][c4 * 4 + 2]) =
                __floats2bfloat162_rn(vb.z * zrs[c4 * 4 + 2], vb.w * zrs[c4 * 4 + 3]);
        }
    }
    __syncthreads();

    const int lane = t & 31;
    const int w = t >> 5;
    const int wm = w & 3, wn = w >> 2;
    const int grp = lane >> 2, qid = lane & 3;

    unsigned as_base = (unsigned)__cvta_generic_to_shared(&Abf[0][0]);
    unsigned bs_base = (unsigned)__cvta_generic_to_shared(&Bbf[0][0]);
    unsigned a_addr = as_base + (((wm * 32 + (lane & 15)) * 72 + ((lane >> 4) << 3)) << 1);
    unsigned b_addr = bs_base + (((wn * 64 + (lane & 7) + ((lane & 16) >> 1)) * 72 + (lane & 8)) << 1);

    float d[2][8][4];
#pragma unroll
    for (int mt = 0; mt < 2; mt++)
#pragma unroll
        for (int nt = 0; nt < 8; nt++)
#pragma unroll
            for (int e = 0; e < 4; e++) d[mt][nt][e] = 0.f;

#pragma unroll
    for (int kk = 0; kk < 4; kk++) {
        unsigned a[2][4];
        ldmx4(a[0][0], a[0][1], a[0][2], a[0][3], a_addr + kk * 32);
        ldmx4(a[1][0], a[1][1], a[1][2], a[1][3], a_addr + 2304 + kk * 32);
#pragma unroll
        for (int np = 0; np < 4; np++) {
            unsigned b0, b1, b2, b3;
            ldmx4(b0, b1, b2, b3, b_addr + np * 2304 + kk * 32);
            mma_bf16(d[0][2 * np],     a[0][0], a[0][1], a[0][2], a[0][3], b0, b1);
            mma_bf16(d[0][2 * np + 1], a[0][0], a[0][1], a[0][2], a[0][3], b2, b3);
            mma_bf16(d[1][2 * np],     a[1][0], a[1][1], a[1][2], a[1][3], b0, b1);
            mma_bf16(d[1][2 * np + 1], a[1][0], a[1][1], a[1][2], a[1][3], b2, b3);
        }
    }

    // epilogue: moment transform -> bf16 G
    float A1i[4], A2i[4], A3i[4], Vi[4];
#pragma unroll
    for (int mh = 0; mh < 4; mh++) {
        int gi = b * 512 + ib + wm * 32 + (mh >> 1) * 16 + grp + (mh & 1) * 8;
        A1i[mh] = g_a1[gi]; A2i[mh] = g_a2[gi]; A3i[mh] = g_a3[gi]; Vi[mh] = g_v[gi];
    }
#pragma unroll
    for (int nt = 0; nt < 8; nt++) {
        int gj0 = jb + wn * 64 + nt * 8 + qid * 2;
        float A1j[2], A2j[2], A3j[2], Vj[2];
#pragma unroll
        for (int c = 0; c < 2; c++) {
            int gj = b * 512 + gj0 + c;
            A1j[c] = g_a1[gj]; A2j[c] = g_a2[gj]; A3j[c] = g_a3[gj]; Vj[c] = g_v[gj];
        }
#pragma unroll
        for (int mh = 0; mh < 4; mh++) {
            int mt = mh >> 1, hh = mh & 1;
            int gi = ib + wm * 32 + mt * 16 + grp + hh * 8;
            float hv[2];
#pragma unroll
            for (int c = 0; c < 2; c++) {
                int gj = gj0 + c;
                float c0 = d[mt][nt][hh * 2 + c];
                float h;
                if (diag_tile && gi < gj) {
                    h = 0.f;
                } else if (gi == gj) {
                    c0 = Vi[mh];                       // exact fp32 diagonal
                    float cc2 = c0 * c0;
                    h = 0.5f * (A1i[mh] * A1j[c] * c0
                              + 2.f * A2i[mh] * A2j[c] * cc2
                              + A3i[mh] * A3j[c] * (6.f * cc2 * c0 + 9.f * Vi[mh] * Vj[c] * c0));
                } else {
                    float cc2 = c0 * c0;
                    h = A1i[mh] * A1j[c] * c0
                      + 2.f * A2i[mh] * A2j[c] * cc2
                      + A3i[mh] * A3j[c] * (6.f * cc2 * c0 + 9.f * Vi[mh] * Vj[c] * c0);
                }
                hv[c] = h;
            }
            *reinterpret_cast<__nv_bfloat162*>(
                &g_Hbf[((size_t)b * 512 + gi) * 512 + gj0]) =
                __floats2bfloat162_rn(hv[0], hv[1]);
        }
    }
}

// ------------------- diag + probs via bf16 tensor cores + ldmatrix -------------
// G loads use __ldcg (L2-only) so the per-block w41bf slice stays L1-resident
// across the 4 jt passes.
__global__ __launch_bounds__(256, 2) void bilinear_probs_bf16(
    const float* __restrict__ w41, float* __restrict__ probs_out)
{
    __shared__ __align__(16) __nv_bfloat16 As[128][72];   // [o][k]
    __shared__ __align__(16) __nv_bfloat16 Bs[128][72];   // [j][k] = G[j][k]

    const int t = threadIdx.x;
    const int lane = t & 31;
    const int w = t >> 5;
    const int ob = blockIdx.x * 128;
    const int b  = blockIdx.y;
    const __nv_bfloat16* Hb = g_Hbf + ((size_t)b << 18);

    const int grp = lane >> 2;
    const int qid = lane & 3;

    unsigned as_base = (unsigned)__cvta_generic_to_shared(&As[0][0]);
    unsigned bs_base = (unsigned)__cvta_generic_to_shared(&Bs[0][0]);
    unsigned a_addr = as_base + (((w * 16 + (lane & 15)) * 72 + ((lane >> 4) << 3)) << 1);
    unsigned b_addr = bs_base + ((((lane & 7) + ((lane & 16) >> 1)) * 72 + (lane & 8)) << 1);

    float s0 = 0.f, s1 = 0.f;
    const int o_r0 = ob + w * 16 + grp;
    const int o_r1 = o_r0 + 8;

    for (int jt = 0; jt < 4; jt++) {
        const int jb = jt * 128;
        const int kend = (jt + 1) * 128;       // triangular truncation
        float d[16][4];
#pragma unroll
        for (int nt = 0; nt < 16; nt++)
#pragma unroll
            for (int c = 0; c < 4; c++) d[nt][c] = 0.f;

        for (int kc = 0; kc < kend; kc += 64) {
#pragma unroll
            for (int q = 0; q < 4; q++) {
                int f = t + q * 256;
                int row = f >> 3, g = f & 7;
                int og = ob + row;
                uint4 av = make_uint4(0, 0, 0, 0);
                if (og < 784)
                    av = *reinterpret_cast<const uint4*>(g_w41bf + (size_t)og * 512 + kc + g * 8);
                *reinterpret_cast<uint4*>(&As[row][g * 8]) = av;
                uint4 bv = __ldcg(reinterpret_cast<const uint4*>(
                    Hb + (size_t)(jb + row) * 512 + kc + g * 8));
                *reinterpret_cast<uint4*>(&Bs[row][g * 8]) = bv;
            }
            __syncthreads();

#pragma unroll
            for (int kk = 0; kk < 4; kk++) {
                unsigned a0, a1, a2, a3;
                ldmx4(a0, a1, a2, a3, a_addr + kk * 32);
#pragma unroll
                for (int nt2 = 0; nt2 < 8; nt2++) {
                    unsigned b0, b1, b2, b3;
                    ldmx4(b0, b1, b2, b3, b_addr + nt2 * 2304 + kk * 32);
                    mma_bf16(d[2 * nt2],     a0, a1, a2, a3, b0, b1);
                    mma_bf16(d[2 * nt2 + 1], a0, a1, a2, a3, b2, b3);
                }
            }
            __syncthreads();
        }

        if (o_r0 < 784) {
#pragma unroll
            for (int nt = 0; nt < 16; nt++) {
                int j0 = jb + nt * 8 + qid * 2;
                float2 u0 = *reinterpret_cast<const float2*>(w41 + (size_t)o_r0 * 512 + j0);
                float2 u1 = *reinterpret_cast<const float2*>(w41 + (size_t)o_r1 * 512 + j0);
                s0 += d[nt][0] * u0.x + d[nt][1] * u0.y;
                s1 += d[nt][2] * u1.x + d[nt][3] * u1.y;
            }
        }
    }

    s0 += __shfl_xor_sync(0xffffffff, s0, 1);
    s0 += __shfl_xor_sync(0xffffffff, s0, 2);
    s1 += __shfl_xor_sync(0xffffffff, s1, 1);
    s1 += __shfl_xor_sync(0xffffffff, s1, 2);

    if (qid == 0 && o_r0 < 784) {
        float vv[2] = {fmaxf(2.f * s0, EPSC), fmaxf(2.f * s1, EPSC)};
        int oo[2] = {o_r0, o_r1};
#pragma unroll
        for (int u = 0; u < 2; u++) {
            float m = g_m41[b * 784 + oo[u]];
            float s = 0.f;
#pragma unroll
            for (int g = 0; g < 5; g++) {
                float gam = GSU[g];
                float cg = 1.0f / (2.0f * gam * gam);
                float ivh = vv[u] + cg;
                s += WSU[g] * 0.5f * (1.0f + erff(m / sqrtf(2.0f * ivh)));
            }
            probs_out[b * 784 + oo[u]] = s * 0.1f;
        }
    }
}

// ------------------- launcher --------------------------------------------------
extern "C" void kernel_launch(void* const* d_in, const int* in_sizes, int n_in,
                              void* d_out, int out_size)
{
    const float* x   = (const float*)d_in[0];
    const float* w1  = (const float*)d_in[1];
    const float* b1  = (const float*)d_in[2];
    const float* w21 = (const float*)d_in[3];
    const float* b21 = (const float*)d_in[4];
    const float* w22 = (const float*)d_in[5];
    const float* b22 = (const float*)d_in[6];
    const float* w3  = (const float*)d_in[7];
    const float* b3  = (const float*)d_in[8];
    const float* w41 = (const float*)d_in[9];
    const float* b41 = (const float*)d_in[10];
    float* out = (float*)d_out;

    float* h1;
    cudaGetSymbolAddress((void**)&h1, g_h1);

    // h1 GEMM (128 blocks, 8x4 warp tiles) + w41 bf16 conversion (784 blocks)
    h1_conv<<<912, 256>>>(x, w1, b1, w41);
    // z_mean -> out[0:4096], z_logvar -> out[4096:8192] (+exp -> g_zvar)
    gemm_warp_zdual<<<256, 256>>>(h1, w21, b21, w22, b22, out);
    // fused m3 GEMM + tanh moment coefficients (5 weighted gammas)
    moments_tanh<<<128, 256>>>(w3, b3, out);
    // G build via bf16 MMA (640 blocks) + m41 GEMM (196 blocks, 8x4 tiles)
    build_H_m41<<<836, 256>>>(w3, w41, b41);
    // diag of cov41 (x2 triangular) + fused sigmoid probs -> out[8192:]
    bilinear_probs_bf16<<<dim3(7, 64), 256>>>(w41, out + 2 * 64 * 64);
}

// round 9
// speedup vs baseline: 9.1003x; 1.0014x over previous
#include <cuda_runtime.h>
#include <cuda_bf16.h>
#include <math.h>

#define EPSC 1e-6f
#define INV_SQRT_2PI 0.3989422804014327f

// deduped gamma tables (values within 4e-6 merged; weights preserve the mean)
__constant__ float GTU[5] = {0.715951561820333f, 1.039358092507381f, 0.948607106485449f,
                             0.484068718800797f, 1.446433070133343f};
__constant__ float WTU[5] = {4.f, 3.f, 1.f, 1.f, 1.f};
__constant__ float GSU[5] = {0.519483084417772f, 0.357944855434941f, 0.723301195883257f,
                             0.474918009444542f, 0.242049896394596f};
__constant__ float WSU[5] = {3.f, 4.f, 1.f, 1.f, 1.f};

// lower-triangle tile-pair tables for build_H (row tile >= col tile)
__constant__ int RT[10] = {0, 1, 1, 2, 2, 2, 3, 3, 3, 3};
__constant__ int CT[10] = {0, 0, 1, 0, 1, 2, 0, 1, 2, 3};

// ------------------- scratch (__device__ globals, no allocs) -------------------
__device__ float g_h1[64 * 512];
__device__ float g_zvar[64 * 64];
__device__ float g_a0[64 * 512];
__device__ float g_a1[64 * 512];
__device__ float g_a2[64 * 512];
__device__ float g_a3[64 * 512];
__device__ float g_v[64 * 512];
__device__ __nv_bfloat16 g_Hbf[(size_t)64 * 512 * 512];   // G = lower(H)+half-diag, bf16
__device__ __nv_bfloat16 g_w41bf[784 * 512];
__device__ float g_m41[64 * 784];

// ------------------- mma/ldmatrix helpers --------------------------------------
__device__ __forceinline__ void mma_bf16(float* d, unsigned a0, unsigned a1,
                                         unsigned a2, unsigned a3,
                                         unsigned b0, unsigned b1) {
    asm volatile(
        "mma.sync.aligned.m16n8k16.row.col.f32.bf16.bf16.f32 "
        "{%0,%1,%2,%3}, {%4,%5,%6,%7}, {%8,%9}, {%0,%1,%2,%3};"
        : "+f"(d[0]), "+f"(d[1]), "+f"(d[2]), "+f"(d[3])
        : "r"(a0), "r"(a1), "r"(a2), "r"(a3), "r"(b0), "r"(b1));
}
__device__ __forceinline__ void ldmx4(unsigned& r0, unsigned& r1, unsigned& r2,
                                      unsigned& r3, unsigned addr) {
    asm volatile(
        "ldmatrix.sync.aligned.m8n8.x4.shared.b16 {%0,%1,%2,%3}, [%4];"
        : "=r"(r0), "=r"(r1), "=r"(r2), "=r"(r3) : "r"(addr));
}

// ------------------- 8x4 warp-tile fp32 GEMM body ------------------------------
template <bool TANH>
__device__ __forceinline__ void warp_gemm_8x4(
    const float* __restrict__ A, int lda,
    const float* __restrict__ B, int ldb,
    const float* __restrict__ bias,
    float* __restrict__ out, int ldo,
    int m0, int n0, int K4, int lane)
{
    float s[8][4];
#pragma unroll
    for (int r = 0; r < 8; r++)
#pragma unroll
        for (int c = 0; c < 4; c++) s[r][c] = 0.f;

    const float4* ap[8];
#pragma unroll
    for (int r = 0; r < 8; r++)
        ap[r] = reinterpret_cast<const float4*>(A + (size_t)(m0 + r) * lda);
    const float4* bp[4];
#pragma unroll
    for (int c = 0; c < 4; c++)
        bp[c] = reinterpret_cast<const float4*>(B + (size_t)(n0 + c) * ldb);

    for (int i = lane; i < K4; i += 32) {
        float4 w[4];
#pragma unroll
        for (int c = 0; c < 4; c++) w[c] = bp[c][i];
#pragma unroll
        for (int r = 0; r < 8; r++) {
            float4 a = ap[r][i];
#pragma unroll
            for (int c = 0; c < 4; c++)
                s[r][c] += a.x * w[c].x + a.y * w[c].y + a.z * w[c].z + a.w * w[c].w;
        }
    }
#pragma unroll
    for (int off = 16; off; off >>= 1)
#pragma unroll
        for (int r = 0; r < 8; r++)
#pragma unroll
            for (int c = 0; c < 4; c++)
                s[r][c] += __shfl_xor_sync(0xffffffff, s[r][c], off);

    if (lane < 8) {
        float4 bb = *reinterpret_cast<const float4*>(bias + n0);
        float v0 = 0.f, v1 = 0.f, v2 = 0.f, v3 = 0.f;
#pragma unroll
        for (int r = 0; r < 8; r++)
            if (lane == r) { v0 = s[r][0]; v1 = s[r][1]; v2 = s[r][2]; v3 = s[r][3]; }
        float4 o;
        if (TANH) {
            o.x = tanhf(v0 + bb.x); o.y = tanhf(v1 + bb.y);
            o.z = tanhf(v2 + bb.z); o.w = tanhf(v3 + bb.w);
        } else {
            o.x = v0 + bb.x; o.y = v1 + bb.y; o.z = v2 + bb.z; o.w = v3 + bb.w;
        }
        *reinterpret_cast<float4*>(out + (size_t)(m0 + lane) * ldo + n0) = o;
    }
}

// ------------------- h1 GEMM (8x4 tiles) + w41 bf16 conversion -----------------
__global__ __launch_bounds__(256) void h1_conv(
    const float* __restrict__ x, const float* __restrict__ w1,
    const float* __restrict__ b1, const float* __restrict__ w41)
{
    if (blockIdx.x >= 128) {           // w41 -> bf16, 784 blocks
        int i = (blockIdx.x - 128) * 256 + threadIdx.x;
        float2 v = reinterpret_cast<const float2*>(w41)[i];
        reinterpret_cast<__nv_bfloat162*>(g_w41bf)[i] = __floats2bfloat162_rn(v.x, v.y);
        return;
    }
    const int wid  = (blockIdx.x * 256 + threadIdx.x) >> 5;
    const int lane = threadIdx.x & 31;
    const int tm = wid >> 7, tn = wid & 127;
    warp_gemm_8x4<true>(x, 784, w1, 784, b1, g_h1, 512,
                        tm * 8, tn * 4, 196, lane);
}

// ------------------- zmoments: z GEMMs + tanh moment coefficients --------------
// Block = (batch b, half). Computes z_mean/z_logvar row for b (redundantly per
// half; writers split), then the moments math for 256 of the 512 i-indices.
__global__ __launch_bounds__(256) void zmoments(
    const float* __restrict__ h1,
    const float* __restrict__ w21, const float* __restrict__ b21,
    const float* __restrict__ w22, const float* __restrict__ b22,
    const float* __restrict__ w3, const float* __restrict__ b3,
    float* __restrict__ out)
{
    __shared__ float hs[512];
    __shared__ float zm[64], zr[64];
    const int t = threadIdx.x;
    const int b = blockIdx.x >> 1;
    const int half = blockIdx.x & 1;
    const int lane = t & 31, w = t >> 5;

    if (t < 128)
        *reinterpret_cast<float4*>(&hs[t * 4]) =
            *reinterpret_cast<const float4*>(h1 + (size_t)b * 512 + t * 4);
    __syncthreads();

    // warp w computes (mean, logvar) dots for n in [w*8, w*8+8)
#pragma unroll
    for (int u = 0; u < 8; u++) {
        int n = w * 8 + u;
        const float4* wmp = reinterpret_cast<const float4*>(w21 + (size_t)n * 512);
        const float4* wlp = reinterpret_cast<const float4*>(w22 + (size_t)n * 512);
        float sm = 0.f, sl = 0.f;
#pragma unroll
        for (int i = lane; i < 128; i += 32) {
            float4 hv = *reinterpret_cast<const float4*>(&hs[i * 4]);
            float4 a = wmp[i], bb2 = wlp[i];
            sm += hv.x * a.x + hv.y * a.y + hv.z * a.z + hv.w * a.w;
            sl += hv.x * bb2.x + hv.y * bb2.y + hv.z * bb2.z + hv.w * bb2.w;
        }
#pragma unroll
        for (int off = 16; off; off >>= 1) {
            sm += __shfl_xor_sync(0xffffffff, sm, off);
            sl += __shfl_xor_sync(0xffffffff, sl, off);
        }
        if (lane == 0) {
            sm += b21[n]; sl += b22[n];
            float ev = expf(sl);
            zm[n] = sm; zr[n] = ev;
            if (half == 0) {
                out[b * 64 + n] = sm;                  // z_mean
            } else {
                out[64 * 64 + b * 64 + n] = sl;        // z_logvar
                g_zvar[b * 64 + n] = ev;
            }
        }
    }
    __syncthreads();

    // moments for i = half*256 + t
    const int i = (half << 8) + t;
    const float4* wr = reinterpret_cast<const float4*>(w3 + (size_t)i * 64);
    float v = 0.f, m = b3[i];
#pragma unroll
    for (int q = 0; q < 16; q++) {
        float4 wv = wr[q];
        v += wv.x * wv.x * zr[q * 4 + 0] + wv.y * wv.y * zr[q * 4 + 1]
           + wv.z * wv.z * zr[q * 4 + 2] + wv.w * wv.w * zr[q * 4 + 3];
        m += wv.x * zm[q * 4 + 0] + wv.y * zm[q * 4 + 1]
           + wv.z * zm[q * 4 + 2] + wv.w * zm[q * 4 + 3];
    }
    v = fmaxf(v, EPSC);

    float s0 = 0.f, s1 = 0.f, s2 = 0.f, s3 = 0.f;
#pragma unroll
    for (int g = 0; g < 5; g++) {
        float gam = GTU[g], wgt = WTU[g];
        float cg = 1.0f / (2.0f * gam * gam);
        float ivh = v + cg;
        float sq = sqrtf(ivh);
        float mu = m / sq;
        float Bv = expf(-0.5f * mu * mu) * INV_SQRT_2PI / sq;
        float Cv = 0.5f * (1.0f + erff(mu * 0.70710678118654752f));
        s0 += wgt * (2.f * Cv - 1.f);
        s1 += wgt * (2.f * Bv);
        s2 += wgt * (-Bv * m / ivh);
        s3 += wgt * ((1.f / 3.f) * Bv * (m * m - ivh) / (ivh * ivh));
    }
    int idx = b * 512 + i;
    g_a0[idx] = s0 * 0.1f;
    g_a1[idx] = s1 * 0.1f;
    g_a2[idx] = s2 * 0.1f;
    g_a3[idx] = s3 * 0.1f;
    g_v[idx]  = v;
}

// ------------------- build G (bf16 MMA) + m41 GEMM (merged launch) -------------
// blocks [0,640): G = lower(H)+half-diag via tensor cores
// blocks [640,836): m41 = a0 @ w41^T + b41  (8x4 warp tiles)
__global__ __launch_bounds__(256, 2) void build_H_m41(
    const float* __restrict__ w3, const float* __restrict__ w41,
    const float* __restrict__ b41)
{
    __shared__ __align__(16) char sbuf[36864];   // Abf+Bbf during MMA; Gt after
    __shared__ float zrs[64];
    __shared__ float cA1i[128], cA2i[128], cA3i[128], cVi[128];
    __shared__ float cA1j[128], cA2j[128], cA3j[128], cVj[128];

    const int t = threadIdx.x;
    if (blockIdx.x >= 640) {            // ---- m41 8x4 warp GEMM ----
        const int wid  = ((blockIdx.x - 640) * 256 + t) >> 5;
        const int lane = t & 31;
        const int tm = wid / 196, tn = wid - tm * 196;
        warp_gemm_8x4<false>(g_a0, 512, w41, 512, b41, g_m41, 784,
                             tm * 8, tn * 4, 128, lane);
        return;
    }

    __nv_bfloat16 (*Abf)[72] = reinterpret_cast<__nv_bfloat16(*)[72]>(sbuf);
    __nv_bfloat16 (*Bbf)[72] = reinterpret_cast<__nv_bfloat16(*)[72]>(sbuf + 18432);

    // ---- build G ----
    const int pair = blockIdx.x % 10;
    const int b = blockIdx.x / 10;
    const int ib = RT[pair] * 128, jb = CT[pair] * 128;
    const bool diag_tile = (ib == jb);

    if (t < 64) zrs[t] = g_zvar[b * 64 + t];
    {   // coalesced coefficient staging: t<128 -> i side, else j side
        int side = t >> 7;
        int r = t & 127;
        int gg = b * 512 + (side ? jb : ib) + r;
        if (side == 0) {
            cA1i[r] = g_a1[gg]; cA2i[r] = g_a2[gg];
            cA3i[r] = g_a3[gg]; cVi[r]  = g_v[gg];
        } else {
            cA1j[r] = g_a1[gg]; cA2j[r] = g_a2[gg];
            cA3j[r] = g_a3[gg]; cVj[r]  = g_v[gg];
        }
    }
    __syncthreads();

    {   // stage W3 tiles (bf16), B side z-scaled
        int row = t >> 1, base = (t & 1) * 8;
        const float4* wa = reinterpret_cast<const float4*>(w3 + (size_t)(ib + row) * 64);
        const float4* wb = reinterpret_cast<const float4*>(w3 + (size_t)(jb + row) * 64);
#pragma unroll
        for (int q = 0; q < 8; q++) {
            int c4 = base + q;
            float4 va = wa[c4];
            *reinterpret_cast<__nv_bfloat162*>(&Abf[row][c4 * 4])     = __floats2bfloat162_rn(va.x, va.y);
            *reinterpret_cast<__nv_bfloat162*>(&Abf[row][c4 * 4 + 2]) = __floats2bfloat162_rn(va.z, va.w);
            float4 vb = wb[c4];
            *reinterpret_cast<__nv_bfloat162*>(&Bbf[row][c4 * 4])     =
                __floats2bfloat162_rn(vb.x * zrs[c4 * 4 + 0], vb.y * zrs[c4 * 4 + 1]);
            *reinterpret_cast<__nv_bfloat162*>(&Bbf[row][c4 * 4 + 2]) =
                __floats2bfloat162_rn(vb.z * zrs[c4 * 4 + 2], vb.w * zrs[c4 * 4 + 3]);
        }
    }
    __syncthreads();

    const int lane = t & 31;
    const int w = t >> 5;
    const int wm = w & 3, wn = w >> 2;
    const int grp = lane >> 2, qid = lane & 3;

    unsigned as_base = (unsigned)__cvta_generic_to_shared(&Abf[0][0]);
    unsigned bs_base = (unsigned)__cvta_generic_to_shared(&Bbf[0][0]);
    unsigned a_addr = as_base + (((wm * 32 + (lane & 15)) * 72 + ((lane >> 4) << 3)) << 1);
    unsigned b_addr = bs_base + (((wn * 64 + (lane & 7) + ((lane & 16) >> 1)) * 72 + (lane & 8)) << 1);

    float d[2][8][4];
#pragma unroll
    for (int mt = 0; mt < 2; mt++)
#pragma unroll
        for (int nt = 0; nt < 8; nt++)
#pragma unroll
            for (int e = 0; e < 4; e++) d[mt][nt][e] = 0.f;

#pragma unroll
    for (int kk = 0; kk < 4; kk++) {
        unsigned a[2][4];
        ldmx4(a[0][0], a[0][1], a[0][2], a[0][3], a_addr + kk * 32);
        ldmx4(a[1][0], a[1][1], a[1][2], a[1][3], a_addr + 2304 + kk * 32);
#pragma unroll
        for (int np = 0; np < 4; np++) {
            unsigned b0, b1, b2, b3;
            ldmx4(b0, b1, b2, b3, b_addr + np * 2304 + kk * 32);
            mma_bf16(d[0][2 * np],     a[0][0], a[0][1], a[0][2], a[0][3], b0, b1);
            mma_bf16(d[0][2 * np + 1], a[0][0], a[0][1], a[0][2], a[0][3], b2, b3);
            mma_bf16(d[1][2 * np],     a[1][0], a[1][1], a[1][2], a[1][3], b0, b1);
            mma_bf16(d[1][2 * np + 1], a[1][0], a[1][1], a[1][2], a[1][3], b2, b3);
        }
    }
    __syncthreads();   // ldmx4 done -> safe to overlay Gt on Abf/Bbf

    // epilogue: moment transform -> smem tile (conflict-free), coefficients smem
    __nv_bfloat16 (*Gt)[136] = reinterpret_cast<__nv_bfloat16(*)[136]>(sbuf);
#pragma unroll
    for (int nt = 0; nt < 8; nt++) {
        int jl0 = wn * 64 + nt * 8 + qid * 2;
        float A1j[2] = {cA1j[jl0], cA1j[jl0 + 1]};
        float A2j[2] = {cA2j[jl0], cA2j[jl0 + 1]};
        float A3j[2] = {cA3j[jl0], cA3j[jl0 + 1]};
        float Vj[2]  = {cVj[jl0],  cVj[jl0 + 1]};
#pragma unroll
        for (int mh = 0; mh < 4; mh++) {
            int mt = mh >> 1, hh = mh & 1;
            int il = wm * 32 + mt * 16 + grp + hh * 8;
            int gi = ib + il;
            float A1 = cA1i[il], A2 = cA2i[il], A3 = cA3i[il], Vv = cVi[il];
            float hv[2];
#pragma unroll
            for (int c = 0; c < 2; c++) {
                int gj = jb + jl0 + c;
                float c0 = d[mt][nt][hh * 2 + c];
                float h;
                if (diag_tile && gi < gj) {
                    h = 0.f;
                } else if (gi == gj) {
                    c0 = Vv;                           // exact fp32 diagonal
                    float cc2 = c0 * c0;
                    h = 0.5f * (A1 * A1j[c] * c0
                              + 2.f * A2 * A2j[c] * cc2
                              + A3 * A3j[c] * (6.f * cc2 * c0 + 9.f * Vv * Vj[c] * c0));
                } else {
                    float cc2 = c0 * c0;
                    h = A1 * A1j[c] * c0
                      + 2.f * A2 * A2j[c] * cc2
                      + A3 * A3j[c] * (6.f * cc2 * c0 + 9.f * Vv * Vj[c] * c0);
                }
                hv[c] = h;
            }
            *reinterpret_cast<__nv_bfloat162*>(&Gt[il][jl0]) =
                __floats2bfloat162_rn(hv[0], hv[1]);
        }
    }
    __syncthreads();

    // coalesced uint4 store of the 128x128 bf16 tile
#pragma unroll
    for (int q = 0; q < 8; q++) {
        int f = t + q * 256;
        int row = f >> 4, c16 = f & 15;
        *reinterpret_cast<uint4*>(
            &g_Hbf[((size_t)b * 512 + ib + row) * 512 + jb + c16 * 8]) =
            *reinterpret_cast<const uint4*>(&Gt[row][c16 * 8]);
    }
}

// ------------------- diag + probs via bf16 tensor cores + ldmatrix -------------
__global__ __launch_bounds__(256, 2) void bilinear_probs_bf16(
    const float* __restrict__ w41, float* __restrict__ probs_out)
{
    __shared__ __align__(16) __nv_bfloat16 As[128][72];   // [o][k]
    __shared__ __align__(16) __nv_bfloat16 Bs[128][72];   // [j][k] = G[j][k]

    const int t = threadIdx.x;
    const int lane = t & 31;
    const int w = t >> 5;
    const int ob = blockIdx.x * 128;
    const int b  = blockIdx.y;
    const __nv_bfloat16* Hb = g_Hbf + ((size_t)b << 18);

    const int grp = lane >> 2;
    const int qid = lane & 3;

    unsigned as_base = (unsigned)__cvta_generic_to_shared(&As[0][0]);
    unsigned bs_base = (unsigned)__cvta_generic_to_shared(&Bs[0][0]);
    unsigned a_addr = as_base + (((w * 16 + (lane & 15)) * 72 + ((lane >> 4) << 3)) << 1);
    unsigned b_addr = bs_base + ((((lane & 7) + ((lane & 16) >> 1)) * 72 + (lane & 8)) << 1);

    float s0 = 0.f, s1 = 0.f;
    const int o_r0 = ob + w * 16 + grp;
    const int o_r1 = o_r0 + 8;

    for (int jt = 0; jt < 4; jt++) {
        const int jb = jt * 128;
        const int kend = (jt + 1) * 128;       // triangular truncation
        float d[16][4];
#pragma unroll
        for (int nt = 0; nt < 16; nt++)
#pragma unroll
            for (int c = 0; c < 4; c++) d[nt][c] = 0.f;

        for (int kc = 0; kc < kend; kc += 64) {
#pragma unroll
            for (int q = 0; q < 4; q++) {
                int f = t + q * 256;
                int row = f >> 3, g = f & 7;
                int og = ob + row;
                uint4 av = make_uint4(0, 0, 0, 0);
                if (og < 784)
                    av = *reinterpret_cast<const uint4*>(g_w41bf + (size_t)og * 512 + kc + g * 8);
                *reinterpret_cast<uint4*>(&As[row][g * 8]) = av;
                uint4 bv = __ldcg(reinterpret_cast<const uint4*>(
                    Hb + (size_t)(jb + row) * 512 + kc + g * 8));
                *reinterpret_cast<uint4*>(&Bs[row][g * 8]) = bv;
            }
            __syncthreads();

#pragma unroll
            for (int kk = 0; kk < 4; kk++) {
                unsigned a0, a1, a2, a3;
                ldmx4(a0, a1, a2, a3, a_addr + kk * 32);
#pragma unroll
                for (int nt2 = 0; nt2 < 8; nt2++) {
                    unsigned b0, b1, b2, b3;
                    ldmx4(b0, b1, b2, b3, b_addr + nt2 * 2304 + kk * 32);
                    mma_bf16(d[2 * nt2],     a0, a1, a2, a3, b0, b1);
                    mma_bf16(d[2 * nt2 + 1], a0, a1, a2, a3, b2, b3);
                }
            }
            __syncthreads();
        }

        if (o_r0 < 784) {
#pragma unroll
            for (int nt = 0; nt < 16; nt++) {
                int j0 = jb + nt * 8 + qid * 2;
                float2 u0 = *reinterpret_cast<const float2*>(w41 + (size_t)o_r0 * 512 + j0);
                float2 u1 = *reinterpret_cast<const float2*>(w41 + (size_t)o_r1 * 512 + j0);
                s0 += d[nt][0] * u0.x + d[nt][1] * u0.y;
                s1 += d[nt][2] * u1.x + d[nt][3] * u1.y;
            }
        }
    }

    s0 += __shfl_xor_sync(0xffffffff, s0, 1);
    s0 += __shfl_xor_sync(0xffffffff, s0, 2);
    s1 += __shfl_xor_sync(0xffffffff, s1, 1);
    s1 += __shfl_xor_sync(0xffffffff, s1, 2);

    if (qid == 0 && o_r0 < 784) {
        float vv[2] = {fmaxf(2.f * s0, EPSC), fmaxf(2.f * s1, EPSC)};
        int oo[2] = {o_r0, o_r1};
#pragma unroll
        for (int u = 0; u < 2; u++) {
            float m = g_m41[b * 784 + oo[u]];
            float s = 0.f;
#pragma unroll
            for (int g = 0; g < 5; g++) {
                float gam = GSU[g];
                float cg = 1.0f / (2.0f * gam * gam);
                float ivh = vv[u] + cg;
                s += WSU[g] * 0.5f * (1.0f + erff(m / sqrtf(2.0f * ivh)));
            }
            probs_out[b * 784 + oo[u]] = s * 0.1f;
        }
    }
}

// ------------------- launcher --------------------------------------------------
extern "C" void kernel_launch(void* const* d_in, const int* in_sizes, int n_in,
                              void* d_out, int out_size)
{
    const float* x   = (const float*)d_in[0];
    const float* w1  = (const float*)d_in[1];
    const float* b1  = (const float*)d_in[2];
    const float* w21 = (const float*)d_in[3];
    const float* b21 = (const float*)d_in[4];
    const float* w22 = (const float*)d_in[5];
    const float* b22 = (const float*)d_in[6];
    const float* w3  = (const float*)d_in[7];
    const float* b3  = (const float*)d_in[8];
    const float* w41 = (const float*)d_in[9];
    const float* b41 = (const float*)d_in[10];
    float* out = (float*)d_out;

    float* h1;
    cudaGetSymbolAddress((void**)&h1, g_h1);

    // h1 GEMM (128 blocks, 8x4 warp tiles) + w41 bf16 conversion (784 blocks)
    h1_conv<<<912, 256>>>(x, w1, b1, w41);
    // z GEMMs + tanh moment coefficients, one launch (z_mean/z_logvar -> out)
    zmoments<<<128, 256>>>(h1, w21, b21, w22, b22, w3, b3, out);
    // G build via bf16 MMA (640 blocks) + m41 GEMM (196 blocks, 8x4 tiles)
    build_H_m41<<<836, 256>>>(w3, w41, b41);
    // diag of cov41 (x2 triangular) + fused sigmoid probs -> out[8192:]
    bilinear_probs_bf16<<<dim3(7, 64), 256>>>(w41, out + 2 * 64 * 64);
}

// round 10
// speedup vs baseline: 9.7437x; 1.0707x over previous
#include <cuda_runtime.h>
#include <cuda_bf16.h>
#include <math.h>

#define EPSC 1e-6f
#define INV_SQRT_2PI 0.3989422804014327f

// deduped gamma tables (values within 4e-6 merged; weights preserve the mean)
__constant__ float GTU[5] = {0.715951561820333f, 1.039358092507381f, 0.948607106485449f,
                             0.484068718800797f, 1.446433070133343f};
__constant__ float WTU[5] = {4.f, 3.f, 1.f, 1.f, 1.f};
__constant__ float GSU[5] = {0.519483084417772f, 0.357944855434941f, 0.723301195883257f,
                             0.474918009444542f, 0.242049896394596f};
__constant__ float WSU[5] = {3.f, 4.f, 1.f, 1.f, 1.f};

// lower-triangle tile-pair tables for build_H (row tile >= col tile)
__constant__ int RT[10] = {0, 1, 1, 2, 2, 2, 3, 3, 3, 3};
__constant__ int CT[10] = {0, 0, 1, 0, 1, 2, 0, 1, 2, 3};

// ------------------- scratch (__device__ globals, no allocs) -------------------
__device__ float g_h1[64 * 512];
__device__ float g_zvar[64 * 64];
__device__ float g_a0[64 * 512];
__device__ float g_a1[64 * 512];
__device__ float g_a2[64 * 512];
__device__ float g_a3[64 * 512];
__device__ float g_v[64 * 512];
__device__ __nv_bfloat16 g_Hbf[(size_t)64 * 512 * 512];   // G = lower(H)+half-diag, bf16
__device__ __nv_bfloat16 g_w41bf[784 * 512];
__device__ float g_m41[64 * 784];

// ------------------- mma/ldmatrix helpers --------------------------------------
__device__ __forceinline__ void mma_bf16(float* d, unsigned a0, unsigned a1,
                                         unsigned a2, unsigned a3,
                                         unsigned b0, unsigned b1) {
    asm volatile(
        "mma.sync.aligned.m16n8k16.row.col.f32.bf16.bf16.f32 "
        "{%0,%1,%2,%3}, {%4,%5,%6,%7}, {%8,%9}, {%0,%1,%2,%3};"
        : "+f"(d[0]), "+f"(d[1]), "+f"(d[2]), "+f"(d[3])
        : "r"(a0), "r"(a1), "r"(a2), "r"(a3), "r"(b0), "r"(b1));
}
__device__ __forceinline__ void ldmx4(unsigned& r0, unsigned& r1, unsigned& r2,
                                      unsigned& r3, unsigned addr) {
    asm volatile(
        "ldmatrix.sync.aligned.m8n8.x4.shared.b16 {%0,%1,%2,%3}, [%4];"
        : "=r"(r0), "=r"(r1), "=r"(r2), "=r"(r3) : "r"(addr));
}

// ------------------- 8x4 warp-tile fp32 GEMM body ------------------------------
template <bool TANH>
__device__ __forceinline__ void warp_gemm_8x4(
    const float* __restrict__ A, int lda,
    const float* __restrict__ B, int ldb,
    const float* __restrict__ bias,
    float* __restrict__ out, int ldo,
    int m0, int n0, int K4, int lane)
{
    float s[8][4];
#pragma unroll
    for (int r = 0; r < 8; r++)
#pragma unroll
        for (int c = 0; c < 4; c++) s[r][c] = 0.f;

    const float4* ap[8];
#pragma unroll
    for (int r = 0; r < 8; r++)
        ap[r] = reinterpret_cast<const float4*>(A + (size_t)(m0 + r) * lda);
    const float4* bp[4];
#pragma unroll
    for (int c = 0; c < 4; c++)
        bp[c] = reinterpret_cast<const float4*>(B + (size_t)(n0 + c) * ldb);

    for (int i = lane; i < K4; i += 32) {
        float4 w[4];
#pragma unroll
        for (int c = 0; c < 4; c++) w[c] = bp[c][i];
#pragma unroll
        for (int r = 0; r < 8; r++) {
            float4 a = ap[r][i];
#pragma unroll
            for (int c = 0; c < 4; c++)
                s[r][c] += a.x * w[c].x + a.y * w[c].y + a.z * w[c].z + a.w * w[c].w;
        }
    }
#pragma unroll
    for (int off = 16; off; off >>= 1)
#pragma unroll
        for (int r = 0; r < 8; r++)
#pragma unroll
            for (int c = 0; c < 4; c++)
                s[r][c] += __shfl_xor_sync(0xffffffff, s[r][c], off);

    if (lane < 8) {
        float4 bb = *reinterpret_cast<const float4*>(bias + n0);
        float v0 = 0.f, v1 = 0.f, v2 = 0.f, v3 = 0.f;
#pragma unroll
        for (int r = 0; r < 8; r++)
            if (lane == r) { v0 = s[r][0]; v1 = s[r][1]; v2 = s[r][2]; v3 = s[r][3]; }
        float4 o;
        if (TANH) {
            o.x = tanhf(v0 + bb.x); o.y = tanhf(v1 + bb.y);
            o.z = tanhf(v2 + bb.z); o.w = tanhf(v3 + bb.w);
        } else {
            o.x = v0 + bb.x; o.y = v1 + bb.y; o.z = v2 + bb.z; o.w = v3 + bb.w;
        }
        *reinterpret_cast<float4*>(out + (size_t)(m0 + lane) * ldo + n0) = o;
    }
}

// ------------------- h1 GEMM (8x4 tiles) + w41 bf16 conversion -----------------
__global__ __launch_bounds__(256) void h1_conv(
    const float* __restrict__ x, const float* __restrict__ w1,
    const float* __restrict__ b1, const float* __restrict__ w41)
{
    if (blockIdx.x >= 128) {           // w41 -> bf16, 784 blocks
        int i = (blockIdx.x - 128) * 256 + threadIdx.x;
        float2 v = reinterpret_cast<const float2*>(w41)[i];
        reinterpret_cast<__nv_bfloat162*>(g_w41bf)[i] = __floats2bfloat162_rn(v.x, v.y);
        return;
    }
    const int wid  = (blockIdx.x * 256 + threadIdx.x) >> 5;
    const int lane = threadIdx.x & 31;
    const int tm = wid >> 7, tn = wid & 127;
    warp_gemm_8x4<true>(x, 784, w1, 784, b1, g_h1, 512,
                        tm * 8, tn * 4, 196, lane);
}

// ------------------- zmoments: z GEMMs + tanh moment coefficients --------------
__global__ __launch_bounds__(256) void zmoments(
    const float* __restrict__ h1,
    const float* __restrict__ w21, const float* __restrict__ b21,
    const float* __restrict__ w22, const float* __restrict__ b22,
    const float* __restrict__ w3, const float* __restrict__ b3,
    float* __restrict__ out)
{
    __shared__ float hs[512];
    __shared__ float zm[64], zr[64];
    const int t = threadIdx.x;
    const int b = blockIdx.x >> 1;
    const int half = blockIdx.x & 1;
    const int lane = t & 31, w = t >> 5;

    if (t < 128)
        *reinterpret_cast<float4*>(&hs[t * 4]) =
            *reinterpret_cast<const float4*>(h1 + (size_t)b * 512 + t * 4);
    __syncthreads();

#pragma unroll
    for (int u = 0; u < 8; u++) {
        int n = w * 8 + u;
        const float4* wmp = reinterpret_cast<const float4*>(w21 + (size_t)n * 512);
        const float4* wlp = reinterpret_cast<const float4*>(w22 + (size_t)n * 512);
        float sm = 0.f, sl = 0.f;
#pragma unroll
        for (int i = lane; i < 128; i += 32) {
            float4 hv = *reinterpret_cast<const float4*>(&hs[i * 4]);
            float4 a = wmp[i], bb2 = wlp[i];
            sm += hv.x * a.x + hv.y * a.y + hv.z * a.z + hv.w * a.w;
            sl += hv.x * bb2.x + hv.y * bb2.y + hv.z * bb2.z + hv.w * bb2.w;
        }
#pragma unroll
        for (int off = 16; off; off >>= 1) {
            sm += __shfl_xor_sync(0xffffffff, sm, off);
            sl += __shfl_xor_sync(0xffffffff, sl, off);
        }
        if (lane == 0) {
            sm += b21[n]; sl += b22[n];
            float ev = expf(sl);
            zm[n] = sm; zr[n] = ev;
            if (half == 0) {
                out[b * 64 + n] = sm;                  // z_mean
            } else {
                out[64 * 64 + b * 64 + n] = sl;        // z_logvar
                g_zvar[b * 64 + n] = ev;
            }
        }
    }
    __syncthreads();

    const int i = (half << 8) + t;
    const float4* wr = reinterpret_cast<const float4*>(w3 + (size_t)i * 64);
    float v = 0.f, m = b3[i];
#pragma unroll
    for (int q = 0; q < 16; q++) {
        float4 wv = wr[q];
        v += wv.x * wv.x * zr[q * 4 + 0] + wv.y * wv.y * zr[q * 4 + 1]
           + wv.z * wv.z * zr[q * 4 + 2] + wv.w * wv.w * zr[q * 4 + 3];
        m += wv.x * zm[q * 4 + 0] + wv.y * zm[q * 4 + 1]
           + wv.z * zm[q * 4 + 2] + wv.w * zm[q * 4 + 3];
    }
    v = fmaxf(v, EPSC);

    float s0 = 0.f, s1 = 0.f, s2 = 0.f, s3 = 0.f;
#pragma unroll
    for (int g = 0; g < 5; g++) {
        float gam = GTU[g], wgt = WTU[g];
        float cg = 1.0f / (2.0f * gam * gam);
        float ivh = v + cg;
        float sq = sqrtf(ivh);
        float mu = m / sq;
        float Bv = expf(-0.5f * mu * mu) * INV_SQRT_2PI / sq;
        float Cv = 0.5f * (1.0f + erff(mu * 0.70710678118654752f));
        s0 += wgt * (2.f * Cv - 1.f);
        s1 += wgt * (2.f * Bv);
        s2 += wgt * (-Bv * m / ivh);
        s3 += wgt * ((1.f / 3.f) * Bv * (m * m - ivh) / (ivh * ivh));
    }
    int idx = b * 512 + i;
    g_a0[idx] = s0 * 0.1f;
    g_a1[idx] = s1 * 0.1f;
    g_a2[idx] = s2 * 0.1f;
    g_a3[idx] = s3 * 0.1f;
    g_v[idx]  = v;
}

// ------------------- build G (bf16 MMA) + m41 GEMM (merged launch) -------------
__global__ __launch_bounds__(256, 2) void build_H_m41(
    const float* __restrict__ w3, const float* __restrict__ w41,
    const float* __restrict__ b41)
{
    __shared__ __align__(16) char sbuf[36864];   // Abf+Bbf during MMA; Gt after
    __shared__ float zrs[64];
    __shared__ float cA1i[128], cA2i[128], cA3i[128], cVi[128];
    __shared__ float cA1j[128], cA2j[128], cA3j[128], cVj[128];

    const int t = threadIdx.x;
    if (blockIdx.x >= 640) {            // ---- m41 8x4 warp GEMM ----
        const int wid  = ((blockIdx.x - 640) * 256 + t) >> 5;
        const int lane = t & 31;
        const int tm = wid / 196, tn = wid - tm * 196;
        warp_gemm_8x4<false>(g_a0, 512, w41, 512, b41, g_m41, 784,
                             tm * 8, tn * 4, 128, lane);
        return;
    }

    __nv_bfloat16 (*Abf)[72] = reinterpret_cast<__nv_bfloat16(*)[72]>(sbuf);
    __nv_bfloat16 (*Bbf)[72] = reinterpret_cast<__nv_bfloat16(*)[72]>(sbuf + 18432);

    const int pair = blockIdx.x % 10;
    const int b = blockIdx.x / 10;
    const int ib = RT[pair] * 128, jb = CT[pair] * 128;
    const bool diag_tile = (ib == jb);

    if (t < 64) zrs[t] = g_zvar[b * 64 + t];
    {   // coalesced coefficient staging
        int side = t >> 7;
        int r = t & 127;
        int gg = b * 512 + (side ? jb : ib) + r;
        if (side == 0) {
            cA1i[r] = g_a1[gg]; cA2i[r] = g_a2[gg];
            cA3i[r] = g_a3[gg]; cVi[r]  = g_v[gg];
        } else {
            cA1j[r] = g_a1[gg]; cA2j[r] = g_a2[gg];
            cA3j[r] = g_a3[gg]; cVj[r]  = g_v[gg];
        }
    }
    __syncthreads();

    {   // stage W3 tiles (bf16), B side z-scaled
        int row = t >> 1, base = (t & 1) * 8;
        const float4* wa = reinterpret_cast<const float4*>(w3 + (size_t)(ib + row) * 64);
        const float4* wb = reinterpret_cast<const float4*>(w3 + (size_t)(jb + row) * 64);
#pragma unroll
        for (int q = 0; q < 8; q++) {
            int c4 = base + q;
            float4 va = wa[c4];
            *reinterpret_cast<__nv_bfloat162*>(&Abf[row][c4 * 4])     = __floats2bfloat162_rn(va.x, va.y);
            *reinterpret_cast<__nv_bfloat162*>(&Abf[row][c4 * 4 + 2]) = __floats2bfloat162_rn(va.z, va.w);
            float4 vb = wb[c4];
            *reinterpret_cast<__nv_bfloat162*>(&Bbf[row][c4 * 4])     =
                __floats2bfloat162_rn(vb.x * zrs[c4 * 4 + 0], vb.y * zrs[c4 * 4 + 1]);
            *reinterpret_cast<__nv_bfloat162*>(&Bbf[row][c4 * 4 + 2]) =
                __floats2bfloat162_rn(vb.z * zrs[c4 * 4 + 2], vb.w * zrs[c4 * 4 + 3]);
        }
    }
    __syncthreads();

    const int lane = t & 31;
    const int w = t >> 5;
    const int wm = w & 3, wn = w >> 2;
    const int grp = lane >> 2, qid = lane & 3;

    unsigned as_base = (unsigned)__cvta_generic_to_shared(&Abf[0][0]);
    unsigned bs_base = (unsigned)__cvta_generic_to_shared(&Bbf[0][0]);
    unsigned a_addr = as_base + (((wm * 32 + (lane & 15)) * 72 + ((lane >> 4) << 3)) << 1);
    unsigned b_addr = bs_base + (((wn * 64 + (lane & 7) + ((lane & 16) >> 1)) * 72 + (lane & 8)) << 1);

    float d[2][8][4];
#pragma unroll
    for (int mt = 0; mt < 2; mt++)
#pragma unroll
        for (int nt = 0; nt < 8; nt++)
#pragma unroll
            for (int e = 0; e < 4; e++) d[mt][nt][e] = 0.f;

#pragma unroll
    for (int kk = 0; kk < 4; kk++) {
        unsigned a[2][4];
        ldmx4(a[0][0], a[0][1], a[0][2], a[0][3], a_addr + kk * 32);
        ldmx4(a[1][0], a[1][1], a[1][2], a[1][3], a_addr + 2304 + kk * 32);
#pragma unroll
        for (int np = 0; np < 4; np++) {
            unsigned b0, b1, b2, b3;
            ldmx4(b0, b1, b2, b3, b_addr + np * 2304 + kk * 32);
            mma_bf16(d[0][2 * np],     a[0][0], a[0][1], a[0][2], a[0][3], b0, b1);
            mma_bf16(d[0][2 * np + 1], a[0][0], a[0][1], a[0][2], a[0][3], b2, b3);
            mma_bf16(d[1][2 * np],     a[1][0], a[1][1], a[1][2], a[1][3], b0, b1);
            mma_bf16(d[1][2 * np + 1], a[1][0], a[1][1], a[1][2], a[1][3], b2, b3);
        }
    }
    __syncthreads();   // ldmx4 done -> safe to overlay Gt on Abf/Bbf

    __nv_bfloat16 (*Gt)[136] = reinterpret_cast<__nv_bfloat16(*)[136]>(sbuf);
#pragma unroll
    for (int nt = 0; nt < 8; nt++) {
        int jl0 = wn * 64 + nt * 8 + qid * 2;
        float A1j[2] = {cA1j[jl0], cA1j[jl0 + 1]};
        float A2j[2] = {cA2j[jl0], cA2j[jl0 + 1]};
        float A3j[2] = {cA3j[jl0], cA3j[jl0 + 1]};
        float Vj[2]  = {cVj[jl0],  cVj[jl0 + 1]};
#pragma unroll
        for (int mh = 0; mh < 4; mh++) {
            int mt = mh >> 1, hh = mh & 1;
            int il = wm * 32 + mt * 16 + grp + hh * 8;
            int gi = ib + il;
            float A1 = cA1i[il], A2 = cA2i[il], A3 = cA3i[il], Vv = cVi[il];
            float hv[2];
#pragma unroll
            for (int c = 0; c < 2; c++) {
                int gj = jb + jl0 + c;
                float c0 = d[mt][nt][hh * 2 + c];
                float h;
                if (diag_tile && gi < gj) {
                    h = 0.f;
                } else if (gi == gj) {
                    c0 = Vv;                           // exact fp32 diagonal
                    float cc2 = c0 * c0;
                    h = 0.5f * (A1 * A1j[c] * c0
                              + 2.f * A2 * A2j[c] * cc2
                              + A3 * A3j[c] * (6.f * cc2 * c0 + 9.f * Vv * Vj[c] * c0));
                } else {
                    float cc2 = c0 * c0;
                    h = A1 * A1j[c] * c0
                      + 2.f * A2 * A2j[c] * cc2
                      + A3 * A3j[c] * (6.f * cc2 * c0 + 9.f * Vv * Vj[c] * c0);
                }
                hv[c] = h;
            }
            *reinterpret_cast<__nv_bfloat162*>(&Gt[il][jl0]) =
                __floats2bfloat162_rn(hv[0], hv[1]);
        }
    }
    __syncthreads();

#pragma unroll
    for (int q = 0; q < 8; q++) {
        int f = t + q * 256;
        int row = f >> 4, c16 = f & 15;
        *reinterpret_cast<uint4*>(
            &g_Hbf[((size_t)b * 512 + ib + row) * 512 + jb + c16 * 8]) =
            *reinterpret_cast<const uint4*>(&Gt[row][c16 * 8]);
    }
}

// ------------------- diag + probs: bf16 MMA, cp.async double-buffered ----------
// dynamic smem layout: [As0 18432][Bs0 18432][As1 18432][Bs1 18432] = 73728 B
__global__ __launch_bounds__(256, 2) void bilinear_probs_bf16(
    const float* __restrict__ w41, float* __restrict__ probs_out)
{
    extern __shared__ __align__(16) char dsm[];

    const int t = threadIdx.x;
    const int lane = t & 31;
    const int w = t >> 5;
    const int ob = blockIdx.x * 128;
    const int b  = blockIdx.y;
    const __nv_bfloat16* Hb = g_Hbf + ((size_t)b << 18);

    const int grp = lane >> 2;
    const int qid = lane & 3;

    unsigned smem_base = (unsigned)__cvta_generic_to_shared(dsm);
    unsigned a_frag = smem_base + (((w * 16 + (lane & 15)) * 72 + ((lane >> 4) << 3)) << 1);
    unsigned b_frag = smem_base + 18432u +
                      ((((lane & 7) + ((lane & 16) >> 1)) * 72 + (lane & 8)) << 1);

    float s0 = 0.f, s1 = 0.f;
    const int o_r0 = ob + w * 16 + grp;
    const int o_r1 = o_r0 + 8;

    for (int jt = 0; jt < 4; jt++) {
        const int jb = jt * 128;
        const int nch = 2 * (jt + 1);          // 64-wide chunks (triangular)
        float d[16][4];
#pragma unroll
        for (int nt = 0; nt < 16; nt++)
#pragma unroll
            for (int c = 0; c < 4; c++) d[nt][c] = 0.f;

        // cp.async stage of chunk kc into buffer buf
        auto stage = [&](int kc, int buf) {
            unsigned off = buf ? 36864u : 0u;
#pragma unroll
            for (int q = 0; q < 4; q++) {
                int f = t + q * 256;
                int row = f >> 3, g = f & 7;
                int og = ob + row;
                const __nv_bfloat16* asrc =
                    g_w41bf + (size_t)(og < 784 ? og : 783) * 512 + kc + g * 8;
                unsigned adst = smem_base + off + ((unsigned)(row * 72 + g * 8) << 1);
                unsigned nbytes = (og < 784) ? 16u : 0u;   // zero-fill OOB rows
                asm volatile("cp.async.cg.shared.global [%0], [%1], 16, %2;"
                             :: "r"(adst), "l"(asrc), "r"(nbytes));
                const __nv_bfloat16* bsrc = Hb + (size_t)(jb + row) * 512 + kc + g * 8;
                unsigned bdst = smem_base + 18432u + off +
                                ((unsigned)(row * 72 + g * 8) << 1);
                asm volatile("cp.async.cg.shared.global [%0], [%1], 16;"
                             :: "r"(bdst), "l"(bsrc));
            }
            asm volatile("cp.async.commit_group;");
        };

        stage(0, 0);
        for (int c = 0; c < nch; c++) {
            if (c + 1 < nch) {
                stage((c + 1) * 64, (c + 1) & 1);
                asm volatile("cp.async.wait_group 1;" ::: "memory");
            } else {
                asm volatile("cp.async.wait_group 0;" ::: "memory");
            }
            __syncthreads();

            unsigned sel = (c & 1) ? 36864u : 0u;
#pragma unroll
            for (int kk = 0; kk < 4; kk++) {
                unsigned a0, a1, a2, a3;
                ldmx4(a0, a1, a2, a3, a_frag + sel + kk * 32);
#pragma unroll
                for (int nt2 = 0; nt2 < 8; nt2++) {
                    unsigned b0, b1, b2, b3;
                    ldmx4(b0, b1, b2, b3, b_frag + sel + nt2 * 2304 + kk * 32);
                    mma_bf16(d[2 * nt2],     a0, a1, a2, a3, b0, b1);
                    mma_bf16(d[2 * nt2 + 1], a0, a1, a2, a3, b2, b3);
                }
            }
            __syncthreads();
        }

        if (o_r0 < 784) {
#pragma unroll
            for (int nt = 0; nt < 16; nt++) {
                int j0 = jb + nt * 8 + qid * 2;
                float2 u0 = *reinterpret_cast<const float2*>(w41 + (size_t)o_r0 * 512 + j0);
                float2 u1 = *reinterpret_cast<const float2*>(w41 + (size_t)o_r1 * 512 + j0);
                s0 += d[nt][0] * u0.x + d[nt][1] * u0.y;
                s1 += d[nt][2] * u1.x + d[nt][3] * u1.y;
            }
        }
    }

    s0 += __shfl_xor_sync(0xffffffff, s0, 1);
    s0 += __shfl_xor_sync(0xffffffff, s0, 2);
    s1 += __shfl_xor_sync(0xffffffff, s1, 1);
    s1 += __shfl_xor_sync(0xffffffff, s1, 2);

    if (qid == 0 && o_r0 < 784) {
        float vv[2] = {fmaxf(2.f * s0, EPSC), fmaxf(2.f * s1, EPSC)};
        int oo[2] = {o_r0, o_r1};
#pragma unroll
        for (int u = 0; u < 2; u++) {
            float m = g_m41[b * 784 + oo[u]];
            float s = 0.f;
#pragma unroll
            for (int g = 0; g < 5; g++) {
                float gam = GSU[g];
                float cg = 1.0f / (2.0f * gam * gam);
                float ivh = vv[u] + cg;
                s += WSU[g] * 0.5f * (1.0f + erff(m / sqrtf(2.0f * ivh)));
            }
            probs_out[b * 784 + oo[u]] = s * 0.1f;
        }
    }
}

// ------------------- launcher --------------------------------------------------
extern "C" void kernel_launch(void* const* d_in, const int* in_sizes, int n_in,
                              void* d_out, int out_size)
{
    const float* x   = (const float*)d_in[0];
    const float* w1  = (const float*)d_in[1];
    const float* b1  = (const float*)d_in[2];
    const float* w21 = (const float*)d_in[3];
    const float* b21 = (const float*)d_in[4];
    const float* w22 = (const float*)d_in[5];
    const float* b22 = (const float*)d_in[6];
    const float* w3  = (const float*)d_in[7];
    const float* b3  = (const float*)d_in[8];
    const float* w41 = (const float*)d_in[9];
    const float* b41 = (const float*)d_in[10];
    float* out = (float*)d_out;

    float* h1;
    cudaGetSymbolAddress((void**)&h1, g_h1);

    const int BIL_SMEM = 73728;
    cudaFuncSetAttribute(bilinear_probs_bf16,
                         cudaFuncAttributeMaxDynamicSharedMemorySize, BIL_SMEM);

    // h1 GEMM (128 blocks, 8x4 warp tiles) + w41 bf16 conversion (784 blocks)
    h1_conv<<<912, 256>>>(x, w1, b1, w41);
    // z GEMMs + tanh moment coefficients, one launch (z_mean/z_logvar -> out)
    zmoments<<<128, 256>>>(h1, w21, b21, w22, b22, w3, b3, out);
    // G build via bf16 MMA (640 blocks) + m41 GEMM (196 blocks, 8x4 tiles)
    build_H_m41<<<836, 256>>>(w3, w41, b41);
    // diag of cov41 (x2 triangular, cp.async double-buffered) + fused probs
    bilinear_probs_bf16<<<dim3(7, 64), 256, BIL_SMEM>>>(w41, out + 2 * 64 * 64);
}